// round 9
// baseline (speedup 1.0000x reference)
#include <cuda_runtime.h>
#include <cuda_bf16.h>
#include <math.h>
#include <stdint.h>

// ---------------- arch feature gate (tcgen05 is an "a"-feature) ----------------
#if defined(__CUDA_ARCH_FEAT_SM103_ALL) || defined(__CUDA_ARCH_FEAT_SM100_ALL) || \
    defined(__CUDA_ARCH_FEAT_SM101_ALL) || \
    (defined(__CUDA_ARCH_SPECIFIC__) && (__CUDA_ARCH_SPECIFIC__ >= 1000))
#define HAS_TCGEN05 1
#else
#define HAS_TCGEN05 0
#endif

// ---------------- problem constants ----------------
#define BATCH 2
#define CHN   256
#define HQ    64
#define WQ    64
#define HK    128
#define WK    128
#define NQ    (HQ*WQ)     // 4096
#define NK    (HK*WK)     // 16384
#define HEADS 8
#define CPH   32

// ---------------- scratch (device globals) ----------------
static __device__ float g_q  [BATCH*CHN*NQ];
static __device__ float g_kv [BATCH*2*CHN*NK];
static __device__ float g_qwt[BATCH*CHN*NQ];
static __device__ float g_vwt[BATCH*CHN*NK];
static __device__ float g_kdn[BATCH*CHN*NQ];
static __device__ float g_qn2[BATCH*CHN];
static __device__ float g_kn2[BATCH*CHN];
static __device__ float g_lg [BATCH*HEADS*CPH*CPH];
static __device__ __nv_bfloat16 g_xt_hi[BATCH*NQ*CHN];
static __device__ __nv_bfloat16 g_xt_lo[BATCH*NQ*CHN];
static __device__ __nv_bfloat16 g_ct_hi[BATCH*NK*CHN];
static __device__ __nv_bfloat16 g_ct_lo[BATCH*NK*CHN];
static __device__ __nv_bfloat16 g_aq_hi[CHN*CHN];
static __device__ __nv_bfloat16 g_aq_lo[CHN*CHN];
static __device__ __nv_bfloat16 g_akv_hi[2*CHN*CHN];
static __device__ __nv_bfloat16 g_akv_lo[2*CHN*CHN];

// ---------------- PTX helpers ----------------
__device__ __forceinline__ uint32_t smem_to_u32(const void* p) {
    uint32_t a;
    asm("{ .reg .u64 t; cvta.to.shared.u64 t, %1; cvt.u32.u64 %0, t; }" : "=r"(a) : "l"(p));
    return a;
}
#define SW128(o) ((o) ^ (((o) >> 3) & 0x70))

#if HAS_TCGEN05
__device__ __forceinline__ uint32_t elect_one_pred() {
    uint32_t pred;
    asm volatile("{\n\t.reg .pred p;\n\telect.sync _|p, 0xFFFFFFFF;\n\tselp.b32 %0, 1, 0, p;\n\t}"
                 : "=r"(pred));
    return pred;
}

static constexpr uint64_t SMEM_DESC_BASE_SW128 =
    (uint64_t(2) << 61) | (uint64_t(1) << 46) | (uint64_t(64) << 32) | (uint64_t(1) << 16);
#define MAKE_SMEM_DESC(base_addr) \
    (SMEM_DESC_BASE_SW128 | ((uint64_t)((base_addr) >> 4) & 0x3FFF))

#define TCGEN05_ALLOC(smem_result_addr, nCols) \
    asm volatile("tcgen05.alloc.cta_group::1.sync.aligned.shared::cta.b32 [%0], %1;" \
        :: "r"((uint32_t)(smem_result_addr)), "r"((uint32_t)(nCols)) : "memory")
#define TCGEN05_DEALLOC(tmem_addr, nCols) \
    asm volatile("tcgen05.dealloc.cta_group::1.sync.aligned.b32 %0, %1;" \
        :: "r"(tmem_addr), "r"((uint32_t)(nCols)))
#define TCGEN05_RELINQUISH() \
    asm volatile("tcgen05.relinquish_alloc_permit.cta_group::1.sync.aligned;")
#define TCGEN05_COMMIT(mbar_smem_addr) \
    asm volatile("tcgen05.commit.cta_group::1.mbarrier::arrive::one.shared::cluster.b64 [%0];" \
        :: "r"((uint32_t)(mbar_smem_addr)) : "memory")
#define TCGEN05_FENCE_AFTER() \
    asm volatile("tcgen05.fence::after_thread_sync;" ::: "memory")
#define TCGEN05_WAIT_LD() \
    asm volatile("tcgen05.wait::ld.sync.aligned;" ::: "memory")
#define FENCE_PROXY_ASYNC_SHARED_CTA() \
    asm volatile("fence.proxy.async.shared::cta;" ::: "memory")
#define MBARRIER_INIT(mbar, count) \
    asm volatile("mbarrier.init.shared.b64 [%0], %1;" \
        :: "r"((uint32_t)(mbar)), "r"((uint32_t)(count)) : "memory")
#define MBARRIER_INVAL(mbar) \
    asm volatile("mbarrier.inval.shared.b64 [%0];" :: "r"((uint32_t)(mbar)) : "memory")
#define MBARRIER_WAIT_PARITY(mbar_smem_addr, phase_parity) do { \
    uint32_t _mbar = (uint32_t)(mbar_smem_addr); \
    uint32_t _parity = (uint32_t)(phase_parity); \
    uint32_t _done; \
    asm volatile("{\n\t.reg .pred p;\n\t" \
        "mbarrier.try_wait.parity.acquire.cta.shared::cta.b64 p, [%1], %2;\n\t" \
        "selp.b32 %0, 1, 0, p;\n\t}" \
        : "=r"(_done) : "r"(_mbar), "r"(_parity) : "memory"); \
    if (!_done) { \
        asm volatile("{\n\t.reg .pred P1;\n\t" \
            "WAIT_LOOP_%=:\n\t" \
            "mbarrier.try_wait.parity.acquire.cta.shared::cta.b64 P1, [%0], %1, 0x989680;\n\t" \
            "@P1 bra.uni WAIT_DONE_%=;\n\t" \
            "bra.uni WAIT_LOOP_%=;\n\t" \
            "WAIT_DONE_%=:\n\t}" \
            :: "r"(_mbar), "r"(_parity) : "memory"); \
    } \
} while(0)

#define TCGEN05_LD_32X32B_X32(r, tmem_addr) \
    asm volatile("tcgen05.ld.sync.aligned.32x32b.x32.b32 " \
        "{%0, %1, %2, %3, %4, %5, %6, %7, %8, %9, %10, %11, %12, %13, %14, %15, " \
        " %16, %17, %18, %19, %20, %21, %22, %23, %24, %25, %26, %27, %28, %29, %30, %31}, [%32];" \
        : "=r"((r)[0]),  "=r"((r)[1]),  "=r"((r)[2]),  "=r"((r)[3]), \
          "=r"((r)[4]),  "=r"((r)[5]),  "=r"((r)[6]),  "=r"((r)[7]), \
          "=r"((r)[8]),  "=r"((r)[9]),  "=r"((r)[10]), "=r"((r)[11]), \
          "=r"((r)[12]), "=r"((r)[13]), "=r"((r)[14]), "=r"((r)[15]), \
          "=r"((r)[16]), "=r"((r)[17]), "=r"((r)[18]), "=r"((r)[19]), \
          "=r"((r)[20]), "=r"((r)[21]), "=r"((r)[22]), "=r"((r)[23]), \
          "=r"((r)[24]), "=r"((r)[25]), "=r"((r)[26]), "=r"((r)[27]), \
          "=r"((r)[28]), "=r"((r)[29]), "=r"((r)[30]), "=r"((r)[31]) \
        : "r"(tmem_addr))

__device__ __forceinline__ void mma_f16_ss(uint32_t d_tmem, uint64_t a_desc, uint64_t b_desc,
                                           uint32_t idesc, uint32_t enable_d) {
    asm volatile(
        "{\n\t.reg .pred p;\n\t"
        "setp.ne.u32 p, %4, 0;\n\t"
        "tcgen05.mma.cta_group::1.kind::f16 [%0], %1, %2, %3, {%5, %5, %5, %5}, p;\n\t}"
        :: "r"(d_tmem), "l"(a_desc), "l"(b_desc), "r"(idesc), "r"(enable_d), "r"(0u)
        : "memory");
}

static constexpr uint32_t GEMM_IDESC =
    (1u << 4) | (1u << 7) | (1u << 10) | ((128u / 8u) << 17) | ((128u / 16u) << 24);
#endif  // HAS_TCGEN05

// ---------------- convert helpers ----------------
__device__ __forceinline__ void split_bf16(float x, __nv_bfloat16& h, __nv_bfloat16& l) {
    h = __float2bfloat16(x);
    l = __float2bfloat16(x - __bfloat162float(h));
}
__device__ __forceinline__ float bfu2f(uint32_t u16) {
    return __bfloat162float(__ushort_as_bfloat16((unsigned short)u16));
}

__global__ void convert_w(const float* __restrict__ Wq, const float* __restrict__ Wk,
                          const float* __restrict__ Wv,
                          __nv_bfloat16* __restrict__ aq_hi, __nv_bfloat16* __restrict__ aq_lo,
                          __nv_bfloat16* __restrict__ akv_hi, __nv_bfloat16* __restrict__ akv_lo,
                          float* __restrict__ lg, float* __restrict__ kn2,
                          float* __restrict__ qn2)
{
    if (blockIdx.x == 0) {
        for (int i = threadIdx.x; i < BATCH*HEADS*CPH*CPH; i += 256) lg[i] = 0.f;
        for (int i = threadIdx.x; i < BATCH*CHN; i += 256) { kn2[i] = 0.f; qn2[i] = 0.f; }
    }
    int i = blockIdx.x * 256 + threadIdx.x;
    __nv_bfloat16 h, l;
    if (i < 65536) {
        split_bf16(Wq[i], h, l); aq_hi[i] = h; aq_lo[i] = l;
    } else if (i < 131072) {
        int j = i - 65536;
        split_bf16(Wk[j], h, l); akv_hi[j] = h; akv_lo[j] = l;
    } else {
        int j = i - 131072;
        split_bf16(Wv[j], h, l); akv_hi[65536 + j] = h; akv_lo[65536 + j] = l;
    }
}

// ---------------- X convert: [B,C,N] f32 -> [B,N,C] bf16 hi/lo ----------------
__global__ __launch_bounds__(256) void convert_x(const float* __restrict__ X,
                                                 __nv_bfloat16* __restrict__ Th,
                                                 __nv_bfloat16* __restrict__ Tl, int N)
{
    __shared__ float s[64][33];
    int b = blockIdx.z, c0 = blockIdx.y * 64, n0 = blockIdx.x * 32;
    const float* Xb = X + (size_t)b * 256 * N;
    int lane = threadIdx.x & 31, w = threadIdx.x >> 5;
#pragma unroll
    for (int i = 0; i < 8; i++) {
        int c = w + i * 8;
        s[c][lane] = Xb[(size_t)(c0 + c) * N + n0 + lane];
    }
    __syncthreads();
    uint32_t* TH = (uint32_t*)(Th + (size_t)b * N * 256);
    uint32_t* TL = (uint32_t*)(Tl + (size_t)b * N * 256);
#pragma unroll
    for (int i = 0; i < 4; i++) {
        int n = w + i * 8;
        float x0 = s[2 * lane][n], x1 = s[2 * lane + 1][n];
        __nv_bfloat16 h0, l0, h1, l1;
        split_bf16(x0, h0, l0); split_bf16(x1, h1, l1);
        uint32_t hp = ((uint32_t)__bfloat16_as_ushort(h1) << 16) | __bfloat16_as_ushort(h0);
        uint32_t lp = ((uint32_t)__bfloat16_as_ushort(l1) << 16) | __bfloat16_as_ushort(l0);
        size_t idx = (size_t)(n0 + n) * 128 + (c0 >> 1) + lane;
        TH[idx] = hp; TL[idx] = lp;
    }
}

// ---------------- GEMM ----------------
#if HAS_TCGEN05
__device__ __forceinline__ void load_tile_sw(const __nv_bfloat16* __restrict__ src,
                                             char* __restrict__ dst, int tid)
{
#pragma unroll
    for (int it = 0; it < 4; it++) {
        int i = tid + it * 256;
        int row = i >> 3, seg = i & 7;
        uint4 v = *(const uint4*)(src + (size_t)row * 256 + seg * 8);
        uint32_t off = (uint32_t)(row * 128 + seg * 16);
        *(uint4*)(dst + SW128(off)) = v;
    }
}
#endif

__global__ __launch_bounds__(256, 1) void gemm_tc(
    const __nv_bfloat16* __restrict__ Ahi, const __nv_bfloat16* __restrict__ Alo,
    const __nv_bfloat16* __restrict__ Bhi, const __nv_bfloat16* __restrict__ Blo,
    float* __restrict__ Y, int Ntot)
{
    extern __shared__ char dsm[];
    int tid = threadIdx.x;
    int m0 = blockIdx.y * 128, n0 = blockIdx.x * 128, b = blockIdx.z;
    int Mtot = gridDim.y * 128;
    const __nv_bfloat16* Bh = Bhi + (size_t)b * Ntot * 256;
    const __nv_bfloat16* Bl = Blo + (size_t)b * Ntot * 256;
    float* Yb = Y + (size_t)b * Mtot * Ntot;

#if HAS_TCGEN05
    __shared__ uint32_t s_tmem[1];
    __shared__ unsigned long long s_mbar[2];
    uint32_t dsm_u = smem_to_u32(dsm);
    uint32_t sb = (dsm_u + 1023) & ~1023u;
    char* sbp = dsm + (sb - dsm_u);
    uint32_t mb[2] = { smem_to_u32(&s_mbar[0]), smem_to_u32(&s_mbar[1]) };
    int wid = tid >> 5;

    if (wid == 0) TCGEN05_ALLOC(smem_to_u32(s_tmem), 128);
    if (tid == 0) { MBARRIER_INIT(mb[0], 1); MBARRIER_INIT(mb[1], 1); }
    __syncthreads();
    uint32_t tbase = s_tmem[0];

    for (int ch = 0; ch < 4; ch++) {
        int buf = ch & 1;
        char* bp = sbp + buf * 65536;
        if (ch >= 2) MBARRIER_WAIT_PARITY(mb[buf], 0);
        int c0 = ch * 64;
        load_tile_sw(Ahi + (size_t)m0 * 256 + c0, bp,          tid);
        load_tile_sw(Alo + (size_t)m0 * 256 + c0, bp + 16384,  tid);
        load_tile_sw(Bh  + (size_t)n0 * 256 + c0, bp + 32768,  tid);
        load_tile_sw(Bl  + (size_t)n0 * 256 + c0, bp + 49152,  tid);
        FENCE_PROXY_ASYNC_SHARED_CTA();
        __syncthreads();
        if (wid == 0) {
            if (elect_one_pred()) {
                uint32_t base = sb + buf * 65536;
                uint64_t dah = MAKE_SMEM_DESC(base);
                uint64_t dal = MAKE_SMEM_DESC(base + 16384);
                uint64_t dbh = MAKE_SMEM_DESC(base + 32768);
                uint64_t dbl = MAKE_SMEM_DESC(base + 49152);
#pragma unroll
                for (int k = 0; k < 4; k++)
                    mma_f16_ss(tbase, dah + 2 * k, dbh + 2 * k, GEMM_IDESC,
                               (ch > 0 || k > 0) ? 1u : 0u);
#pragma unroll
                for (int k = 0; k < 4; k++)
                    mma_f16_ss(tbase, dah + 2 * k, dbl + 2 * k, GEMM_IDESC, 1u);
#pragma unroll
                for (int k = 0; k < 4; k++)
                    mma_f16_ss(tbase, dal + 2 * k, dbh + 2 * k, GEMM_IDESC, 1u);
                TCGEN05_COMMIT(mb[buf]);
            }
        }
    }

    MBARRIER_WAIT_PARITY(mb[0], 1);
    MBARRIER_WAIT_PARITY(mb[1], 1);
    TCGEN05_FENCE_AFTER();

    float* Ds = (float*)sbp;
    uint32_t woff = (uint32_t)(wid & 3) << 21;
    int cb0 = (wid >= 4) ? 2 : 0;
    int lane = tid & 31;
    int row = (wid & 3) * 32 + lane;
    uint32_t regs[32];
#pragma unroll
    for (int j = 0; j < 2; j++) {
        int cb = cb0 + j;
        TCGEN05_LD_32X32B_X32(regs, tbase + cb * 32 + woff);
        TCGEN05_WAIT_LD();
#pragma unroll
        for (int c = 0; c < 32; c++)
            Ds[row * 132 + cb * 32 + c] = __uint_as_float(regs[c]);
    }
    __syncthreads();
#pragma unroll
    for (int it = 0; it < 16; it++) {
        int i = tid + it * 256;
        int r = i >> 5, c4 = (i & 31) * 4;
        float4 v = *(float4*)&Ds[r * 132 + c4];
        *(float4*)&Yb[(size_t)(m0 + r) * Ntot + n0 + c4] = v;
    }
    __syncthreads();
    if (tid == 0) { MBARRIER_INVAL(mb[0]); MBARRIER_INVAL(mb[1]); }
    if (wid == 0) { TCGEN05_RELINQUISH(); TCGEN05_DEALLOC(tbase, 128); }

#else  // SIMT fallback
    float* As = (float*)dsm;
    float* Bs = As + 8 * 128;
    int ty = tid >> 4, tx = tid & 15;
    int r = tid >> 1, kq = (tid & 1) * 4;

    float acc[8][8];
#pragma unroll
    for (int i = 0; i < 8; i++)
#pragma unroll
        for (int j = 0; j < 8; j++) acc[i][j] = 0.f;

    for (int c0 = 0; c0 < 256; c0 += 8) {
        {
            size_t off = (size_t)(m0 + r) * 256 + c0 + kq;
            uint2 vh = *(const uint2*)(Ahi + off);
            uint2 vl = *(const uint2*)(Alo + off);
            As[(kq + 0) * 128 + r] = bfu2f(vh.x & 0xffff)  + bfu2f(vl.x & 0xffff);
            As[(kq + 1) * 128 + r] = bfu2f(vh.x >> 16)     + bfu2f(vl.x >> 16);
            As[(kq + 2) * 128 + r] = bfu2f(vh.y & 0xffff)  + bfu2f(vl.y & 0xffff);
            As[(kq + 3) * 128 + r] = bfu2f(vh.y >> 16)     + bfu2f(vl.y >> 16);
            size_t offb = (size_t)(n0 + r) * 256 + c0 + kq;
            uint2 wh = *(const uint2*)(Bh + offb);
            uint2 wl = *(const uint2*)(Bl + offb);
            Bs[(kq + 0) * 128 + r] = bfu2f(wh.x & 0xffff)  + bfu2f(wl.x & 0xffff);
            Bs[(kq + 1) * 128 + r] = bfu2f(wh.x >> 16)     + bfu2f(wl.x >> 16);
            Bs[(kq + 2) * 128 + r] = bfu2f(wh.y & 0xffff)  + bfu2f(wl.y & 0xffff);
            Bs[(kq + 3) * 128 + r] = bfu2f(wh.y >> 16)     + bfu2f(wl.y >> 16);
        }
        __syncthreads();
#pragma unroll
        for (int kk = 0; kk < 8; kk++) {
            float a[8], bb[8];
            *(float4*)&a[0]  = *(const float4*)&As[kk * 128 + ty * 8];
            *(float4*)&a[4]  = *(const float4*)&As[kk * 128 + ty * 8 + 4];
            *(float4*)&bb[0] = *(const float4*)&Bs[kk * 128 + tx * 8];
            *(float4*)&bb[4] = *(const float4*)&Bs[kk * 128 + tx * 8 + 4];
#pragma unroll
            for (int i = 0; i < 8; i++)
#pragma unroll
                for (int j = 0; j < 8; j++)
                    acc[i][j] = fmaf(a[i], bb[j], acc[i][j]);
        }
        __syncthreads();
    }
#pragma unroll
    for (int i = 0; i < 8; i++) {
        float* yp = Yb + (size_t)(m0 + ty * 8 + i) * Ntot + n0 + tx * 8;
        *(float4*)yp       = make_float4(acc[i][0], acc[i][1], acc[i][2], acc[i][3]);
        *(float4*)(yp + 4) = make_float4(acc[i][4], acc[i][5], acc[i][6], acc[i][7]);
    }
#endif
}

// ---------------- plain templated WTConv (Haar, ks=3), 16-row tiles — used for v ----------------
template<int W>
__global__ __launch_bounds__(256) void wtconv_t(
    const float* __restrict__ X, float* __restrict__ Y,
    const float* __restrict__ base_w, const float* __restrict__ base_s,
    const float* __restrict__ wav_w,  const float* __restrict__ wav_s,
    int H, int cs_in)
{
    constexpr int LW = W + 4;
    constexpr int SWc = (W >> 1) + 2;
    constexpr int Wh = W >> 1;
    __shared__ float ins[20][LW];
    __shared__ float sub[4][10][SWc];
    __shared__ float swav[4][9];
    __shared__ float sbw[9];
    __shared__ float swsc[4];
    __shared__ float sbs;

    int bc = blockIdx.x;
    int b  = bc >> 8;
    int c  = bc & 255;
    int y0 = blockIdx.y * 16;
    const float* Xc = X + ((size_t)b * cs_in + c) * H * W;
    float*       Yc = Y + (size_t)bc * H * W;
    int tid = threadIdx.x;

    if (tid < 36) {
        int f = tid / 9, i = tid - f * 9;
        swav[f][i] = wav_w[(size_t)(c * 4 + f) * 9 + i];
    } else if (tid < 45) {
        sbw[tid - 36] = base_w[(size_t)c * 9 + tid - 36];
    } else if (tid < 49) {
        swsc[tid - 45] = wav_s[c * 4 + tid - 45];
    } else if (tid == 49) {
        sbs = base_s[c];
    }

    for (int idx = tid; idx < 20 * LW; idx += 256) {
        int ly = idx / LW, lx = idx - ly * LW;
        int gy = y0 + ly - 2, gx = lx - 2;
        float v = 0.f;
        if (gy >= 0 && gy < H && gx >= 0 && gx < W) v = Xc[gy * W + gx];
        ins[ly][lx] = v;
    }
    __syncthreads();

    for (int idx = tid; idx < 10 * SWc; idx += 256) {
        int sy = idx / SWc, sx = idx - sy * SWc;
        float a = ins[2 * sy][2 * sx],     bq = ins[2 * sy][2 * sx + 1];
        float d = ins[2 * sy + 1][2 * sx], e = ins[2 * sy + 1][2 * sx + 1];
        sub[0][sy][sx] = 0.5f * (a + bq + d + e);
        sub[1][sy][sx] = 0.5f * (a + bq - d - e);
        sub[2][sy][sx] = 0.5f * (a - bq + d - e);
        sub[3][sy][sx] = 0.5f * (a - bq - d + e);
    }
    __syncthreads();

    for (int idx = tid; idx < 8 * Wh; idx += 256) {
        int syi = idx / Wh, sxi = idx - syi * Wh;
        int sy = syi + 1, sx = sxi + 1;
        float r[4];
#pragma unroll
        for (int f = 0; f < 4; f++) {
            float s = 0.f;
#pragma unroll
            for (int dy = 0; dy < 3; dy++)
#pragma unroll
                for (int dx = 0; dx < 3; dx++)
                    s = fmaf(swav[f][dy * 3 + dx], sub[f][sy - 1 + dy][sx - 1 + dx], s);
            r[f] = s * swsc[f];
        }
        float y00 = 0.5f * (r[0] + r[1] + r[2] + r[3]);
        float y01 = 0.5f * (r[0] + r[1] - r[2] - r[3]);
        float y10 = 0.5f * (r[0] - r[1] + r[2] - r[3]);
        float y11 = 0.5f * (r[0] - r[1] - r[2] + r[3]);

        float base[2][2];
#pragma unroll
        for (int p = 0; p < 2; p++)
#pragma unroll
            for (int q = 0; q < 2; q++) {
                float s = 0.f;
#pragma unroll
                for (int dy = 0; dy < 3; dy++)
#pragma unroll
                    for (int dx = 0; dx < 3; dx++)
                        s = fmaf(sbw[dy * 3 + dx],
                                 ins[2 * syi + p + 1 + dy][2 * sxi + q + 1 + dx], s);
                base[p][q] = s * sbs;
            }
        int gy = y0 + 2 * syi, gx = 2 * sxi;
        Yc[(gy + 0) * W + gx + 0] = base[0][0] + y00;
        Yc[(gy + 0) * W + gx + 1] = base[0][1] + y01;
        Yc[(gy + 1) * W + gx + 0] = base[1][0] + y10;
        Yc[(gy + 1) * W + gx + 1] = base[1][1] + y11;
    }
}

// ---------------- fused wtconv(k) + transposed-bilinear downsample + ||k||², 16-row tiles ----------------
#define KD_SMEM ((24*132 + 4*12*66 + 20*130) * 4)

__global__ __launch_bounds__(256) void wtconv_k_down(
    const float* __restrict__ X, float* __restrict__ kdn,
    const float* __restrict__ base_w, const float* __restrict__ base_s,
    const float* __restrict__ wav_w,  const float* __restrict__ wav_s,
    float* __restrict__ kn2)
{
    extern __shared__ float sm[];
    float* ins  = sm;                    // [24][132]  rows y0-4..y0+19
    float* sub  = ins + 24 * 132;        // [4][12][66]
    float* outb = sub + 4 * 12 * 66;     // [20][130]  rows y0-2..y0+17
    __shared__ float swav[4][9];
    __shared__ float sbw[9];
    __shared__ float swsc[4];
    __shared__ float sbs;
    __shared__ float red[256];

    int bc = blockIdx.x;
    int b  = bc >> 8;
    int c  = bc & 255;
    int by = blockIdx.y;
    int y0 = by * 16;
    const float* Xc = X + ((size_t)b * 512 + c) * (size_t)NK;
    int tid = threadIdx.x;

    if (tid < 36) {
        int f = tid / 9, i = tid - f * 9;
        swav[f][i] = wav_w[(size_t)(c * 4 + f) * 9 + i];
    } else if (tid < 45) {
        sbw[tid - 36] = base_w[(size_t)c * 9 + tid - 36];
    } else if (tid < 49) {
        swsc[tid - 45] = wav_s[c * 4 + tid - 45];
    } else if (tid == 49) {
        sbs = base_s[c];
    }

    for (int idx = tid; idx < 24 * 132; idx += 256) {
        int ly = idx / 132, lx = idx - ly * 132;
        int gy = y0 + ly - 4, gx = lx - 2;
        float v = 0.f;
        if (gy >= 0 && gy < 128 && gx >= 0 && gx < 128) v = Xc[gy * 128 + gx];
        ins[idx] = v;
    }
    __syncthreads();

    for (int idx = tid; idx < 12 * 66; idx += 256) {
        int sy = idx / 66, sx = idx - sy * 66;
        const float* r0 = ins + (2 * sy) * 132 + 2 * sx;
        float a = r0[0], bq = r0[1], d = r0[132], e = r0[133];
        sub[0 * 792 + idx] = 0.5f * (a + bq + d + e);
        sub[1 * 792 + idx] = 0.5f * (a + bq - d - e);
        sub[2 * 792 + idx] = 0.5f * (a - bq + d - e);
        sub[3 * 792 + idx] = 0.5f * (a - bq - d + e);
    }
    __syncthreads();

    // output 2-row blocks: syo 0..9 -> out rows local 2syo, 2syo+1 (global y0-2+2syo..)
    for (int idx = tid; idx < 10 * 64; idx += 256) {
        int syo = idx >> 6, j = idx & 63;
        int sy = syo + 1, sx = j + 1;
        float r[4];
#pragma unroll
        for (int f = 0; f < 4; f++) {
            const float* sf = sub + f * 792;
            float s = 0.f;
#pragma unroll
            for (int dy = 0; dy < 3; dy++)
#pragma unroll
                for (int dx = 0; dx < 3; dx++)
                    s = fmaf(swav[f][dy * 3 + dx], sf[(sy - 1 + dy) * 66 + sx - 1 + dx], s);
            r[f] = s * swsc[f];
        }
        float y00 = 0.5f * (r[0] + r[1] + r[2] + r[3]);
        float y01 = 0.5f * (r[0] + r[1] - r[2] - r[3]);
        float y10 = 0.5f * (r[0] - r[1] + r[2] - r[3]);
        float y11 = 0.5f * (r[0] - r[1] - r[2] + r[3]);

        float base[2][2];
#pragma unroll
        for (int p = 0; p < 2; p++)
#pragma unroll
            for (int q = 0; q < 2; q++) {
                float s = 0.f;
#pragma unroll
                for (int dy = 0; dy < 3; dy++)
#pragma unroll
                    for (int dx = 0; dx < 3; dx++)
                        s = fmaf(sbw[dy * 3 + dx],
                                 ins[(2 * syo + 1 + p + dy) * 132 + 2 * j + 1 + q + dx], s);
                base[p][q] = s * sbs;
            }
        outb[(2 * syo) * 130 + 2 * j]         = base[0][0] + y00;
        outb[(2 * syo) * 130 + 2 * j + 1]     = base[0][1] + y01;
        outb[(2 * syo + 1) * 130 + 2 * j]     = base[1][0] + y10;
        outb[(2 * syo + 1) * 130 + 2 * j + 1] = base[1][1] + y11;
    }
    __syncthreads();

    // norm² over owned rows (local 2..17 == global y0..y0+15)
    float sumsq = 0.f;
    for (int idx = tid; idx < 16 * 128; idx += 256) {
        int lr = (idx >> 7) + 2, lc = idx & 127;
        float v = outb[lr * 130 + lc];
        sumsq += v * v;
    }

    // kdn rows jy in [8by, 8by+7]
    for (int idx = tid; idx < 8 * 64; idx += 256) {
        int jj = idx >> 6, jx = idx & 63;
        int jy = 8 * by + jj;
        int lyt[4]; float wyt[4]; int cy = 0;
        if (jy > 0)  { lyt[cy] = 2*jj+1; wyt[cy++] = 0.25f; }
        lyt[cy] = 2*jj+2; wyt[cy++] = (jy == 0)  ? 1.0f : 0.75f;
        lyt[cy] = 2*jj+3; wyt[cy++] = (jy == 63) ? 1.0f : 0.75f;
        if (jy < 63) { lyt[cy] = 2*jj+4; wyt[cy++] = 0.25f; }
        int lxt[4]; float wxt[4]; int cx = 0;
        if (jx > 0)  { lxt[cx] = 2*jx-1; wxt[cx++] = 0.25f; }
        lxt[cx] = 2*jx;   wxt[cx++] = (jx == 0)  ? 1.0f : 0.75f;
        lxt[cx] = 2*jx+1; wxt[cx++] = (jx == 63) ? 1.0f : 0.75f;
        if (jx < 63) { lxt[cx] = 2*jx+2; wxt[cx++] = 0.25f; }
        float s = 0.f;
        for (int a = 0; a < cy; a++) {
            const float* row = outb + lyt[a] * 130;
            float rs = 0.f;
            for (int e = 0; e < cx; e++) rs = fmaf(wxt[e], row[lxt[e]], rs);
            s = fmaf(wyt[a], rs, s);
        }
        kdn[(size_t)bc * NQ + jy * 64 + jx] = s;
    }

    red[tid] = sumsq; __syncthreads();
    for (int o = 128; o > 0; o >>= 1) {
        if (tid < o) red[tid] += red[tid + o];
        __syncthreads();
    }
    if (tid == 0) atomicAdd(&kn2[bc], red[0]);
}

// ---------------- fused wtconv(q) + ||upsample(q)||² (atomic) ----------------
__global__ __launch_bounds__(256) void wtconv_q_norm(
    const float* __restrict__ X, float* __restrict__ Y,
    const float* __restrict__ base_w, const float* __restrict__ base_s,
    const float* __restrict__ wav_w,  const float* __restrict__ wav_s,
    float* __restrict__ qn2)
{
    __shared__ float ins[40][68];
    __shared__ float sub[4][20][36];
    __shared__ float outb[36][66];
    __shared__ float swav[4][9];
    __shared__ float sbw[9];
    __shared__ float swsc[4];
    __shared__ float sbs;
    __shared__ float red[256];

    int bc = blockIdx.x;
    int c  = bc & 255;
    int by = blockIdx.y;
    int y0 = by * 32;
    const float* Xc = X + (size_t)bc * NQ;
    float*       Yc = Y + (size_t)bc * NQ;
    int tid = threadIdx.x;

    if (tid < 36) {
        int f = tid / 9, i = tid - f * 9;
        swav[f][i] = wav_w[(size_t)(c * 4 + f) * 9 + i];
    } else if (tid < 45) {
        sbw[tid - 36] = base_w[(size_t)c * 9 + tid - 36];
    } else if (tid < 49) {
        swsc[tid - 45] = wav_s[c * 4 + tid - 45];
    } else if (tid == 49) {
        sbs = base_s[c];
    }

    for (int idx = tid; idx < 40 * 68; idx += 256) {
        int ly = idx / 68, lx = idx - ly * 68;
        int gy = y0 + ly - 4, gx = lx - 2;
        float v = 0.f;
        if (gy >= 0 && gy < 64 && gx >= 0 && gx < 64) v = Xc[gy * 64 + gx];
        ins[ly][lx] = v;
    }
    __syncthreads();

    for (int idx = tid; idx < 20 * 34; idx += 256) {
        int sy = idx / 34, sx = idx - sy * 34;
        float a = ins[2 * sy][2 * sx],     bq = ins[2 * sy][2 * sx + 1];
        float d = ins[2 * sy + 1][2 * sx], e = ins[2 * sy + 1][2 * sx + 1];
        sub[0][sy][sx] = 0.5f * (a + bq + d + e);
        sub[1][sy][sx] = 0.5f * (a + bq - d - e);
        sub[2][sy][sx] = 0.5f * (a - bq + d - e);
        sub[3][sy][sx] = 0.5f * (a - bq - d + e);
    }
    __syncthreads();

    for (int idx = tid; idx < 18 * 32; idx += 256) {
        int syo = idx >> 5, j = idx & 31;
        int sy = syo + 1, sx = j + 1;
        float r[4];
#pragma unroll
        for (int f = 0; f < 4; f++) {
            float s = 0.f;
#pragma unroll
            for (int dy = 0; dy < 3; dy++)
#pragma unroll
                for (int dx = 0; dx < 3; dx++)
                    s = fmaf(swav[f][dy * 3 + dx], sub[f][sy - 1 + dy][sx - 1 + dx], s);
            r[f] = s * swsc[f];
        }
        float y00 = 0.5f * (r[0] + r[1] + r[2] + r[3]);
        float y01 = 0.5f * (r[0] + r[1] - r[2] - r[3]);
        float y10 = 0.5f * (r[0] - r[1] + r[2] - r[3]);
        float y11 = 0.5f * (r[0] - r[1] - r[2] + r[3]);

        float base[2][2];
#pragma unroll
        for (int p = 0; p < 2; p++)
#pragma unroll
            for (int q = 0; q < 2; q++) {
                float s = 0.f;
#pragma unroll
                for (int dy = 0; dy < 3; dy++)
#pragma unroll
                    for (int dx = 0; dx < 3; dx++)
                        s = fmaf(sbw[dy * 3 + dx],
                                 ins[2 * syo + 1 + p + dy][2 * j + 1 + q + dx], s);
                base[p][q] = s * sbs;
            }
        float o00 = base[0][0] + y00, o01 = base[0][1] + y01;
        float o10 = base[1][0] + y10, o11 = base[1][1] + y11;
        outb[2 * syo][2 * j]         = o00;
        outb[2 * syo][2 * j + 1]     = o01;
        outb[2 * syo + 1][2 * j]     = o10;
        outb[2 * syo + 1][2 * j + 1] = o11;
        if (syo >= 1 && syo <= 16) {
            int gy = y0 - 2 + 2 * syo;
            Yc[(gy + 0) * 64 + 2 * j]     = o00;
            Yc[(gy + 0) * 64 + 2 * j + 1] = o01;
            Yc[(gy + 1) * 64 + 2 * j]     = o10;
            Yc[(gy + 1) * 64 + 2 * j + 1] = o11;
        }
    }
    __syncthreads();

    float sum = 0.f;
    for (int idx = tid; idx < 64 * 128; idx += 256) {
        int yl = idx >> 7, x = idx & 127;
        int yg = 64 * by + yl;
        int jy = yg >> 1, jx = x >> 1;
        int gy0, gy1, gx0, gx1; float wy0, wx0;
        if (yg & 1) { gy0 = jy; gy1 = (jy + 1 < 64) ? jy + 1 : 63; wy0 = 0.75f; }
        else        { gy0 = (jy > 0) ? jy - 1 : 0; gy1 = jy;       wy0 = 0.25f; }
        if (x & 1)  { gx0 = jx; gx1 = (jx + 1 < 64) ? jx + 1 : 63; wx0 = 0.75f; }
        else        { gx0 = (jx > 0) ? jx - 1 : 0; gx1 = jx;       wx0 = 0.25f; }
        float wy1 = 1.f - wy0, wx1 = 1.f - wx0;
        int l0 = gy0 - y0 + 2, l1 = gy1 - y0 + 2;
        float v = wy0 * (wx0 * outb[l0][gx0] + wx1 * outb[l0][gx1])
                + wy1 * (wx0 * outb[l1][gx0] + wx1 * outb[l1][gx1]);
        sum += v * v;
    }
    red[tid] = sum; __syncthreads();
    for (int o = 128; o > 0; o >>= 1) {
        if (tid < o) red[tid] += red[tid + o];
        __syncthreads();
    }
    if (tid == 0) atomicAdd(&qn2[bc], red[0]);
}

// ---------------- attention logits ----------------
__global__ __launch_bounds__(256) void attn_partial(
    const float* __restrict__ qp, const float* __restrict__ kp,
    float* __restrict__ logits, int N)
{
    __shared__ float qsT[64][33];
    __shared__ float ksT[64][33];
    int bh = blockIdx.y;
    int n0 = blockIdx.x * 512;
    const float* q = qp + (size_t)bh * 32 * N + n0;
    const float* k = kp + (size_t)bh * 32 * N + n0;
    int tid = threadIdx.x;
    int i0 = (tid & 7) * 4, j0 = ((tid >> 3) & 7) * 4, ns = tid >> 6;

    float acc[4][4];
#pragma unroll
    for (int i = 0; i < 4; i++)
#pragma unroll
        for (int j = 0; j < 4; j++) acc[i][j] = 0.f;

    for (int nc = 0; nc < 512; nc += 64) {
        for (int l = tid; l < 512; l += 256) {
            int row = l >> 4, col4 = (l & 15) * 4;
            float4 a = *(const float4*)(q + (size_t)row * N + nc + col4);
            float4 b = *(const float4*)(k + (size_t)row * N + nc + col4);
            qsT[col4 + 0][row] = a.x; qsT[col4 + 1][row] = a.y;
            qsT[col4 + 2][row] = a.z; qsT[col4 + 3][row] = a.w;
            ksT[col4 + 0][row] = b.x; ksT[col4 + 1][row] = b.y;
            ksT[col4 + 2][row] = b.z; ksT[col4 + 3][row] = b.w;
        }
        __syncthreads();
        for (int nn = ns; nn < 64; nn += 4) {
            float qv[4], kv[4];
#pragma unroll
            for (int m = 0; m < 4; m++) { qv[m] = qsT[nn][i0 + m]; kv[m] = ksT[nn][j0 + m]; }
#pragma unroll
            for (int i = 0; i < 4; i++)
#pragma unroll
                for (int j = 0; j < 4; j++)
                    acc[i][j] = fmaf(qv[i], kv[j], acc[i][j]);
        }
        __syncthreads();
    }
    float* L = logits + (size_t)bh * 1024;
#pragma unroll
    for (int i = 0; i < 4; i++)
#pragma unroll
        for (int j = 0; j < 4; j++)
            atomicAdd(&L[(i0 + i) * 32 + j0 + j], acc[i][j]);
}

// ---------------- fused softmax + (attn @ v) + proj WTConv(ks=1) -> d_out ----------------
__global__ __launch_bounds__(256) void av_proj_kernel(
    const float* __restrict__ logits, const float* __restrict__ qn2,
    const float* __restrict__ kn2, const float* __restrict__ temp,
    const float* __restrict__ v,
    const float* __restrict__ pbw, const float* __restrict__ pbs,
    const float* __restrict__ pww, const float* __restrict__ pws,
    float* __restrict__ out)
{
    __shared__ float As[32][33];
    __shared__ float2 vt[32][2][8];

    int by = blockIdx.x;
    int bh = blockIdx.y;
    int b  = bh >> 3, h = bh & 7;
    int tid = threadIdx.x;
    int i  = tid >> 3;
    int pb = tid & 7;

    for (int l = tid; l < 1024; l += 256) As[l >> 5][l & 31] = logits[(size_t)bh * 1024 + l];
    __syncthreads();

    // in-block softmax with folded L2 norms + temperature (warp w owns rows 4w..4w+3)
    {
        int w = tid >> 5, lane = tid & 31;
        float tmp = temp[h];
        float kvn = fmaxf(sqrtf(kn2[b * 256 + h * 32 + lane]), 1e-12f);
#pragma unroll
        for (int rr = 0; rr < 4; rr++) {
            int r = w * 4 + rr;
            float qvn = fmaxf(sqrtf(qn2[b * 256 + h * 32 + r]), 1e-12f);
            float val = As[r][lane] * tmp / (qvn * kvn);
            float m = val;
#pragma unroll
            for (int o = 16; o; o >>= 1) m = fmaxf(m, __shfl_xor_sync(0xffffffffu, m, o));
            float e = expf(val - m);
            float s = e;
#pragma unroll
            for (int o = 16; o; o >>= 1) s += __shfl_xor_sync(0xffffffffu, s, o);
            As[r][lane] = e / s;
        }
    }

    int cw = h * 32 + i;
    float bw  = pbw[cw] * pbs[cw];
    float wv0 = pww[cw * 4 + 0] * pws[cw * 4 + 0];
    float wv1 = pww[cw * 4 + 1] * pws[cw * 4 + 1];
    float wv2 = pww[cw * 4 + 2] * pws[cw * 4 + 2];
    float wv3 = pww[cw * 4 + 3] * pws[cw * 4 + 3];

    const float* vb = v + (size_t)(b * 256 + h * 32) * NK;
    float* ob = out + (size_t)(b * 256 + h * 32 + i) * NK;

    int sj = tid >> 3, sr = (tid >> 2) & 1, sxq = tid & 3;

    for (int bx0 = 0; bx0 < 64; bx0 += 8) {
        __syncthreads();
        {
            float4 v4 = *(const float4*)(vb + (size_t)sj * NK + (2 * by + sr) * 128
                                         + 2 * bx0 + sxq * 4);
            vt[sj][sr][2 * sxq + 0] = make_float2(v4.x, v4.y);
            vt[sj][sr][2 * sxq + 1] = make_float2(v4.z, v4.w);
        }
        __syncthreads();

        float a00 = 0.f, a01 = 0.f, a10 = 0.f, a11 = 0.f;
#pragma unroll
        for (int j = 0; j < 32; j++) {
            float aA = As[i][j];
            float2 t0 = vt[j][0][pb];
            float2 t1 = vt[j][1][pb];
            a00 = fmaf(aA, t0.x, a00); a01 = fmaf(aA, t0.y, a01);
            a10 = fmaf(aA, t1.x, a10); a11 = fmaf(aA, t1.y, a11);
        }

        float r0 = 0.5f * (a00 + a01 + a10 + a11) * wv0;
        float r1 = 0.5f * (a00 + a01 - a10 - a11) * wv1;
        float r2 = 0.5f * (a00 - a01 + a10 - a11) * wv2;
        float r3 = 0.5f * (a00 - a01 - a10 + a11) * wv3;
        float y00 = 0.5f * (r0 + r1 + r2 + r3) + a00 * bw;
        float y01 = 0.5f * (r0 + r1 - r2 - r3) + a01 * bw;
        float y10 = 0.5f * (r0 - r1 + r2 - r3) + a10 * bw;
        float y11 = 0.5f * (r0 - r1 - r2 + r3) + a11 * bw;

        int gx = 2 * (bx0 + pb);
        *(float2*)&ob[(2 * by + 0) * 128 + gx] = make_float2(y00, y01);
        *(float2*)&ob[(2 * by + 1) * 128 + gx] = make_float2(y10, y11);
    }
}

// ---------------- launch (multi-stream fork/join DAG) ----------------
#define GEMM_SMEM (1024 + 2 * 65536)

extern "C" void kernel_launch(void* const* d_in, const int* in_sizes, int n_in,
                              void* d_out, int out_size)
{
    const float* x    = (const float*)d_in[0];
    const float* cf   = (const float*)d_in[1];
    const float* Wq   = (const float*)d_in[2];
    const float* Wk   = (const float*)d_in[3];
    const float* Wv   = (const float*)d_in[4];
    const float* temp = (const float*)d_in[5];
    const float* qbw = (const float*)d_in[6];  const float* qbs = (const float*)d_in[7];
    const float* qww = (const float*)d_in[8];  const float* qws = (const float*)d_in[9];
    const float* kbw = (const float*)d_in[10]; const float* kbs = (const float*)d_in[11];
    const float* kww = (const float*)d_in[12]; const float* kws = (const float*)d_in[13];
    const float* vbw = (const float*)d_in[14]; const float* vbs = (const float*)d_in[15];
    const float* vww = (const float*)d_in[16]; const float* vws = (const float*)d_in[17];
    const float* pbw = (const float*)d_in[18]; const float* pbs = (const float*)d_in[19];
    const float* pww = (const float*)d_in[20]; const float* pws = (const float*)d_in[21];
    float* out = (float*)d_out;

    float *q, *kv, *qwt, *vwt, *kdn, *qn2, *kn2, *lg;
    __nv_bfloat16 *xt_hi, *xt_lo, *ct_hi, *ct_lo, *aq_hi, *aq_lo, *akv_hi, *akv_lo;
    cudaGetSymbolAddress((void**)&q,     g_q);
    cudaGetSymbolAddress((void**)&kv,    g_kv);
    cudaGetSymbolAddress((void**)&qwt,   g_qwt);
    cudaGetSymbolAddress((void**)&vwt,   g_vwt);
    cudaGetSymbolAddress((void**)&kdn,   g_kdn);
    cudaGetSymbolAddress((void**)&qn2,   g_qn2);
    cudaGetSymbolAddress((void**)&kn2,   g_kn2);
    cudaGetSymbolAddress((void**)&lg,    g_lg);
    cudaGetSymbolAddress((void**)&xt_hi, g_xt_hi);
    cudaGetSymbolAddress((void**)&xt_lo, g_xt_lo);
    cudaGetSymbolAddress((void**)&ct_hi, g_ct_hi);
    cudaGetSymbolAddress((void**)&ct_lo, g_ct_lo);
    cudaGetSymbolAddress((void**)&aq_hi, g_aq_hi);
    cudaGetSymbolAddress((void**)&aq_lo, g_aq_lo);
    cudaGetSymbolAddress((void**)&akv_hi, g_akv_hi);
    cudaGetSymbolAddress((void**)&akv_lo, g_akv_lo);

    cudaFuncSetAttribute(gemm_tc, cudaFuncAttributeMaxDynamicSharedMemorySize, GEMM_SMEM);
    cudaFuncSetAttribute(wtconv_k_down, cudaFuncAttributeMaxDynamicSharedMemorySize, KD_SMEM);

    static cudaStream_t s1 = nullptr, s2 = nullptr;
    static cudaEvent_t ev0 = nullptr, evW = nullptr, evE = nullptr, evF = nullptr, evH = nullptr;
    if (s1 == nullptr) {
        cudaStreamCreateWithFlags(&s1, cudaStreamNonBlocking);
        cudaStreamCreateWithFlags(&s2, cudaStreamNonBlocking);
        cudaEventCreateWithFlags(&ev0, cudaEventDisableTiming);
        cudaEventCreateWithFlags(&evW, cudaEventDisableTiming);
        cudaEventCreateWithFlags(&evE, cudaEventDisableTiming);
        cudaEventCreateWithFlags(&evF, cudaEventDisableTiming);
        cudaEventCreateWithFlags(&evH, cudaEventDisableTiming);
    }
    cudaStream_t s0 = 0;

    // fork
    cudaEventRecord(ev0, s0);
    cudaStreamWaitEvent(s1, ev0, 0);
    cudaStreamWaitEvent(s2, ev0, 0);

    // s2: weights convert + zero accumulators (off critical path)
    convert_w<<<768, 256, 0, s2>>>(Wq, Wk, Wv, aq_hi, aq_lo, akv_hi, akv_lo, lg, kn2, qn2);
    cudaEventRecord(evW, s2);

    // s1: q-path prologue
    convert_x<<<dim3(NQ / 32, 4, BATCH), 256, 0, s1>>>(x, xt_hi, xt_lo, NQ);
    cudaStreamWaitEvent(s1, evW, 0);
    gemm_tc<<<dim3(NQ / 128, 2, BATCH), 256, GEMM_SMEM, s1>>>(aq_hi, aq_lo, xt_hi, xt_lo, q, NQ);
    wtconv_q_norm<<<dim3(BATCH * CHN, 2), 256, 0, s1>>>(q, qwt, qbw, qbs, qww, qws, qn2);
    cudaEventRecord(evF, s1);

    // main: cf convert -> kv GEMM
    convert_x<<<dim3(NK / 32, 4, BATCH), 256, 0, s0>>>(cf, ct_hi, ct_lo, NK);
    cudaStreamWaitEvent(s0, evW, 0);
    gemm_tc<<<dim3(NK / 128, 4, BATCH), 256, GEMM_SMEM, s0>>>(akv_hi, akv_lo, ct_hi, ct_lo, kv, NK);
    cudaEventRecord(evE, s0);

    // s2: v wtconv (needs kv)
    cudaStreamWaitEvent(s2, evE, 0);
    wtconv_t<128><<<dim3(BATCH * CHN, 8), 256, 0, s2>>>(kv + (size_t)CHN * NK, vwt,
                                                        vbw, vbs, vww, vws, HK, 512);
    cudaEventRecord(evH, s2);

    // main: k wtconv + downsample + norm
    wtconv_k_down<<<dim3(BATCH * CHN, 8), 256, KD_SMEM, s0>>>(kv, kdn, kbw, kbs, kww, kws, kn2);

    // join q-path, attention logits
    cudaStreamWaitEvent(s0, evF, 0);
    attn_partial<<<dim3(NQ / 512, BATCH * HEADS), 256, 0, s0>>>(qwt, kdn, lg, NQ);

    // join v-path, fused softmax + av + proj
    cudaStreamWaitEvent(s0, evH, 0);
    av_proj_kernel<<<dim3(64, BATCH * HEADS), 256, 0, s0>>>(lg, qn2, kn2, temp, vwt,
                                                            pbw, pbs, pww, pws, out);
}

// round 10
// speedup vs baseline: 1.1539x; 1.1539x over previous
#include <cuda_runtime.h>
#include <cuda_bf16.h>
#include <math.h>
#include <stdint.h>

// ---------------- arch feature gate (tcgen05 is an "a"-feature) ----------------
#if defined(__CUDA_ARCH_FEAT_SM103_ALL) || defined(__CUDA_ARCH_FEAT_SM100_ALL) || \
    defined(__CUDA_ARCH_FEAT_SM101_ALL) || \
    (defined(__CUDA_ARCH_SPECIFIC__) && (__CUDA_ARCH_SPECIFIC__ >= 1000))
#define HAS_TCGEN05 1
#else
#define HAS_TCGEN05 0
#endif

// ---------------- problem constants ----------------
#define BATCH 2
#define CHN   256
#define HQ    64
#define WQ    64
#define HK    128
#define WK    128
#define NQ    (HQ*WQ)     // 4096
#define NK    (HK*WK)     // 16384
#define HEADS 8
#define CPH   32

// ---------------- scratch (device globals) ----------------
static __device__ float g_q  [BATCH*CHN*NQ];
static __device__ float g_kv [BATCH*2*CHN*NK];
static __device__ float g_qwt[BATCH*CHN*NQ];
static __device__ float g_vwt[BATCH*CHN*NK];
static __device__ float g_kdn[BATCH*CHN*NQ];
static __device__ float g_qn2[BATCH*CHN];
static __device__ float g_kn2[BATCH*CHN];
static __device__ float g_lg [BATCH*HEADS*CPH*CPH];
static __device__ __nv_bfloat16 g_xt_hi[BATCH*NQ*CHN];
static __device__ __nv_bfloat16 g_xt_lo[BATCH*NQ*CHN];
static __device__ __nv_bfloat16 g_ct_hi[BATCH*NK*CHN];
static __device__ __nv_bfloat16 g_ct_lo[BATCH*NK*CHN];
static __device__ __nv_bfloat16 g_aq_hi[CHN*CHN];
static __device__ __nv_bfloat16 g_aq_lo[CHN*CHN];
static __device__ __nv_bfloat16 g_akv_hi[2*CHN*CHN];
static __device__ __nv_bfloat16 g_akv_lo[2*CHN*CHN];

// ---------------- PTX helpers ----------------
__device__ __forceinline__ uint32_t smem_to_u32(const void* p) {
    uint32_t a;
    asm("{ .reg .u64 t; cvta.to.shared.u64 t, %1; cvt.u32.u64 %0, t; }" : "=r"(a) : "l"(p));
    return a;
}
#define SW128(o) ((o) ^ (((o) >> 3) & 0x70))

#if HAS_TCGEN05
__device__ __forceinline__ uint32_t elect_one_pred() {
    uint32_t pred;
    asm volatile("{\n\t.reg .pred p;\n\telect.sync _|p, 0xFFFFFFFF;\n\tselp.b32 %0, 1, 0, p;\n\t}"
                 : "=r"(pred));
    return pred;
}

static constexpr uint64_t SMEM_DESC_BASE_SW128 =
    (uint64_t(2) << 61) | (uint64_t(1) << 46) | (uint64_t(64) << 32) | (uint64_t(1) << 16);
#define MAKE_SMEM_DESC(base_addr) \
    (SMEM_DESC_BASE_SW128 | ((uint64_t)((base_addr) >> 4) & 0x3FFF))

#define TCGEN05_ALLOC(smem_result_addr, nCols) \
    asm volatile("tcgen05.alloc.cta_group::1.sync.aligned.shared::cta.b32 [%0], %1;" \
        :: "r"((uint32_t)(smem_result_addr)), "r"((uint32_t)(nCols)) : "memory")
#define TCGEN05_DEALLOC(tmem_addr, nCols) \
    asm volatile("tcgen05.dealloc.cta_group::1.sync.aligned.b32 %0, %1;" \
        :: "r"(tmem_addr), "r"((uint32_t)(nCols)))
#define TCGEN05_RELINQUISH() \
    asm volatile("tcgen05.relinquish_alloc_permit.cta_group::1.sync.aligned;")
#define TCGEN05_COMMIT(mbar_smem_addr) \
    asm volatile("tcgen05.commit.cta_group::1.mbarrier::arrive::one.shared::cluster.b64 [%0];" \
        :: "r"((uint32_t)(mbar_smem_addr)) : "memory")
#define TCGEN05_FENCE_AFTER() \
    asm volatile("tcgen05.fence::after_thread_sync;" ::: "memory")
#define TCGEN05_WAIT_LD() \
    asm volatile("tcgen05.wait::ld.sync.aligned;" ::: "memory")
#define FENCE_PROXY_ASYNC_SHARED_CTA() \
    asm volatile("fence.proxy.async.shared::cta;" ::: "memory")
#define MBARRIER_INIT(mbar, count) \
    asm volatile("mbarrier.init.shared.b64 [%0], %1;" \
        :: "r"((uint32_t)(mbar)), "r"((uint32_t)(count)) : "memory")
#define MBARRIER_INVAL(mbar) \
    asm volatile("mbarrier.inval.shared.b64 [%0];" :: "r"((uint32_t)(mbar)) : "memory")
#define MBARRIER_WAIT_PARITY(mbar_smem_addr, phase_parity) do { \
    uint32_t _mbar = (uint32_t)(mbar_smem_addr); \
    uint32_t _parity = (uint32_t)(phase_parity); \
    uint32_t _done; \
    asm volatile("{\n\t.reg .pred p;\n\t" \
        "mbarrier.try_wait.parity.acquire.cta.shared::cta.b64 p, [%1], %2;\n\t" \
        "selp.b32 %0, 1, 0, p;\n\t}" \
        : "=r"(_done) : "r"(_mbar), "r"(_parity) : "memory"); \
    if (!_done) { \
        asm volatile("{\n\t.reg .pred P1;\n\t" \
            "WAIT_LOOP_%=:\n\t" \
            "mbarrier.try_wait.parity.acquire.cta.shared::cta.b64 P1, [%0], %1, 0x989680;\n\t" \
            "@P1 bra.uni WAIT_DONE_%=;\n\t" \
            "bra.uni WAIT_LOOP_%=;\n\t" \
            "WAIT_DONE_%=:\n\t}" \
            :: "r"(_mbar), "r"(_parity) : "memory"); \
    } \
} while(0)

#define TCGEN05_LD_32X32B_X32(r, tmem_addr) \
    asm volatile("tcgen05.ld.sync.aligned.32x32b.x32.b32 " \
        "{%0, %1, %2, %3, %4, %5, %6, %7, %8, %9, %10, %11, %12, %13, %14, %15, " \
        " %16, %17, %18, %19, %20, %21, %22, %23, %24, %25, %26, %27, %28, %29, %30, %31}, [%32];" \
        : "=r"((r)[0]),  "=r"((r)[1]),  "=r"((r)[2]),  "=r"((r)[3]), \
          "=r"((r)[4]),  "=r"((r)[5]),  "=r"((r)[6]),  "=r"((r)[7]), \
          "=r"((r)[8]),  "=r"((r)[9]),  "=r"((r)[10]), "=r"((r)[11]), \
          "=r"((r)[12]), "=r"((r)[13]), "=r"((r)[14]), "=r"((r)[15]), \
          "=r"((r)[16]), "=r"((r)[17]), "=r"((r)[18]), "=r"((r)[19]), \
          "=r"((r)[20]), "=r"((r)[21]), "=r"((r)[22]), "=r"((r)[23]), \
          "=r"((r)[24]), "=r"((r)[25]), "=r"((r)[26]), "=r"((r)[27]), \
          "=r"((r)[28]), "=r"((r)[29]), "=r"((r)[30]), "=r"((r)[31]) \
        : "r"(tmem_addr))

__device__ __forceinline__ void mma_f16_ss(uint32_t d_tmem, uint64_t a_desc, uint64_t b_desc,
                                           uint32_t idesc, uint32_t enable_d) {
    asm volatile(
        "{\n\t.reg .pred p;\n\t"
        "setp.ne.u32 p, %4, 0;\n\t"
        "tcgen05.mma.cta_group::1.kind::f16 [%0], %1, %2, %3, {%5, %5, %5, %5}, p;\n\t}"
        :: "r"(d_tmem), "l"(a_desc), "l"(b_desc), "r"(idesc), "r"(enable_d), "r"(0u)
        : "memory");
}

static constexpr uint32_t GEMM_IDESC =
    (1u << 4) | (1u << 7) | (1u << 10) | ((128u / 8u) << 17) | ((128u / 16u) << 24);
#endif  // HAS_TCGEN05

// ---------------- convert helpers ----------------
__device__ __forceinline__ void split_bf16(float x, __nv_bfloat16& h, __nv_bfloat16& l) {
    h = __float2bfloat16(x);
    l = __float2bfloat16(x - __bfloat162float(h));
}
__device__ __forceinline__ float bfu2f(uint32_t u16) {
    return __bfloat162float(__ushort_as_bfloat16((unsigned short)u16));
}

__global__ void convert_w(const float* __restrict__ Wq, const float* __restrict__ Wk,
                          const float* __restrict__ Wv,
                          __nv_bfloat16* __restrict__ aq_hi, __nv_bfloat16* __restrict__ aq_lo,
                          __nv_bfloat16* __restrict__ akv_hi, __nv_bfloat16* __restrict__ akv_lo,
                          float* __restrict__ lg, float* __restrict__ kn2,
                          float* __restrict__ qn2)
{
    if (blockIdx.x == 0) {
        for (int i = threadIdx.x; i < BATCH*HEADS*CPH*CPH; i += 256) lg[i] = 0.f;
        for (int i = threadIdx.x; i < BATCH*CHN; i += 256) { kn2[i] = 0.f; qn2[i] = 0.f; }
    }
    int i = blockIdx.x * 256 + threadIdx.x;
    __nv_bfloat16 h, l;
    if (i < 65536) {
        split_bf16(Wq[i], h, l); aq_hi[i] = h; aq_lo[i] = l;
    } else if (i < 131072) {
        int j = i - 65536;
        split_bf16(Wk[j], h, l); akv_hi[j] = h; akv_lo[j] = l;
    } else {
        int j = i - 131072;
        split_bf16(Wv[j], h, l); akv_hi[65536 + j] = h; akv_lo[65536 + j] = l;
    }
}

// ---------------- X convert: [B,C,N] f32 -> [B,N,C] bf16 hi/lo ----------------
__global__ __launch_bounds__(256) void convert_x(const float* __restrict__ X,
                                                 __nv_bfloat16* __restrict__ Th,
                                                 __nv_bfloat16* __restrict__ Tl, int N)
{
    __shared__ float s[64][33];
    int b = blockIdx.z, c0 = blockIdx.y * 64, n0 = blockIdx.x * 32;
    const float* Xb = X + (size_t)b * 256 * N;
    int lane = threadIdx.x & 31, w = threadIdx.x >> 5;
#pragma unroll
    for (int i = 0; i < 8; i++) {
        int c = w + i * 8;
        s[c][lane] = Xb[(size_t)(c0 + c) * N + n0 + lane];
    }
    __syncthreads();
    uint32_t* TH = (uint32_t*)(Th + (size_t)b * N * 256);
    uint32_t* TL = (uint32_t*)(Tl + (size_t)b * N * 256);
#pragma unroll
    for (int i = 0; i < 4; i++) {
        int n = w + i * 8;
        float x0 = s[2 * lane][n], x1 = s[2 * lane + 1][n];
        __nv_bfloat16 h0, l0, h1, l1;
        split_bf16(x0, h0, l0); split_bf16(x1, h1, l1);
        uint32_t hp = ((uint32_t)__bfloat16_as_ushort(h1) << 16) | __bfloat16_as_ushort(h0);
        uint32_t lp = ((uint32_t)__bfloat16_as_ushort(l1) << 16) | __bfloat16_as_ushort(l0);
        size_t idx = (size_t)(n0 + n) * 128 + (c0 >> 1) + lane;
        TH[idx] = hp; TL[idx] = lp;
    }
}

// ---------------- GEMM ----------------
#if HAS_TCGEN05
__device__ __forceinline__ void load_tile_sw(const __nv_bfloat16* __restrict__ src,
                                             char* __restrict__ dst, int tid)
{
#pragma unroll
    for (int it = 0; it < 4; it++) {
        int i = tid + it * 256;
        int row = i >> 3, seg = i & 7;
        uint4 v = *(const uint4*)(src + (size_t)row * 256 + seg * 8);
        uint32_t off = (uint32_t)(row * 128 + seg * 16);
        *(uint4*)(dst + SW128(off)) = v;
    }
}
#endif

__global__ __launch_bounds__(256, 1) void gemm_tc(
    const __nv_bfloat16* __restrict__ Ahi, const __nv_bfloat16* __restrict__ Alo,
    const __nv_bfloat16* __restrict__ Bhi, const __nv_bfloat16* __restrict__ Blo,
    float* __restrict__ Y, int Ntot)
{
    extern __shared__ char dsm[];
    int tid = threadIdx.x;
    int m0 = blockIdx.y * 128, n0 = blockIdx.x * 128, b = blockIdx.z;
    int Mtot = gridDim.y * 128;
    const __nv_bfloat16* Bh = Bhi + (size_t)b * Ntot * 256;
    const __nv_bfloat16* Bl = Blo + (size_t)b * Ntot * 256;
    float* Yb = Y + (size_t)b * Mtot * Ntot;

#if HAS_TCGEN05
    __shared__ uint32_t s_tmem[1];
    __shared__ unsigned long long s_mbar[2];
    uint32_t dsm_u = smem_to_u32(dsm);
    uint32_t sb = (dsm_u + 1023) & ~1023u;
    char* sbp = dsm + (sb - dsm_u);
    uint32_t mb[2] = { smem_to_u32(&s_mbar[0]), smem_to_u32(&s_mbar[1]) };
    int wid = tid >> 5;

    if (wid == 0) TCGEN05_ALLOC(smem_to_u32(s_tmem), 128);
    if (tid == 0) { MBARRIER_INIT(mb[0], 1); MBARRIER_INIT(mb[1], 1); }
    __syncthreads();
    uint32_t tbase = s_tmem[0];

    for (int ch = 0; ch < 4; ch++) {
        int buf = ch & 1;
        char* bp = sbp + buf * 65536;
        if (ch >= 2) MBARRIER_WAIT_PARITY(mb[buf], 0);
        int c0 = ch * 64;
        load_tile_sw(Ahi + (size_t)m0 * 256 + c0, bp,          tid);
        load_tile_sw(Alo + (size_t)m0 * 256 + c0, bp + 16384,  tid);
        load_tile_sw(Bh  + (size_t)n0 * 256 + c0, bp + 32768,  tid);
        load_tile_sw(Bl  + (size_t)n0 * 256 + c0, bp + 49152,  tid);
        FENCE_PROXY_ASYNC_SHARED_CTA();
        __syncthreads();
        if (wid == 0) {
            if (elect_one_pred()) {
                uint32_t base = sb + buf * 65536;
                uint64_t dah = MAKE_SMEM_DESC(base);
                uint64_t dal = MAKE_SMEM_DESC(base + 16384);
                uint64_t dbh = MAKE_SMEM_DESC(base + 32768);
                uint64_t dbl = MAKE_SMEM_DESC(base + 49152);
#pragma unroll
                for (int k = 0; k < 4; k++)
                    mma_f16_ss(tbase, dah + 2 * k, dbh + 2 * k, GEMM_IDESC,
                               (ch > 0 || k > 0) ? 1u : 0u);
#pragma unroll
                for (int k = 0; k < 4; k++)
                    mma_f16_ss(tbase, dah + 2 * k, dbl + 2 * k, GEMM_IDESC, 1u);
#pragma unroll
                for (int k = 0; k < 4; k++)
                    mma_f16_ss(tbase, dal + 2 * k, dbh + 2 * k, GEMM_IDESC, 1u);
                TCGEN05_COMMIT(mb[buf]);
            }
        }
    }

    MBARRIER_WAIT_PARITY(mb[0], 1);
    MBARRIER_WAIT_PARITY(mb[1], 1);
    TCGEN05_FENCE_AFTER();

    float* Ds = (float*)sbp;
    uint32_t woff = (uint32_t)(wid & 3) << 21;
    int cb0 = (wid >= 4) ? 2 : 0;
    int lane = tid & 31;
    int row = (wid & 3) * 32 + lane;
    uint32_t regs[32];
#pragma unroll
    for (int j = 0; j < 2; j++) {
        int cb = cb0 + j;
        TCGEN05_LD_32X32B_X32(regs, tbase + cb * 32 + woff);
        TCGEN05_WAIT_LD();
#pragma unroll
        for (int c = 0; c < 32; c++)
            Ds[row * 132 + cb * 32 + c] = __uint_as_float(regs[c]);
    }
    __syncthreads();
#pragma unroll
    for (int it = 0; it < 16; it++) {
        int i = tid + it * 256;
        int r = i >> 5, c4 = (i & 31) * 4;
        float4 v = *(float4*)&Ds[r * 132 + c4];
        *(float4*)&Yb[(size_t)(m0 + r) * Ntot + n0 + c4] = v;
    }
    __syncthreads();
    if (tid == 0) { MBARRIER_INVAL(mb[0]); MBARRIER_INVAL(mb[1]); }
    if (wid == 0) { TCGEN05_RELINQUISH(); TCGEN05_DEALLOC(tbase, 128); }

#else  // SIMT fallback
    float* As = (float*)dsm;
    float* Bs = As + 8 * 128;
    int ty = tid >> 4, tx = tid & 15;
    int r = tid >> 1, kq = (tid & 1) * 4;

    float acc[8][8];
#pragma unroll
    for (int i = 0; i < 8; i++)
#pragma unroll
        for (int j = 0; j < 8; j++) acc[i][j] = 0.f;

    for (int c0 = 0; c0 < 256; c0 += 8) {
        {
            size_t off = (size_t)(m0 + r) * 256 + c0 + kq;
            uint2 vh = *(const uint2*)(Ahi + off);
            uint2 vl = *(const uint2*)(Alo + off);
            As[(kq + 0) * 128 + r] = bfu2f(vh.x & 0xffff)  + bfu2f(vl.x & 0xffff);
            As[(kq + 1) * 128 + r] = bfu2f(vh.x >> 16)     + bfu2f(vl.x >> 16);
            As[(kq + 2) * 128 + r] = bfu2f(vh.y & 0xffff)  + bfu2f(vl.y & 0xffff);
            As[(kq + 3) * 128 + r] = bfu2f(vh.y >> 16)     + bfu2f(vl.y >> 16);
            size_t offb = (size_t)(n0 + r) * 256 + c0 + kq;
            uint2 wh = *(const uint2*)(Bh + offb);
            uint2 wl = *(const uint2*)(Bl + offb);
            Bs[(kq + 0) * 128 + r] = bfu2f(wh.x & 0xffff)  + bfu2f(wl.x & 0xffff);
            Bs[(kq + 1) * 128 + r] = bfu2f(wh.x >> 16)     + bfu2f(wl.x >> 16);
            Bs[(kq + 2) * 128 + r] = bfu2f(wh.y & 0xffff)  + bfu2f(wl.y & 0xffff);
            Bs[(kq + 3) * 128 + r] = bfu2f(wh.y >> 16)     + bfu2f(wl.y >> 16);
        }
        __syncthreads();
#pragma unroll
        for (int kk = 0; kk < 8; kk++) {
            float a[8], bb[8];
            *(float4*)&a[0]  = *(const float4*)&As[kk * 128 + ty * 8];
            *(float4*)&a[4]  = *(const float4*)&As[kk * 128 + ty * 8 + 4];
            *(float4*)&bb[0] = *(const float4*)&Bs[kk * 128 + tx * 8];
            *(float4*)&bb[4] = *(const float4*)&Bs[kk * 128 + tx * 8 + 4];
#pragma unroll
            for (int i = 0; i < 8; i++)
#pragma unroll
                for (int j = 0; j < 8; j++)
                    acc[i][j] = fmaf(a[i], bb[j], acc[i][j]);
        }
        __syncthreads();
    }
#pragma unroll
    for (int i = 0; i < 8; i++) {
        float* yp = Yb + (size_t)(m0 + ty * 8 + i) * Ntot + n0 + tx * 8;
        *(float4*)yp       = make_float4(acc[i][0], acc[i][1], acc[i][2], acc[i][3]);
        *(float4*)(yp + 4) = make_float4(acc[i][4], acc[i][5], acc[i][6], acc[i][7]);
    }
#endif
}

// ---------------- plain templated WTConv (Haar, ks=3), 32-row tiles — used for v ----------------
template<int W>
__global__ __launch_bounds__(256) void wtconv_t(
    const float* __restrict__ X, float* __restrict__ Y,
    const float* __restrict__ base_w, const float* __restrict__ base_s,
    const float* __restrict__ wav_w,  const float* __restrict__ wav_s,
    int H, int cs_in)
{
    constexpr int LW = W + 4;
    constexpr int SWc = (W >> 1) + 2;
    constexpr int Wh = W >> 1;
    __shared__ float ins[36][LW];
    __shared__ float sub[4][18][SWc];
    __shared__ float swav[4][9];
    __shared__ float sbw[9];
    __shared__ float swsc[4];
    __shared__ float sbs;

    int bc = blockIdx.x;
    int b  = bc >> 8;
    int c  = bc & 255;
    int y0 = blockIdx.y * 32;
    const float* Xc = X + ((size_t)b * cs_in + c) * H * W;
    float*       Yc = Y + (size_t)bc * H * W;
    int tid = threadIdx.x;

    if (tid < 36) {
        int f = tid / 9, i = tid - f * 9;
        swav[f][i] = wav_w[(size_t)(c * 4 + f) * 9 + i];
    } else if (tid < 45) {
        sbw[tid - 36] = base_w[(size_t)c * 9 + tid - 36];
    } else if (tid < 49) {
        swsc[tid - 45] = wav_s[c * 4 + tid - 45];
    } else if (tid == 49) {
        sbs = base_s[c];
    }

    for (int idx = tid; idx < 36 * LW; idx += 256) {
        int ly = idx / LW, lx = idx - ly * LW;
        int gy = y0 + ly - 2, gx = lx - 2;
        float v = 0.f;
        if (gy >= 0 && gy < H && gx >= 0 && gx < W) v = Xc[gy * W + gx];
        ins[ly][lx] = v;
    }
    __syncthreads();

    for (int idx = tid; idx < 18 * SWc; idx += 256) {
        int sy = idx / SWc, sx = idx - sy * SWc;
        float a = ins[2 * sy][2 * sx],     bq = ins[2 * sy][2 * sx + 1];
        float d = ins[2 * sy + 1][2 * sx], e = ins[2 * sy + 1][2 * sx + 1];
        sub[0][sy][sx] = 0.5f * (a + bq + d + e);
        sub[1][sy][sx] = 0.5f * (a + bq - d - e);
        sub[2][sy][sx] = 0.5f * (a - bq + d - e);
        sub[3][sy][sx] = 0.5f * (a - bq - d + e);
    }
    __syncthreads();

    for (int idx = tid; idx < 16 * Wh; idx += 256) {
        int syi = idx / Wh, sxi = idx - syi * Wh;
        int sy = syi + 1, sx = sxi + 1;
        float r[4];
#pragma unroll
        for (int f = 0; f < 4; f++) {
            float s = 0.f;
#pragma unroll
            for (int dy = 0; dy < 3; dy++)
#pragma unroll
                for (int dx = 0; dx < 3; dx++)
                    s = fmaf(swav[f][dy * 3 + dx], sub[f][sy - 1 + dy][sx - 1 + dx], s);
            r[f] = s * swsc[f];
        }
        float y00 = 0.5f * (r[0] + r[1] + r[2] + r[3]);
        float y01 = 0.5f * (r[0] + r[1] - r[2] - r[3]);
        float y10 = 0.5f * (r[0] - r[1] + r[2] - r[3]);
        float y11 = 0.5f * (r[0] - r[1] - r[2] + r[3]);

        float base[2][2];
#pragma unroll
        for (int p = 0; p < 2; p++)
#pragma unroll
            for (int q = 0; q < 2; q++) {
                float s = 0.f;
#pragma unroll
                for (int dy = 0; dy < 3; dy++)
#pragma unroll
                    for (int dx = 0; dx < 3; dx++)
                        s = fmaf(sbw[dy * 3 + dx],
                                 ins[2 * sy + p - 1 + dy][2 * sx + q - 1 + dx], s);
                base[p][q] = s * sbs;
            }
        int gy = y0 + 2 * syi, gx = 2 * sxi;
        Yc[(gy + 0) * W + gx + 0] = base[0][0] + y00;
        Yc[(gy + 0) * W + gx + 1] = base[0][1] + y01;
        Yc[(gy + 1) * W + gx + 0] = base[1][0] + y10;
        Yc[(gy + 1) * W + gx + 1] = base[1][1] + y11;
    }
}

// ---------------- fused wtconv(k) + transposed-bilinear downsample + ||k||², 32-row tiles ----------------
#define KD_SMEM ((40*132 + 4*20*66 + 36*130) * 4)

__global__ __launch_bounds__(256) void wtconv_k_down(
    const float* __restrict__ X, float* __restrict__ kdn,
    const float* __restrict__ base_w, const float* __restrict__ base_s,
    const float* __restrict__ wav_w,  const float* __restrict__ wav_s,
    float* __restrict__ kn2)
{
    extern __shared__ float sm[];
    float* ins  = sm;                    // [40][132]
    float* sub  = ins + 40 * 132;        // [4][20][66]
    float* outb = sub + 4 * 20 * 66;     // [36][130]
    __shared__ float swav[4][9];
    __shared__ float sbw[9];
    __shared__ float swsc[4];
    __shared__ float sbs;
    __shared__ float red[256];

    int bc = blockIdx.x;
    int b  = bc >> 8;
    int c  = bc & 255;
    int by = blockIdx.y;
    int y0 = by * 32;
    const float* Xc = X + ((size_t)b * 512 + c) * (size_t)NK;
    int tid = threadIdx.x;

    if (tid < 36) {
        int f = tid / 9, i = tid - f * 9;
        swav[f][i] = wav_w[(size_t)(c * 4 + f) * 9 + i];
    } else if (tid < 45) {
        sbw[tid - 36] = base_w[(size_t)c * 9 + tid - 36];
    } else if (tid < 49) {
        swsc[tid - 45] = wav_s[c * 4 + tid - 45];
    } else if (tid == 49) {
        sbs = base_s[c];
    }

    for (int idx = tid; idx < 40 * 132; idx += 256) {
        int ly = idx / 132, lx = idx - ly * 132;
        int gy = y0 + ly - 4, gx = lx - 2;
        float v = 0.f;
        if (gy >= 0 && gy < 128 && gx >= 0 && gx < 128) v = Xc[gy * 128 + gx];
        ins[idx] = v;
    }
    __syncthreads();

    for (int idx = tid; idx < 20 * 66; idx += 256) {
        int sy = idx / 66, sx = idx - sy * 66;
        const float* r0 = ins + (2 * sy) * 132 + 2 * sx;
        float a = r0[0], bq = r0[1], d = r0[132], e = r0[133];
        sub[0 * 1320 + idx] = 0.5f * (a + bq + d + e);
        sub[1 * 1320 + idx] = 0.5f * (a + bq - d - e);
        sub[2 * 1320 + idx] = 0.5f * (a - bq + d - e);
        sub[3 * 1320 + idx] = 0.5f * (a - bq - d + e);
    }
    __syncthreads();

    for (int idx = tid; idx < 18 * 64; idx += 256) {
        int syo = idx >> 6, j = idx & 63;
        int sy = syo + 1, sx = j + 1;
        float r[4];
#pragma unroll
        for (int f = 0; f < 4; f++) {
            const float* sf = sub + f * 1320;
            float s = 0.f;
#pragma unroll
            for (int dy = 0; dy < 3; dy++)
#pragma unroll
                for (int dx = 0; dx < 3; dx++)
                    s = fmaf(swav[f][dy * 3 + dx], sf[(sy - 1 + dy) * 66 + sx - 1 + dx], s);
            r[f] = s * swsc[f];
        }
        float y00 = 0.5f * (r[0] + r[1] + r[2] + r[3]);
        float y01 = 0.5f * (r[0] + r[1] - r[2] - r[3]);
        float y10 = 0.5f * (r[0] - r[1] + r[2] - r[3]);
        float y11 = 0.5f * (r[0] - r[1] - r[2] + r[3]);

        float base[2][2];
#pragma unroll
        for (int p = 0; p < 2; p++)
#pragma unroll
            for (int q = 0; q < 2; q++) {
                float s = 0.f;
#pragma unroll
                for (int dy = 0; dy < 3; dy++)
#pragma unroll
                    for (int dx = 0; dx < 3; dx++)
                        s = fmaf(sbw[dy * 3 + dx],
                                 ins[(2 * syo + 1 + p + dy) * 132 + 2 * j + 1 + q + dx], s);
                base[p][q] = s * sbs;
            }
        outb[(2 * syo) * 130 + 2 * j]         = base[0][0] + y00;
        outb[(2 * syo) * 130 + 2 * j + 1]     = base[0][1] + y01;
        outb[(2 * syo + 1) * 130 + 2 * j]     = base[1][0] + y10;
        outb[(2 * syo + 1) * 130 + 2 * j + 1] = base[1][1] + y11;
    }
    __syncthreads();

    float sumsq = 0.f;
    for (int idx = tid; idx < 32 * 128; idx += 256) {
        int lr = (idx >> 7) + 2, lc = idx & 127;
        float v = outb[lr * 130 + lc];
        sumsq += v * v;
    }

    for (int idx = tid; idx < 16 * 64; idx += 256) {
        int jj = idx >> 6, jx = idx & 63;
        int jy = 16 * by + jj;
        int lyt[4]; float wyt[4]; int cy = 0;
        if (jy > 0)  { lyt[cy] = 2*jj+1; wyt[cy++] = 0.25f; }
        lyt[cy] = 2*jj+2; wyt[cy++] = (jy == 0)  ? 1.0f : 0.75f;
        lyt[cy] = 2*jj+3; wyt[cy++] = (jy == 63) ? 1.0f : 0.75f;
        if (jy < 63) { lyt[cy] = 2*jj+4; wyt[cy++] = 0.25f; }
        int lxt[4]; float wxt[4]; int cx = 0;
        if (jx > 0)  { lxt[cx] = 2*jx-1; wxt[cx++] = 0.25f; }
        lxt[cx] = 2*jx;   wxt[cx++] = (jx == 0)  ? 1.0f : 0.75f;
        lxt[cx] = 2*jx+1; wxt[cx++] = (jx == 63) ? 1.0f : 0.75f;
        if (jx < 63) { lxt[cx] = 2*jx+2; wxt[cx++] = 0.25f; }
        float s = 0.f;
        for (int a = 0; a < cy; a++) {
            const float* row = outb + lyt[a] * 130;
            float rs = 0.f;
            for (int e = 0; e < cx; e++) rs = fmaf(wxt[e], row[lxt[e]], rs);
            s = fmaf(wyt[a], rs, s);
        }
        kdn[(size_t)bc * NQ + jy * 64 + jx] = s;
    }

    red[tid] = sumsq; __syncthreads();
    for (int o = 128; o > 0; o >>= 1) {
        if (tid < o) red[tid] += red[tid + o];
        __syncthreads();
    }
    if (tid == 0) atomicAdd(&kn2[bc], red[0]);
}

// ---------------- fused wtconv(q) + ||upsample(q)||² (atomic) ----------------
__global__ __launch_bounds__(256) void wtconv_q_norm(
    const float* __restrict__ X, float* __restrict__ Y,
    const float* __restrict__ base_w, const float* __restrict__ base_s,
    const float* __restrict__ wav_w,  const float* __restrict__ wav_s,
    float* __restrict__ qn2)
{
    __shared__ float ins[40][68];
    __shared__ float sub[4][20][36];
    __shared__ float outb[36][66];
    __shared__ float swav[4][9];
    __shared__ float sbw[9];
    __shared__ float swsc[4];
    __shared__ float sbs;
    __shared__ float red[256];

    int bc = blockIdx.x;
    int c  = bc & 255;
    int by = blockIdx.y;
    int y0 = by * 32;
    const float* Xc = X + (size_t)bc * NQ;
    float*       Yc = Y + (size_t)bc * NQ;
    int tid = threadIdx.x;

    if (tid < 36) {
        int f = tid / 9, i = tid - f * 9;
        swav[f][i] = wav_w[(size_t)(c * 4 + f) * 9 + i];
    } else if (tid < 45) {
        sbw[tid - 36] = base_w[(size_t)c * 9 + tid - 36];
    } else if (tid < 49) {
        swsc[tid - 45] = wav_s[c * 4 + tid - 45];
    } else if (tid == 49) {
        sbs = base_s[c];
    }

    for (int idx = tid; idx < 40 * 68; idx += 256) {
        int ly = idx / 68, lx = idx - ly * 68;
        int gy = y0 + ly - 4, gx = lx - 2;
        float v = 0.f;
        if (gy >= 0 && gy < 64 && gx >= 0 && gx < 64) v = Xc[gy * 64 + gx];
        ins[ly][lx] = v;
    }
    __syncthreads();

    for (int idx = tid; idx < 20 * 34; idx += 256) {
        int sy = idx / 34, sx = idx - sy * 34;
        float a = ins[2 * sy][2 * sx],     bq = ins[2 * sy][2 * sx + 1];
        float d = ins[2 * sy + 1][2 * sx], e = ins[2 * sy + 1][2 * sx + 1];
        sub[0][sy][sx] = 0.5f * (a + bq + d + e);
        sub[1][sy][sx] = 0.5f * (a + bq - d - e);
        sub[2][sy][sx] = 0.5f * (a - bq + d - e);
        sub[3][sy][sx] = 0.5f * (a - bq - d + e);
    }
    __syncthreads();

    for (int idx = tid; idx < 18 * 32; idx += 256) {
        int syo = idx >> 5, j = idx & 31;
        int sy = syo + 1, sx = j + 1;
        float r[4];
#pragma unroll
        for (int f = 0; f < 4; f++) {
            float s = 0.f;
#pragma unroll
            for (int dy = 0; dy < 3; dy++)
#pragma unroll
                for (int dx = 0; dx < 3; dx++)
                    s = fmaf(swav[f][dy * 3 + dx], sub[f][sy - 1 + dy][sx - 1 + dx], s);
            r[f] = s * swsc[f];
        }
        float y00 = 0.5f * (r[0] + r[1] + r[2] + r[3]);
        float y01 = 0.5f * (r[0] + r[1] - r[2] - r[3]);
        float y10 = 0.5f * (r[0] - r[1] + r[2] - r[3]);
        float y11 = 0.5f * (r[0] - r[1] - r[2] + r[3]);

        float base[2][2];
#pragma unroll
        for (int p = 0; p < 2; p++)
#pragma unroll
            for (int q = 0; q < 2; q++) {
                float s = 0.f;
#pragma unroll
                for (int dy = 0; dy < 3; dy++)
#pragma unroll
                    for (int dx = 0; dx < 3; dx++)
                        s = fmaf(sbw[dy * 3 + dx],
                                 ins[2 * syo + 1 + p + dy][2 * j + 1 + q + dx], s);
                base[p][q] = s * sbs;
            }
        float o00 = base[0][0] + y00, o01 = base[0][1] + y01;
        float o10 = base[1][0] + y10, o11 = base[1][1] + y11;
        outb[2 * syo][2 * j]         = o00;
        outb[2 * syo][2 * j + 1]     = o01;
        outb[2 * syo + 1][2 * j]     = o10;
        outb[2 * syo + 1][2 * j + 1] = o11;
        if (syo >= 1 && syo <= 16) {
            int gy = y0 - 2 + 2 * syo;
            Yc[(gy + 0) * 64 + 2 * j]     = o00;
            Yc[(gy + 0) * 64 + 2 * j + 1] = o01;
            Yc[(gy + 1) * 64 + 2 * j]     = o10;
            Yc[(gy + 1) * 64 + 2 * j + 1] = o11;
        }
    }
    __syncthreads();

    float sum = 0.f;
    for (int idx = tid; idx < 64 * 128; idx += 256) {
        int yl = idx >> 7, x = idx & 127;
        int yg = 64 * by + yl;
        int jy = yg >> 1, jx = x >> 1;
        int gy0, gy1, gx0, gx1; float wy0, wx0;
        if (yg & 1) { gy0 = jy; gy1 = (jy + 1 < 64) ? jy + 1 : 63; wy0 = 0.75f; }
        else        { gy0 = (jy > 0) ? jy - 1 : 0; gy1 = jy;       wy0 = 0.25f; }
        if (x & 1)  { gx0 = jx; gx1 = (jx + 1 < 64) ? jx + 1 : 63; wx0 = 0.75f; }
        else        { gx0 = (jx > 0) ? jx - 1 : 0; gx1 = jx;       wx0 = 0.25f; }
        float wy1 = 1.f - wy0, wx1 = 1.f - wx0;
        int l0 = gy0 - y0 + 2, l1 = gy1 - y0 + 2;
        float v = wy0 * (wx0 * outb[l0][gx0] + wx1 * outb[l0][gx1])
                + wy1 * (wx0 * outb[l1][gx0] + wx1 * outb[l1][gx1]);
        sum += v * v;
    }
    red[tid] = sum; __syncthreads();
    for (int o = 128; o > 0; o >>= 1) {
        if (tid < o) red[tid] += red[tid + o];
        __syncthreads();
    }
    if (tid == 0) atomicAdd(&qn2[bc], red[0]);
}

// ---------------- attention logits ----------------
__global__ __launch_bounds__(256) void attn_partial(
    const float* __restrict__ qp, const float* __restrict__ kp,
    float* __restrict__ logits, int N)
{
    __shared__ float qsT[64][33];
    __shared__ float ksT[64][33];
    int bh = blockIdx.y;
    int n0 = blockIdx.x * 512;
    const float* q = qp + (size_t)bh * 32 * N + n0;
    const float* k = kp + (size_t)bh * 32 * N + n0;
    int tid = threadIdx.x;
    int i0 = (tid & 7) * 4, j0 = ((tid >> 3) & 7) * 4, ns = tid >> 6;

    float acc[4][4];
#pragma unroll
    for (int i = 0; i < 4; i++)
#pragma unroll
        for (int j = 0; j < 4; j++) acc[i][j] = 0.f;

    for (int nc = 0; nc < 512; nc += 64) {
        for (int l = tid; l < 512; l += 256) {
            int row = l >> 4, col4 = (l & 15) * 4;
            float4 a = *(const float4*)(q + (size_t)row * N + nc + col4);
            float4 b = *(const float4*)(k + (size_t)row * N + nc + col4);
            qsT[col4 + 0][row] = a.x; qsT[col4 + 1][row] = a.y;
            qsT[col4 + 2][row] = a.z; qsT[col4 + 3][row] = a.w;
            ksT[col4 + 0][row] = b.x; ksT[col4 + 1][row] = b.y;
            ksT[col4 + 2][row] = b.z; ksT[col4 + 3][row] = b.w;
        }
        __syncthreads();
        for (int nn = ns; nn < 64; nn += 4) {
            float qv[4], kv[4];
#pragma unroll
            for (int m = 0; m < 4; m++) { qv[m] = qsT[nn][i0 + m]; kv[m] = ksT[nn][j0 + m]; }
#pragma unroll
            for (int i = 0; i < 4; i++)
#pragma unroll
                for (int j = 0; j < 4; j++)
                    acc[i][j] = fmaf(qv[i], kv[j], acc[i][j]);
        }
        __syncthreads();
    }
    float* L = logits + (size_t)bh * 1024;
#pragma unroll
    for (int i = 0; i < 4; i++)
#pragma unroll
        for (int j = 0; j < 4; j++)
            atomicAdd(&L[(i0 + i) * 32 + j0 + j], acc[i][j]);
}

// ---------------- fused softmax + (attn @ v) + proj WTConv(ks=1) -> d_out ----------------
__global__ __launch_bounds__(256) void av_proj_kernel(
    const float* __restrict__ logits, const float* __restrict__ qn2,
    const float* __restrict__ kn2, const float* __restrict__ temp,
    const float* __restrict__ v,
    const float* __restrict__ pbw, const float* __restrict__ pbs,
    const float* __restrict__ pww, const float* __restrict__ pws,
    float* __restrict__ out)
{
    __shared__ float As[32][33];
    __shared__ float2 vt[32][2][8];

    int by = blockIdx.x;
    int bh = blockIdx.y;
    int b  = bh >> 3, h = bh & 7;
    int tid = threadIdx.x;
    int i  = tid >> 3;
    int pb = tid & 7;

    for (int l = tid; l < 1024; l += 256) As[l >> 5][l & 31] = logits[(size_t)bh * 1024 + l];
    __syncthreads();

    // in-block softmax with folded L2 norms + temperature (warp w owns rows 4w..4w+3)
    {
        int w = tid >> 5, lane = tid & 31;
        float tmp = temp[h];
        float kvn = fmaxf(sqrtf(kn2[b * 256 + h * 32 + lane]), 1e-12f);
#pragma unroll
        for (int rr = 0; rr < 4; rr++) {
            int r = w * 4 + rr;
            float qvn = fmaxf(sqrtf(qn2[b * 256 + h * 32 + r]), 1e-12f);
            float val = As[r][lane] * tmp / (qvn * kvn);
            float m = val;
#pragma unroll
            for (int o = 16; o; o >>= 1) m = fmaxf(m, __shfl_xor_sync(0xffffffffu, m, o));
            float e = expf(val - m);
            float s = e;
#pragma unroll
            for (int o = 16; o; o >>= 1) s += __shfl_xor_sync(0xffffffffu, s, o);
            As[r][lane] = e / s;
        }
    }

    int cw = h * 32 + i;
    float bw  = pbw[cw] * pbs[cw];
    float wv0 = pww[cw * 4 + 0] * pws[cw * 4 + 0];
    float wv1 = pww[cw * 4 + 1] * pws[cw * 4 + 1];
    float wv2 = pww[cw * 4 + 2] * pws[cw * 4 + 2];
    float wv3 = pww[cw * 4 + 3] * pws[cw * 4 + 3];

    const float* vb = v + (size_t)(b * 256 + h * 32) * NK;
    float* ob = out + (size_t)(b * 256 + h * 32 + i) * NK;

    int sj = tid >> 3, sr = (tid >> 2) & 1, sxq = tid & 3;

    for (int bx0 = 0; bx0 < 64; bx0 += 8) {
        __syncthreads();
        {
            float4 v4 = *(const float4*)(vb + (size_t)sj * NK + (2 * by + sr) * 128
                                         + 2 * bx0 + sxq * 4);
            vt[sj][sr][2 * sxq + 0] = make_float2(v4.x, v4.y);
            vt[sj][sr][2 * sxq + 1] = make_float2(v4.z, v4.w);
        }
        __syncthreads();

        float a00 = 0.f, a01 = 0.f, a10 = 0.f, a11 = 0.f;
#pragma unroll
        for (int j = 0; j < 32; j++) {
            float aA = As[i][j];
            float2 t0 = vt[j][0][pb];
            float2 t1 = vt[j][1][pb];
            a00 = fmaf(aA, t0.x, a00); a01 = fmaf(aA, t0.y, a01);
            a10 = fmaf(aA, t1.x, a10); a11 = fmaf(aA, t1.y, a11);
        }

        float r0 = 0.5f * (a00 + a01 + a10 + a11) * wv0;
        float r1 = 0.5f * (a00 + a01 - a10 - a11) * wv1;
        float r2 = 0.5f * (a00 - a01 + a10 - a11) * wv2;
        float r3 = 0.5f * (a00 - a01 - a10 + a11) * wv3;
        float y00 = 0.5f * (r0 + r1 + r2 + r3) + a00 * bw;
        float y01 = 0.5f * (r0 + r1 - r2 - r3) + a01 * bw;
        float y10 = 0.5f * (r0 - r1 + r2 - r3) + a10 * bw;
        float y11 = 0.5f * (r0 - r1 - r2 + r3) + a11 * bw;

        int gx = 2 * (bx0 + pb);
        *(float2*)&ob[(2 * by + 0) * 128 + gx] = make_float2(y00, y01);
        *(float2*)&ob[(2 * by + 1) * 128 + gx] = make_float2(y10, y11);
    }
}

// ---------------- launch (multi-stream fork/join DAG) ----------------
#define GEMM_SMEM (1024 + 2 * 65536)

extern "C" void kernel_launch(void* const* d_in, const int* in_sizes, int n_in,
                              void* d_out, int out_size)
{
    const float* x    = (const float*)d_in[0];
    const float* cf   = (const float*)d_in[1];
    const float* Wq   = (const float*)d_in[2];
    const float* Wk   = (const float*)d_in[3];
    const float* Wv   = (const float*)d_in[4];
    const float* temp = (const float*)d_in[5];
    const float* qbw = (const float*)d_in[6];  const float* qbs = (const float*)d_in[7];
    const float* qww = (const float*)d_in[8];  const float* qws = (const float*)d_in[9];
    const float* kbw = (const float*)d_in[10]; const float* kbs = (const float*)d_in[11];
    const float* kww = (const float*)d_in[12]; const float* kws = (const float*)d_in[13];
    const float* vbw = (const float*)d_in[14]; const float* vbs = (const float*)d_in[15];
    const float* vww = (const float*)d_in[16]; const float* vws = (const float*)d_in[17];
    const float* pbw = (const float*)d_in[18]; const float* pbs = (const float*)d_in[19];
    const float* pww = (const float*)d_in[20]; const float* pws = (const float*)d_in[21];
    float* out = (float*)d_out;

    float *q, *kv, *qwt, *vwt, *kdn, *qn2, *kn2, *lg;
    __nv_bfloat16 *xt_hi, *xt_lo, *ct_hi, *ct_lo, *aq_hi, *aq_lo, *akv_hi, *akv_lo;
    cudaGetSymbolAddress((void**)&q,     g_q);
    cudaGetSymbolAddress((void**)&kv,    g_kv);
    cudaGetSymbolAddress((void**)&qwt,   g_qwt);
    cudaGetSymbolAddress((void**)&vwt,   g_vwt);
    cudaGetSymbolAddress((void**)&kdn,   g_kdn);
    cudaGetSymbolAddress((void**)&qn2,   g_qn2);
    cudaGetSymbolAddress((void**)&kn2,   g_kn2);
    cudaGetSymbolAddress((void**)&lg,    g_lg);
    cudaGetSymbolAddress((void**)&xt_hi, g_xt_hi);
    cudaGetSymbolAddress((void**)&xt_lo, g_xt_lo);
    cudaGetSymbolAddress((void**)&ct_hi, g_ct_hi);
    cudaGetSymbolAddress((void**)&ct_lo, g_ct_lo);
    cudaGetSymbolAddress((void**)&aq_hi, g_aq_hi);
    cudaGetSymbolAddress((void**)&aq_lo, g_aq_lo);
    cudaGetSymbolAddress((void**)&akv_hi, g_akv_hi);
    cudaGetSymbolAddress((void**)&akv_lo, g_akv_lo);

    cudaFuncSetAttribute(gemm_tc, cudaFuncAttributeMaxDynamicSharedMemorySize, GEMM_SMEM);
    cudaFuncSetAttribute(wtconv_k_down, cudaFuncAttributeMaxDynamicSharedMemorySize, KD_SMEM);

    static cudaStream_t s1 = nullptr, s2 = nullptr;
    static cudaEvent_t ev0 = nullptr, evW = nullptr, evE = nullptr, evF = nullptr, evH = nullptr;
    if (s1 == nullptr) {
        cudaStreamCreateWithFlags(&s1, cudaStreamNonBlocking);
        cudaStreamCreateWithFlags(&s2, cudaStreamNonBlocking);
        cudaEventCreateWithFlags(&ev0, cudaEventDisableTiming);
        cudaEventCreateWithFlags(&evW, cudaEventDisableTiming);
        cudaEventCreateWithFlags(&evE, cudaEventDisableTiming);
        cudaEventCreateWithFlags(&evF, cudaEventDisableTiming);
        cudaEventCreateWithFlags(&evH, cudaEventDisableTiming);
    }
    cudaStream_t s0 = 0;

    // fork
    cudaEventRecord(ev0, s0);
    cudaStreamWaitEvent(s1, ev0, 0);
    cudaStreamWaitEvent(s2, ev0, 0);

    // s2: weights convert + zero accumulators (off critical path)
    convert_w<<<768, 256, 0, s2>>>(Wq, Wk, Wv, aq_hi, aq_lo, akv_hi, akv_lo, lg, kn2, qn2);
    cudaEventRecord(evW, s2);

    // s1: q-path prologue
    convert_x<<<dim3(NQ / 32, 4, BATCH), 256, 0, s1>>>(x, xt_hi, xt_lo, NQ);
    cudaStreamWaitEvent(s1, evW, 0);
    gemm_tc<<<dim3(NQ / 128, 2, BATCH), 256, GEMM_SMEM, s1>>>(aq_hi, aq_lo, xt_hi, xt_lo, q, NQ);
    wtconv_q_norm<<<dim3(BATCH * CHN, 2), 256, 0, s1>>>(q, qwt, qbw, qbs, qww, qws, qn2);
    cudaEventRecord(evF, s1);

    // main: cf convert -> kv GEMM
    convert_x<<<dim3(NK / 32, 4, BATCH), 256, 0, s0>>>(cf, ct_hi, ct_lo, NK);
    cudaStreamWaitEvent(s0, evW, 0);
    gemm_tc<<<dim3(NK / 128, 4, BATCH), 256, GEMM_SMEM, s0>>>(akv_hi, akv_lo, ct_hi, ct_lo, kv, NK);
    cudaEventRecord(evE, s0);

    // s2: v wtconv (needs kv)
    cudaStreamWaitEvent(s2, evE, 0);
    wtconv_t<128><<<dim3(BATCH * CHN, 4), 256, 0, s2>>>(kv + (size_t)CHN * NK, vwt,
                                                        vbw, vbs, vww, vws, HK, 512);
    cudaEventRecord(evH, s2);

    // main: k wtconv + downsample + norm
    wtconv_k_down<<<dim3(BATCH * CHN, 4), 256, KD_SMEM, s0>>>(kv, kdn, kbw, kbs, kww, kws, kn2);

    // join q-path, attention logits
    cudaStreamWaitEvent(s0, evF, 0);
    attn_partial<<<dim3(NQ / 512, BATCH * HEADS), 256, 0, s0>>>(qwt, kdn, lg, NQ);

    // join v-path, fused softmax + av + proj
    cudaStreamWaitEvent(s0, evH, 0);
    av_proj_kernel<<<dim3(64, BATCH * HEADS), 256, 0, s0>>>(lg, qn2, kn2, temp, vwt,
                                                            pbw, pbs, pww, pws, out);
}

// round 11
// speedup vs baseline: 1.1895x; 1.0309x over previous
#include <cuda_runtime.h>
#include <cuda_bf16.h>
#include <math.h>
#include <stdint.h>

// ---------------- arch feature gate (tcgen05 is an "a"-feature) ----------------
#if defined(__CUDA_ARCH_FEAT_SM103_ALL) || defined(__CUDA_ARCH_FEAT_SM100_ALL) || \
    defined(__CUDA_ARCH_FEAT_SM101_ALL) || \
    (defined(__CUDA_ARCH_SPECIFIC__) && (__CUDA_ARCH_SPECIFIC__ >= 1000))
#define HAS_TCGEN05 1
#else
#define HAS_TCGEN05 0
#endif

// ---------------- problem constants ----------------
#define BATCH 2
#define CHN   256
#define HQ    64
#define WQ    64
#define HK    128
#define WK    128
#define NQ    (HQ*WQ)     // 4096
#define NK    (HK*WK)     // 16384
#define HEADS 8
#define CPH   32

// ---------------- scratch (device globals) ----------------
static __device__ float g_q  [BATCH*CHN*NQ];
static __device__ float g_kv [BATCH*2*CHN*NK];
static __device__ float g_qwt[BATCH*CHN*NQ];
static __device__ float g_vwt[BATCH*CHN*NK];
static __device__ float g_kdn[BATCH*CHN*NQ];
static __device__ float g_qn2[BATCH*CHN];
static __device__ float g_kn2[BATCH*CHN];
static __device__ float g_lg [BATCH*HEADS*CPH*CPH];
static __device__ __nv_bfloat16 g_xt_hi[BATCH*NQ*CHN];
static __device__ __nv_bfloat16 g_xt_lo[BATCH*NQ*CHN];
static __device__ __nv_bfloat16 g_ct_hi[BATCH*NK*CHN];
static __device__ __nv_bfloat16 g_ct_lo[BATCH*NK*CHN];
static __device__ __nv_bfloat16 g_aq_hi[CHN*CHN];
static __device__ __nv_bfloat16 g_aq_lo[CHN*CHN];
static __device__ __nv_bfloat16 g_akv_hi[2*CHN*CHN];
static __device__ __nv_bfloat16 g_akv_lo[2*CHN*CHN];

// ---------------- PTX helpers ----------------
__device__ __forceinline__ uint32_t smem_to_u32(const void* p) {
    uint32_t a;
    asm("{ .reg .u64 t; cvta.to.shared.u64 t, %1; cvt.u32.u64 %0, t; }" : "=r"(a) : "l"(p));
    return a;
}
#define SW128(o) ((o) ^ (((o) >> 3) & 0x70))

#if HAS_TCGEN05
__device__ __forceinline__ uint32_t elect_one_pred() {
    uint32_t pred;
    asm volatile("{\n\t.reg .pred p;\n\telect.sync _|p, 0xFFFFFFFF;\n\tselp.b32 %0, 1, 0, p;\n\t}"
                 : "=r"(pred));
    return pred;
}

static constexpr uint64_t SMEM_DESC_BASE_SW128 =
    (uint64_t(2) << 61) | (uint64_t(1) << 46) | (uint64_t(64) << 32) | (uint64_t(1) << 16);
#define MAKE_SMEM_DESC(base_addr) \
    (SMEM_DESC_BASE_SW128 | ((uint64_t)((base_addr) >> 4) & 0x3FFF))

#define TCGEN05_ALLOC(smem_result_addr, nCols) \
    asm volatile("tcgen05.alloc.cta_group::1.sync.aligned.shared::cta.b32 [%0], %1;" \
        :: "r"((uint32_t)(smem_result_addr)), "r"((uint32_t)(nCols)) : "memory")
#define TCGEN05_DEALLOC(tmem_addr, nCols) \
    asm volatile("tcgen05.dealloc.cta_group::1.sync.aligned.b32 %0, %1;" \
        :: "r"(tmem_addr), "r"((uint32_t)(nCols)))
#define TCGEN05_RELINQUISH() \
    asm volatile("tcgen05.relinquish_alloc_permit.cta_group::1.sync.aligned;")
#define TCGEN05_COMMIT(mbar_smem_addr) \
    asm volatile("tcgen05.commit.cta_group::1.mbarrier::arrive::one.shared::cluster.b64 [%0];" \
        :: "r"((uint32_t)(mbar_smem_addr)) : "memory")
#define TCGEN05_FENCE_AFTER() \
    asm volatile("tcgen05.fence::after_thread_sync;" ::: "memory")
#define TCGEN05_WAIT_LD() \
    asm volatile("tcgen05.wait::ld.sync.aligned;" ::: "memory")
#define FENCE_PROXY_ASYNC_SHARED_CTA() \
    asm volatile("fence.proxy.async.shared::cta;" ::: "memory")
#define MBARRIER_INIT(mbar, count) \
    asm volatile("mbarrier.init.shared.b64 [%0], %1;" \
        :: "r"((uint32_t)(mbar)), "r"((uint32_t)(count)) : "memory")
#define MBARRIER_INVAL(mbar) \
    asm volatile("mbarrier.inval.shared.b64 [%0];" :: "r"((uint32_t)(mbar)) : "memory")
#define MBARRIER_WAIT_PARITY(mbar_smem_addr, phase_parity) do { \
    uint32_t _mbar = (uint32_t)(mbar_smem_addr); \
    uint32_t _parity = (uint32_t)(phase_parity); \
    uint32_t _done; \
    asm volatile("{\n\t.reg .pred p;\n\t" \
        "mbarrier.try_wait.parity.acquire.cta.shared::cta.b64 p, [%1], %2;\n\t" \
        "selp.b32 %0, 1, 0, p;\n\t}" \
        : "=r"(_done) : "r"(_mbar), "r"(_parity) : "memory"); \
    if (!_done) { \
        asm volatile("{\n\t.reg .pred P1;\n\t" \
            "WAIT_LOOP_%=:\n\t" \
            "mbarrier.try_wait.parity.acquire.cta.shared::cta.b64 P1, [%0], %1, 0x989680;\n\t" \
            "@P1 bra.uni WAIT_DONE_%=;\n\t" \
            "bra.uni WAIT_LOOP_%=;\n\t" \
            "WAIT_DONE_%=:\n\t}" \
            :: "r"(_mbar), "r"(_parity) : "memory"); \
    } \
} while(0)

#define TCGEN05_LD_32X32B_X32(r, tmem_addr) \
    asm volatile("tcgen05.ld.sync.aligned.32x32b.x32.b32 " \
        "{%0, %1, %2, %3, %4, %5, %6, %7, %8, %9, %10, %11, %12, %13, %14, %15, " \
        " %16, %17, %18, %19, %20, %21, %22, %23, %24, %25, %26, %27, %28, %29, %30, %31}, [%32];" \
        : "=r"((r)[0]),  "=r"((r)[1]),  "=r"((r)[2]),  "=r"((r)[3]), \
          "=r"((r)[4]),  "=r"((r)[5]),  "=r"((r)[6]),  "=r"((r)[7]), \
          "=r"((r)[8]),  "=r"((r)[9]),  "=r"((r)[10]), "=r"((r)[11]), \
          "=r"((r)[12]), "=r"((r)[13]), "=r"((r)[14]), "=r"((r)[15]), \
          "=r"((r)[16]), "=r"((r)[17]), "=r"((r)[18]), "=r"((r)[19]), \
          "=r"((r)[20]), "=r"((r)[21]), "=r"((r)[22]), "=r"((r)[23]), \
          "=r"((r)[24]), "=r"((r)[25]), "=r"((r)[26]), "=r"((r)[27]), \
          "=r"((r)[28]), "=r"((r)[29]), "=r"((r)[30]), "=r"((r)[31]) \
        : "r"(tmem_addr))

__device__ __forceinline__ void mma_f16_ss(uint32_t d_tmem, uint64_t a_desc, uint64_t b_desc,
                                           uint32_t idesc, uint32_t enable_d) {
    asm volatile(
        "{\n\t.reg .pred p;\n\t"
        "setp.ne.u32 p, %4, 0;\n\t"
        "tcgen05.mma.cta_group::1.kind::f16 [%0], %1, %2, %3, {%5, %5, %5, %5}, p;\n\t}"
        :: "r"(d_tmem), "l"(a_desc), "l"(b_desc), "r"(idesc), "r"(enable_d), "r"(0u)
        : "memory");
}

static constexpr uint32_t GEMM_IDESC =
    (1u << 4) | (1u << 7) | (1u << 10) | ((128u / 8u) << 17) | ((128u / 16u) << 24);
#endif  // HAS_TCGEN05

// ---------------- convert helpers ----------------
__device__ __forceinline__ void split_bf16(float x, __nv_bfloat16& h, __nv_bfloat16& l) {
    h = __float2bfloat16(x);
    l = __float2bfloat16(x - __bfloat162float(h));
}
__device__ __forceinline__ float bfu2f(uint32_t u16) {
    return __bfloat162float(__ushort_as_bfloat16((unsigned short)u16));
}

__global__ void convert_w(const float* __restrict__ Wq, const float* __restrict__ Wk,
                          const float* __restrict__ Wv,
                          __nv_bfloat16* __restrict__ aq_hi, __nv_bfloat16* __restrict__ aq_lo,
                          __nv_bfloat16* __restrict__ akv_hi, __nv_bfloat16* __restrict__ akv_lo,
                          float* __restrict__ lg, float* __restrict__ kn2,
                          float* __restrict__ qn2)
{
    if (blockIdx.x == 0) {
        for (int i = threadIdx.x; i < BATCH*HEADS*CPH*CPH; i += 256) lg[i] = 0.f;
        for (int i = threadIdx.x; i < BATCH*CHN; i += 256) { kn2[i] = 0.f; qn2[i] = 0.f; }
    }
    int i = blockIdx.x * 256 + threadIdx.x;
    __nv_bfloat16 h, l;
    if (i < 65536) {
        split_bf16(Wq[i], h, l); aq_hi[i] = h; aq_lo[i] = l;
    } else if (i < 131072) {
        int j = i - 65536;
        split_bf16(Wk[j], h, l); akv_hi[j] = h; akv_lo[j] = l;
    } else {
        int j = i - 131072;
        split_bf16(Wv[j], h, l); akv_hi[65536 + j] = h; akv_lo[65536 + j] = l;
    }
}

// ---------------- X convert: [B,C,N] f32 -> [B,N,C] bf16 hi/lo ----------------
__global__ __launch_bounds__(256) void convert_x(const float* __restrict__ X,
                                                 __nv_bfloat16* __restrict__ Th,
                                                 __nv_bfloat16* __restrict__ Tl, int N)
{
    __shared__ float s[64][33];
    int b = blockIdx.z, c0 = blockIdx.y * 64, n0 = blockIdx.x * 32;
    const float* Xb = X + (size_t)b * 256 * N;
    int lane = threadIdx.x & 31, w = threadIdx.x >> 5;
#pragma unroll
    for (int i = 0; i < 8; i++) {
        int c = w + i * 8;
        s[c][lane] = Xb[(size_t)(c0 + c) * N + n0 + lane];
    }
    __syncthreads();
    uint32_t* TH = (uint32_t*)(Th + (size_t)b * N * 256);
    uint32_t* TL = (uint32_t*)(Tl + (size_t)b * N * 256);
#pragma unroll
    for (int i = 0; i < 4; i++) {
        int n = w + i * 8;
        float x0 = s[2 * lane][n], x1 = s[2 * lane + 1][n];
        __nv_bfloat16 h0, l0, h1, l1;
        split_bf16(x0, h0, l0); split_bf16(x1, h1, l1);
        uint32_t hp = ((uint32_t)__bfloat16_as_ushort(h1) << 16) | __bfloat16_as_ushort(h0);
        uint32_t lp = ((uint32_t)__bfloat16_as_ushort(l1) << 16) | __bfloat16_as_ushort(l0);
        size_t idx = (size_t)(n0 + n) * 128 + (c0 >> 1) + lane;
        TH[idx] = hp; TL[idx] = lp;
    }
}

// ---------------- GEMM ----------------
#if HAS_TCGEN05
__device__ __forceinline__ void load_tile_sw(const __nv_bfloat16* __restrict__ src,
                                             char* __restrict__ dst, int tid)
{
#pragma unroll
    for (int it = 0; it < 4; it++) {
        int i = tid + it * 256;
        int row = i >> 3, seg = i & 7;
        uint4 v = *(const uint4*)(src + (size_t)row * 256 + seg * 8);
        uint32_t off = (uint32_t)(row * 128 + seg * 16);
        *(uint4*)(dst + SW128(off)) = v;
    }
}
#endif

__global__ __launch_bounds__(256, 1) void gemm_tc(
    const __nv_bfloat16* __restrict__ Ahi, const __nv_bfloat16* __restrict__ Alo,
    const __nv_bfloat16* __restrict__ Bhi, const __nv_bfloat16* __restrict__ Blo,
    float* __restrict__ Y, int Ntot)
{
    extern __shared__ char dsm[];
    int tid = threadIdx.x;
    int m0 = blockIdx.y * 128, n0 = blockIdx.x * 128, b = blockIdx.z;
    int Mtot = gridDim.y * 128;
    const __nv_bfloat16* Bh = Bhi + (size_t)b * Ntot * 256;
    const __nv_bfloat16* Bl = Blo + (size_t)b * Ntot * 256;
    float* Yb = Y + (size_t)b * Mtot * Ntot;

#if HAS_TCGEN05
    __shared__ uint32_t s_tmem[1];
    __shared__ unsigned long long s_mbar[2];
    uint32_t dsm_u = smem_to_u32(dsm);
    uint32_t sb = (dsm_u + 1023) & ~1023u;
    char* sbp = dsm + (sb - dsm_u);
    uint32_t mb[2] = { smem_to_u32(&s_mbar[0]), smem_to_u32(&s_mbar[1]) };
    int wid = tid >> 5;

    if (wid == 0) TCGEN05_ALLOC(smem_to_u32(s_tmem), 128);
    if (tid == 0) { MBARRIER_INIT(mb[0], 1); MBARRIER_INIT(mb[1], 1); }
    __syncthreads();
    uint32_t tbase = s_tmem[0];

    for (int ch = 0; ch < 4; ch++) {
        int buf = ch & 1;
        char* bp = sbp + buf * 65536;
        if (ch >= 2) MBARRIER_WAIT_PARITY(mb[buf], 0);
        int c0 = ch * 64;
        load_tile_sw(Ahi + (size_t)m0 * 256 + c0, bp,          tid);
        load_tile_sw(Alo + (size_t)m0 * 256 + c0, bp + 16384,  tid);
        load_tile_sw(Bh  + (size_t)n0 * 256 + c0, bp + 32768,  tid);
        load_tile_sw(Bl  + (size_t)n0 * 256 + c0, bp + 49152,  tid);
        FENCE_PROXY_ASYNC_SHARED_CTA();
        __syncthreads();
        if (wid == 0) {
            if (elect_one_pred()) {
                uint32_t base = sb + buf * 65536;
                uint64_t dah = MAKE_SMEM_DESC(base);
                uint64_t dal = MAKE_SMEM_DESC(base + 16384);
                uint64_t dbh = MAKE_SMEM_DESC(base + 32768);
                uint64_t dbl = MAKE_SMEM_DESC(base + 49152);
#pragma unroll
                for (int k = 0; k < 4; k++)
                    mma_f16_ss(tbase, dah + 2 * k, dbh + 2 * k, GEMM_IDESC,
                               (ch > 0 || k > 0) ? 1u : 0u);
#pragma unroll
                for (int k = 0; k < 4; k++)
                    mma_f16_ss(tbase, dah + 2 * k, dbl + 2 * k, GEMM_IDESC, 1u);
#pragma unroll
                for (int k = 0; k < 4; k++)
                    mma_f16_ss(tbase, dal + 2 * k, dbh + 2 * k, GEMM_IDESC, 1u);
                TCGEN05_COMMIT(mb[buf]);
            }
        }
    }

    MBARRIER_WAIT_PARITY(mb[0], 1);
    MBARRIER_WAIT_PARITY(mb[1], 1);
    TCGEN05_FENCE_AFTER();

    float* Ds = (float*)sbp;
    uint32_t woff = (uint32_t)(wid & 3) << 21;
    int cb0 = (wid >= 4) ? 2 : 0;
    int lane = tid & 31;
    int row = (wid & 3) * 32 + lane;
    uint32_t regs[32];
#pragma unroll
    for (int j = 0; j < 2; j++) {
        int cb = cb0 + j;
        TCGEN05_LD_32X32B_X32(regs, tbase + cb * 32 + woff);
        TCGEN05_WAIT_LD();
#pragma unroll
        for (int c = 0; c < 32; c++)
            Ds[row * 132 + cb * 32 + c] = __uint_as_float(regs[c]);
    }
    __syncthreads();
#pragma unroll
    for (int it = 0; it < 16; it++) {
        int i = tid + it * 256;
        int r = i >> 5, c4 = (i & 31) * 4;
        float4 v = *(float4*)&Ds[r * 132 + c4];
        *(float4*)&Yb[(size_t)(m0 + r) * Ntot + n0 + c4] = v;
    }
    __syncthreads();
    if (tid == 0) { MBARRIER_INVAL(mb[0]); MBARRIER_INVAL(mb[1]); }
    if (wid == 0) { TCGEN05_RELINQUISH(); TCGEN05_DEALLOC(tbase, 128); }

#else  // SIMT fallback
    float* As = (float*)dsm;
    float* Bs = As + 8 * 128;
    int ty = tid >> 4, tx = tid & 15;
    int r = tid >> 1, kq = (tid & 1) * 4;

    float acc[8][8];
#pragma unroll
    for (int i = 0; i < 8; i++)
#pragma unroll
        for (int j = 0; j < 8; j++) acc[i][j] = 0.f;

    for (int c0 = 0; c0 < 256; c0 += 8) {
        {
            size_t off = (size_t)(m0 + r) * 256 + c0 + kq;
            uint2 vh = *(const uint2*)(Ahi + off);
            uint2 vl = *(const uint2*)(Alo + off);
            As[(kq + 0) * 128 + r] = bfu2f(vh.x & 0xffff)  + bfu2f(vl.x & 0xffff);
            As[(kq + 1) * 128 + r] = bfu2f(vh.x >> 16)     + bfu2f(vl.x >> 16);
            As[(kq + 2) * 128 + r] = bfu2f(vh.y & 0xffff)  + bfu2f(vl.y & 0xffff);
            As[(kq + 3) * 128 + r] = bfu2f(vh.y >> 16)     + bfu2f(vl.y >> 16);
            size_t offb = (size_t)(n0 + r) * 256 + c0 + kq;
            uint2 wh = *(const uint2*)(Bh + offb);
            uint2 wl = *(const uint2*)(Bl + offb);
            Bs[(kq + 0) * 128 + r] = bfu2f(wh.x & 0xffff)  + bfu2f(wl.x & 0xffff);
            Bs[(kq + 1) * 128 + r] = bfu2f(wh.x >> 16)     + bfu2f(wl.x >> 16);
            Bs[(kq + 2) * 128 + r] = bfu2f(wh.y & 0xffff)  + bfu2f(wl.y & 0xffff);
            Bs[(kq + 3) * 128 + r] = bfu2f(wh.y >> 16)     + bfu2f(wl.y >> 16);
        }
        __syncthreads();
#pragma unroll
        for (int kk = 0; kk < 8; kk++) {
            float a[8], bb[8];
            *(float4*)&a[0]  = *(const float4*)&As[kk * 128 + ty * 8];
            *(float4*)&a[4]  = *(const float4*)&As[kk * 128 + ty * 8 + 4];
            *(float4*)&bb[0] = *(const float4*)&Bs[kk * 128 + tx * 8];
            *(float4*)&bb[4] = *(const float4*)&Bs[kk * 128 + tx * 8 + 4];
#pragma unroll
            for (int i = 0; i < 8; i++)
#pragma unroll
                for (int j = 0; j < 8; j++)
                    acc[i][j] = fmaf(a[i], bb[j], acc[i][j]);
        }
        __syncthreads();
    }
#pragma unroll
    for (int i = 0; i < 8; i++) {
        float* yp = Yb + (size_t)(m0 + ty * 8 + i) * Ntot + n0 + tx * 8;
        *(float4*)yp       = make_float4(acc[i][0], acc[i][1], acc[i][2], acc[i][3]);
        *(float4*)(yp + 4) = make_float4(acc[i][4], acc[i][5], acc[i][6], acc[i][7]);
    }
#endif
}

// ---------------- plain templated WTConv (Haar, ks=3), 32-row tiles — used for v ----------------
template<int W>
__global__ __launch_bounds__(256) void wtconv_t(
    const float* __restrict__ X, float* __restrict__ Y,
    const float* __restrict__ base_w, const float* __restrict__ base_s,
    const float* __restrict__ wav_w,  const float* __restrict__ wav_s,
    int H, int cs_in)
{
    constexpr int LW = W + 4;
    constexpr int SWc = (W >> 1) + 2;
    constexpr int Wh = W >> 1;
    __shared__ float ins[36][LW];
    __shared__ float sub[4][18][SWc];
    __shared__ float swav[4][9];
    __shared__ float sbw[9];
    __shared__ float swsc[4];
    __shared__ float sbs;

    int bc = blockIdx.x;
    int b  = bc >> 8;
    int c  = bc & 255;
    int y0 = blockIdx.y * 32;
    const float* Xc = X + ((size_t)b * cs_in + c) * H * W;
    float*       Yc = Y + (size_t)bc * H * W;
    int tid = threadIdx.x;

    if (tid < 36) {
        int f = tid / 9, i = tid - f * 9;
        swav[f][i] = wav_w[(size_t)(c * 4 + f) * 9 + i];
    } else if (tid < 45) {
        sbw[tid - 36] = base_w[(size_t)c * 9 + tid - 36];
    } else if (tid < 49) {
        swsc[tid - 45] = wav_s[c * 4 + tid - 45];
    } else if (tid == 49) {
        sbs = base_s[c];
    }

    for (int idx = tid; idx < 36 * LW; idx += 256) {
        int ly = idx / LW, lx = idx - ly * LW;
        int gy = y0 + ly - 2, gx = lx - 2;
        float v = 0.f;
        if (gy >= 0 && gy < H && gx >= 0 && gx < W) v = Xc[gy * W + gx];
        ins[ly][lx] = v;
    }
    __syncthreads();

    for (int idx = tid; idx < 18 * SWc; idx += 256) {
        int sy = idx / SWc, sx = idx - sy * SWc;
        float a = ins[2 * sy][2 * sx],     bq = ins[2 * sy][2 * sx + 1];
        float d = ins[2 * sy + 1][2 * sx], e = ins[2 * sy + 1][2 * sx + 1];
        sub[0][sy][sx] = 0.5f * (a + bq + d + e);
        sub[1][sy][sx] = 0.5f * (a + bq - d - e);
        sub[2][sy][sx] = 0.5f * (a - bq + d - e);
        sub[3][sy][sx] = 0.5f * (a - bq - d + e);
    }
    __syncthreads();

    for (int idx = tid; idx < 16 * Wh; idx += 256) {
        int syi = idx / Wh, sxi = idx - syi * Wh;
        int sy = syi + 1, sx = sxi + 1;
        float r[4];
#pragma unroll
        for (int f = 0; f < 4; f++) {
            float s = 0.f;
#pragma unroll
            for (int dy = 0; dy < 3; dy++)
#pragma unroll
                for (int dx = 0; dx < 3; dx++)
                    s = fmaf(swav[f][dy * 3 + dx], sub[f][sy - 1 + dy][sx - 1 + dx], s);
            r[f] = s * swsc[f];
        }
        float y00 = 0.5f * (r[0] + r[1] + r[2] + r[3]);
        float y01 = 0.5f * (r[0] + r[1] - r[2] - r[3]);
        float y10 = 0.5f * (r[0] - r[1] + r[2] - r[3]);
        float y11 = 0.5f * (r[0] - r[1] - r[2] + r[3]);

        float base[2][2];
#pragma unroll
        for (int p = 0; p < 2; p++)
#pragma unroll
            for (int q = 0; q < 2; q++) {
                float s = 0.f;
#pragma unroll
                for (int dy = 0; dy < 3; dy++)
#pragma unroll
                    for (int dx = 0; dx < 3; dx++)
                        s = fmaf(sbw[dy * 3 + dx],
                                 ins[2 * sy + p - 1 + dy][2 * sx + q - 1 + dx], s);
                base[p][q] = s * sbs;
            }
        int gy = y0 + 2 * syi, gx = 2 * sxi;
        Yc[(gy + 0) * W + gx + 0] = base[0][0] + y00;
        Yc[(gy + 0) * W + gx + 1] = base[0][1] + y01;
        Yc[(gy + 1) * W + gx + 0] = base[1][0] + y10;
        Yc[(gy + 1) * W + gx + 1] = base[1][1] + y11;
    }
}

// ---------------- fused wtconv(k) + transposed-bilinear downsample + ||k||², 32-row tiles ----------------
#define KD_SMEM ((40*132 + 4*20*66 + 36*130) * 4)

__global__ __launch_bounds__(256) void wtconv_k_down(
    const float* __restrict__ X, float* __restrict__ kdn,
    const float* __restrict__ base_w, const float* __restrict__ base_s,
    const float* __restrict__ wav_w,  const float* __restrict__ wav_s,
    float* __restrict__ kn2)
{
    extern __shared__ float sm[];
    float* ins  = sm;                    // [40][132]
    float* sub  = ins + 40 * 132;        // [4][20][66]
    float* outb = sub + 4 * 20 * 66;     // [36][130]
    __shared__ float swav[4][9];
    __shared__ float sbw[9];
    __shared__ float swsc[4];
    __shared__ float sbs;
    __shared__ float red[256];

    int bc = blockIdx.x;
    int b  = bc >> 8;
    int c  = bc & 255;
    int by = blockIdx.y;
    int y0 = by * 32;
    const float* Xc = X + ((size_t)b * 512 + c) * (size_t)NK;
    int tid = threadIdx.x;

    if (tid < 36) {
        int f = tid / 9, i = tid - f * 9;
        swav[f][i] = wav_w[(size_t)(c * 4 + f) * 9 + i];
    } else if (tid < 45) {
        sbw[tid - 36] = base_w[(size_t)c * 9 + tid - 36];
    } else if (tid < 49) {
        swsc[tid - 45] = wav_s[c * 4 + tid - 45];
    } else if (tid == 49) {
        sbs = base_s[c];
    }

    for (int idx = tid; idx < 40 * 132; idx += 256) {
        int ly = idx / 132, lx = idx - ly * 132;
        int gy = y0 + ly - 4, gx = lx - 2;
        float v = 0.f;
        if (gy >= 0 && gy < 128 && gx >= 0 && gx < 128) v = Xc[gy * 128 + gx];
        ins[idx] = v;
    }
    __syncthreads();

    for (int idx = tid; idx < 20 * 66; idx += 256) {
        int sy = idx / 66, sx = idx - sy * 66;
        const float* r0 = ins + (2 * sy) * 132 + 2 * sx;
        float a = r0[0], bq = r0[1], d = r0[132], e = r0[133];
        sub[0 * 1320 + idx] = 0.5f * (a + bq + d + e);
        sub[1 * 1320 + idx] = 0.5f * (a + bq - d - e);
        sub[2 * 1320 + idx] = 0.5f * (a - bq + d - e);
        sub[3 * 1320 + idx] = 0.5f * (a - bq - d + e);
    }
    __syncthreads();

    for (int idx = tid; idx < 18 * 64; idx += 256) {
        int syo = idx >> 6, j = idx & 63;
        int sy = syo + 1, sx = j + 1;
        float r[4];
#pragma unroll
        for (int f = 0; f < 4; f++) {
            const float* sf = sub + f * 1320;
            float s = 0.f;
#pragma unroll
            for (int dy = 0; dy < 3; dy++)
#pragma unroll
                for (int dx = 0; dx < 3; dx++)
                    s = fmaf(swav[f][dy * 3 + dx], sf[(sy - 1 + dy) * 66 + sx - 1 + dx], s);
            r[f] = s * swsc[f];
        }
        float y00 = 0.5f * (r[0] + r[1] + r[2] + r[3]);
        float y01 = 0.5f * (r[0] + r[1] - r[2] - r[3]);
        float y10 = 0.5f * (r[0] - r[1] + r[2] - r[3]);
        float y11 = 0.5f * (r[0] - r[1] - r[2] + r[3]);

        float base[2][2];
#pragma unroll
        for (int p = 0; p < 2; p++)
#pragma unroll
            for (int q = 0; q < 2; q++) {
                float s = 0.f;
#pragma unroll
                for (int dy = 0; dy < 3; dy++)
#pragma unroll
                    for (int dx = 0; dx < 3; dx++)
                        s = fmaf(sbw[dy * 3 + dx],
                                 ins[(2 * syo + 1 + p + dy) * 132 + 2 * j + 1 + q + dx], s);
                base[p][q] = s * sbs;
            }
        outb[(2 * syo) * 130 + 2 * j]         = base[0][0] + y00;
        outb[(2 * syo) * 130 + 2 * j + 1]     = base[0][1] + y01;
        outb[(2 * syo + 1) * 130 + 2 * j]     = base[1][0] + y10;
        outb[(2 * syo + 1) * 130 + 2 * j + 1] = base[1][1] + y11;
    }
    __syncthreads();

    float sumsq = 0.f;
    for (int idx = tid; idx < 32 * 128; idx += 256) {
        int lr = (idx >> 7) + 2, lc = idx & 127;
        float v = outb[lr * 130 + lc];
        sumsq += v * v;
    }

    for (int idx = tid; idx < 16 * 64; idx += 256) {
        int jj = idx >> 6, jx = idx & 63;
        int jy = 16 * by + jj;
        int lyt[4]; float wyt[4]; int cy = 0;
        if (jy > 0)  { lyt[cy] = 2*jj+1; wyt[cy++] = 0.25f; }
        lyt[cy] = 2*jj+2; wyt[cy++] = (jy == 0)  ? 1.0f : 0.75f;
        lyt[cy] = 2*jj+3; wyt[cy++] = (jy == 63) ? 1.0f : 0.75f;
        if (jy < 63) { lyt[cy] = 2*jj+4; wyt[cy++] = 0.25f; }
        int lxt[4]; float wxt[4]; int cx = 0;
        if (jx > 0)  { lxt[cx] = 2*jx-1; wxt[cx++] = 0.25f; }
        lxt[cx] = 2*jx;   wxt[cx++] = (jx == 0)  ? 1.0f : 0.75f;
        lxt[cx] = 2*jx+1; wxt[cx++] = (jx == 63) ? 1.0f : 0.75f;
        if (jx < 63) { lxt[cx] = 2*jx+2; wxt[cx++] = 0.25f; }
        float s = 0.f;
        for (int a = 0; a < cy; a++) {
            const float* row = outb + lyt[a] * 130;
            float rs = 0.f;
            for (int e = 0; e < cx; e++) rs = fmaf(wxt[e], row[lxt[e]], rs);
            s = fmaf(wyt[a], rs, s);
        }
        kdn[(size_t)bc * NQ + jy * 64 + jx] = s;
    }

    red[tid] = sumsq; __syncthreads();
    for (int o = 128; o > 0; o >>= 1) {
        if (tid < o) red[tid] += red[tid + o];
        __syncthreads();
    }
    if (tid == 0) atomicAdd(&kn2[bc], red[0]);
}

// ---------------- fused wtconv(q) + ||upsample(q)||² via Gram quadratic form ----------------
// ||U q||^2 = q^T (Gy ⊗ Gx) q, G tridiagonal: diag 1.25 (1.625 at edges), off-diag 0.375.
__global__ __launch_bounds__(256) void wtconv_q_norm(
    const float* __restrict__ X, float* __restrict__ Y,
    const float* __restrict__ base_w, const float* __restrict__ base_s,
    const float* __restrict__ wav_w,  const float* __restrict__ wav_s,
    float* __restrict__ qn2)
{
    __shared__ float ins[40][68];
    __shared__ float sub[4][20][36];
    __shared__ float outb[36][66];
    __shared__ float swav[4][9];
    __shared__ float sbw[9];
    __shared__ float swsc[4];
    __shared__ float sbs;
    __shared__ float red[256];

    int bc = blockIdx.x;
    int c  = bc & 255;
    int by = blockIdx.y;
    int y0 = by * 32;
    const float* Xc = X + (size_t)bc * NQ;
    float*       Yc = Y + (size_t)bc * NQ;
    int tid = threadIdx.x;

    if (tid < 36) {
        int f = tid / 9, i = tid - f * 9;
        swav[f][i] = wav_w[(size_t)(c * 4 + f) * 9 + i];
    } else if (tid < 45) {
        sbw[tid - 36] = base_w[(size_t)c * 9 + tid - 36];
    } else if (tid < 49) {
        swsc[tid - 45] = wav_s[c * 4 + tid - 45];
    } else if (tid == 49) {
        sbs = base_s[c];
    }

    for (int idx = tid; idx < 40 * 68; idx += 256) {
        int ly = idx / 68, lx = idx - ly * 68;
        int gy = y0 + ly - 4, gx = lx - 2;
        float v = 0.f;
        if (gy >= 0 && gy < 64 && gx >= 0 && gx < 64) v = Xc[gy * 64 + gx];
        ins[ly][lx] = v;
    }
    __syncthreads();

    for (int idx = tid; idx < 20 * 34; idx += 256) {
        int sy = idx / 34, sx = idx - sy * 34;
        float a = ins[2 * sy][2 * sx],     bq = ins[2 * sy][2 * sx + 1];
        float d = ins[2 * sy + 1][2 * sx], e = ins[2 * sy + 1][2 * sx + 1];
        sub[0][sy][sx] = 0.5f * (a + bq + d + e);
        sub[1][sy][sx] = 0.5f * (a + bq - d - e);
        sub[2][sy][sx] = 0.5f * (a - bq + d - e);
        sub[3][sy][sx] = 0.5f * (a - bq - d + e);
    }
    __syncthreads();

    for (int idx = tid; idx < 18 * 32; idx += 256) {
        int syo = idx >> 5, j = idx & 31;
        int sy = syo + 1, sx = j + 1;
        float r[4];
#pragma unroll
        for (int f = 0; f < 4; f++) {
            float s = 0.f;
#pragma unroll
            for (int dy = 0; dy < 3; dy++)
#pragma unroll
                for (int dx = 0; dx < 3; dx++)
                    s = fmaf(swav[f][dy * 3 + dx], sub[f][sy - 1 + dy][sx - 1 + dx], s);
            r[f] = s * swsc[f];
        }
        float y00 = 0.5f * (r[0] + r[1] + r[2] + r[3]);
        float y01 = 0.5f * (r[0] + r[1] - r[2] - r[3]);
        float y10 = 0.5f * (r[0] - r[1] + r[2] - r[3]);
        float y11 = 0.5f * (r[0] - r[1] - r[2] + r[3]);

        float base[2][2];
#pragma unroll
        for (int p = 0; p < 2; p++)
#pragma unroll
            for (int q = 0; q < 2; q++) {
                float s = 0.f;
#pragma unroll
                for (int dy = 0; dy < 3; dy++)
#pragma unroll
                    for (int dx = 0; dx < 3; dx++)
                        s = fmaf(sbw[dy * 3 + dx],
                                 ins[2 * syo + 1 + p + dy][2 * j + 1 + q + dx], s);
                base[p][q] = s * sbs;
            }
        float o00 = base[0][0] + y00, o01 = base[0][1] + y01;
        float o10 = base[1][0] + y10, o11 = base[1][1] + y11;
        outb[2 * syo][2 * j]         = o00;
        outb[2 * syo][2 * j + 1]     = o01;
        outb[2 * syo + 1][2 * j]     = o10;
        outb[2 * syo + 1][2 * j + 1] = o11;
        if (syo >= 1 && syo <= 16) {
            int gy = y0 - 2 + 2 * syo;
            Yc[(gy + 0) * 64 + 2 * j]     = o00;
            Yc[(gy + 0) * 64 + 2 * j + 1] = o01;
            Yc[(gy + 1) * 64 + 2 * j]     = o10;
            Yc[(gy + 1) * 64 + 2 * j + 1] = o11;
        }
    }
    __syncthreads();

    // Gram quadratic form over owned rows (global y0..y0+31, local 2..33)
    float sum = 0.f;
    for (int idx = tid; idx < 32 * 64; idx += 256) {
        int yl = idx >> 6, x = idx & 63;
        int yg = y0 + yl;
        int ly = yl + 2;
        float dyc = (yg == 0 || yg == 63) ? 1.625f : 1.25f;
        float dxc = (x == 0 || x == 63) ? 1.625f : 1.25f;
        float ql = (x > 0)  ? 0.375f : 0.f;
        float qr = (x < 63) ? 0.375f : 0.f;

        const float* rm = &outb[ly - 1][x];
        const float* rc = &outb[ly][x];
        const float* rp = &outb[ly + 1][x];
        float um = ql * rm[-1] + dxc * rm[0] + qr * rm[1];
        float uc = ql * rc[-1] + dxc * rc[0] + qr * rc[1];
        float up = ql * rp[-1] + dxc * rp[0] + qr * rp[1];

        float gm = (yg > 0)  ? 0.375f : 0.f;
        float gp = (yg < 63) ? 0.375f : 0.f;
        sum += rc[0] * (gm * um + dyc * uc + gp * up);
    }
    red[tid] = sum; __syncthreads();
    for (int o = 128; o > 0; o >>= 1) {
        if (tid < o) red[tid] += red[tid + o];
        __syncthreads();
    }
    if (tid == 0) atomicAdd(&qn2[bc], red[0]);
}

// ---------------- attention logits ----------------
__global__ __launch_bounds__(256) void attn_partial(
    const float* __restrict__ qp, const float* __restrict__ kp,
    float* __restrict__ logits, int N)
{
    __shared__ float qsT[64][33];
    __shared__ float ksT[64][33];
    int bh = blockIdx.y;
    int n0 = blockIdx.x * 512;
    const float* q = qp + (size_t)bh * 32 * N + n0;
    const float* k = kp + (size_t)bh * 32 * N + n0;
    int tid = threadIdx.x;
    int i0 = (tid & 7) * 4, j0 = ((tid >> 3) & 7) * 4, ns = tid >> 6;

    float acc[4][4];
#pragma unroll
    for (int i = 0; i < 4; i++)
#pragma unroll
        for (int j = 0; j < 4; j++) acc[i][j] = 0.f;

    for (int nc = 0; nc < 512; nc += 64) {
        for (int l = tid; l < 512; l += 256) {
            int row = l >> 4, col4 = (l & 15) * 4;
            float4 a = *(const float4*)(q + (size_t)row * N + nc + col4);
            float4 b = *(const float4*)(k + (size_t)row * N + nc + col4);
            qsT[col4 + 0][row] = a.x; qsT[col4 + 1][row] = a.y;
            qsT[col4 + 2][row] = a.z; qsT[col4 + 3][row] = a.w;
            ksT[col4 + 0][row] = b.x; ksT[col4 + 1][row] = b.y;
            ksT[col4 + 2][row] = b.z; ksT[col4 + 3][row] = b.w;
        }
        __syncthreads();
        for (int nn = ns; nn < 64; nn += 4) {
            float qv[4], kv[4];
#pragma unroll
            for (int m = 0; m < 4; m++) { qv[m] = qsT[nn][i0 + m]; kv[m] = ksT[nn][j0 + m]; }
#pragma unroll
            for (int i = 0; i < 4; i++)
#pragma unroll
                for (int j = 0; j < 4; j++)
                    acc[i][j] = fmaf(qv[i], kv[j], acc[i][j]);
        }
        __syncthreads();
    }
    float* L = logits + (size_t)bh * 1024;
#pragma unroll
    for (int i = 0; i < 4; i++)
#pragma unroll
        for (int j = 0; j < 4; j++)
            atomicAdd(&L[(i0 + i) * 32 + j0 + j], acc[i][j]);
}

// ---------------- fused softmax + (attn @ v) + proj WTConv(ks=1) -> d_out ----------------
__global__ __launch_bounds__(256) void av_proj_kernel(
    const float* __restrict__ logits, const float* __restrict__ qn2,
    const float* __restrict__ kn2, const float* __restrict__ temp,
    const float* __restrict__ v,
    const float* __restrict__ pbw, const float* __restrict__ pbs,
    const float* __restrict__ pww, const float* __restrict__ pws,
    float* __restrict__ out)
{
    __shared__ float As[32][33];
    __shared__ float2 vt[32][2][8];

    int by = blockIdx.x;
    int bh = blockIdx.y;
    int b  = bh >> 3, h = bh & 7;
    int tid = threadIdx.x;
    int i  = tid >> 3;
    int pb = tid & 7;

    for (int l = tid; l < 1024; l += 256) As[l >> 5][l & 31] = logits[(size_t)bh * 1024 + l];
    __syncthreads();

    // in-block softmax with folded L2 norms + temperature (warp w owns rows 4w..4w+3)
    {
        int w = tid >> 5, lane = tid & 31;
        float tmp = temp[h];
        float kvn = fmaxf(sqrtf(kn2[b * 256 + h * 32 + lane]), 1e-12f);
#pragma unroll
        for (int rr = 0; rr < 4; rr++) {
            int r = w * 4 + rr;
            float qvn = fmaxf(sqrtf(qn2[b * 256 + h * 32 + r]), 1e-12f);
            float val = As[r][lane] * tmp / (qvn * kvn);
            float m = val;
#pragma unroll
            for (int o = 16; o; o >>= 1) m = fmaxf(m, __shfl_xor_sync(0xffffffffu, m, o));
            float e = expf(val - m);
            float s = e;
#pragma unroll
            for (int o = 16; o; o >>= 1) s += __shfl_xor_sync(0xffffffffu, s, o);
            As[r][lane] = e / s;
        }
    }
    __syncthreads();

    // cache this thread's attention row in registers
    float arow[32];
#pragma unroll
    for (int j = 0; j < 32; j++) arow[j] = As[i][j];

    int cw = h * 32 + i;
    float bw  = pbw[cw] * pbs[cw];
    float wv0 = pww[cw * 4 + 0] * pws[cw * 4 + 0];
    float wv1 = pww[cw * 4 + 1] * pws[cw * 4 + 1];
    float wv2 = pww[cw * 4 + 2] * pws[cw * 4 + 2];
    float wv3 = pww[cw * 4 + 3] * pws[cw * 4 + 3];

    const float* vb = v + (size_t)(b * 256 + h * 32) * NK;
    float* ob = out + (size_t)(b * 256 + h * 32 + i) * NK;

    int sj = tid >> 3, sr = (tid >> 2) & 1, sxq = tid & 3;

    for (int bx0 = 0; bx0 < 64; bx0 += 8) {
        __syncthreads();
        {
            float4 v4 = *(const float4*)(vb + (size_t)sj * NK + (2 * by + sr) * 128
                                         + 2 * bx0 + sxq * 4);
            vt[sj][sr][2 * sxq + 0] = make_float2(v4.x, v4.y);
            vt[sj][sr][2 * sxq + 1] = make_float2(v4.z, v4.w);
        }
        __syncthreads();

        float a00 = 0.f, a01 = 0.f, a10 = 0.f, a11 = 0.f;
#pragma unroll
        for (int j = 0; j < 32; j++) {
            float aA = arow[j];
            float2 t0 = vt[j][0][pb];
            float2 t1 = vt[j][1][pb];
            a00 = fmaf(aA, t0.x, a00); a01 = fmaf(aA, t0.y, a01);
            a10 = fmaf(aA, t1.x, a10); a11 = fmaf(aA, t1.y, a11);
        }

        float r0 = 0.5f * (a00 + a01 + a10 + a11) * wv0;
        float r1 = 0.5f * (a00 + a01 - a10 - a11) * wv1;
        float r2 = 0.5f * (a00 - a01 + a10 - a11) * wv2;
        float r3 = 0.5f * (a00 - a01 - a10 + a11) * wv3;
        float y00 = 0.5f * (r0 + r1 + r2 + r3) + a00 * bw;
        float y01 = 0.5f * (r0 + r1 - r2 - r3) + a01 * bw;
        float y10 = 0.5f * (r0 - r1 + r2 - r3) + a10 * bw;
        float y11 = 0.5f * (r0 - r1 - r2 + r3) + a11 * bw;

        int gx = 2 * (bx0 + pb);
        *(float2*)&ob[(2 * by + 0) * 128 + gx] = make_float2(y00, y01);
        *(float2*)&ob[(2 * by + 1) * 128 + gx] = make_float2(y10, y11);
    }
}

// ---------------- launch (multi-stream fork/join DAG) ----------------
#define GEMM_SMEM (1024 + 2 * 65536)

extern "C" void kernel_launch(void* const* d_in, const int* in_sizes, int n_in,
                              void* d_out, int out_size)
{
    const float* x    = (const float*)d_in[0];
    const float* cf   = (const float*)d_in[1];
    const float* Wq   = (const float*)d_in[2];
    const float* Wk   = (const float*)d_in[3];
    const float* Wv   = (const float*)d_in[4];
    const float* temp = (const float*)d_in[5];
    const float* qbw = (const float*)d_in[6];  const float* qbs = (const float*)d_in[7];
    const float* qww = (const float*)d_in[8];  const float* qws = (const float*)d_in[9];
    const float* kbw = (const float*)d_in[10]; const float* kbs = (const float*)d_in[11];
    const float* kww = (const float*)d_in[12]; const float* kws = (const float*)d_in[13];
    const float* vbw = (const float*)d_in[14]; const float* vbs = (const float*)d_in[15];
    const float* vww = (const float*)d_in[16]; const float* vws = (const float*)d_in[17];
    const float* pbw = (const float*)d_in[18]; const float* pbs = (const float*)d_in[19];
    const float* pww = (const float*)d_in[20]; const float* pws = (const float*)d_in[21];
    float* out = (float*)d_out;

    float *q, *kv, *qwt, *vwt, *kdn, *qn2, *kn2, *lg;
    __nv_bfloat16 *xt_hi, *xt_lo, *ct_hi, *ct_lo, *aq_hi, *aq_lo, *akv_hi, *akv_lo;
    cudaGetSymbolAddress((void**)&q,     g_q);
    cudaGetSymbolAddress((void**)&kv,    g_kv);
    cudaGetSymbolAddress((void**)&qwt,   g_qwt);
    cudaGetSymbolAddress((void**)&vwt,   g_vwt);
    cudaGetSymbolAddress((void**)&kdn,   g_kdn);
    cudaGetSymbolAddress((void**)&qn2,   g_qn2);
    cudaGetSymbolAddress((void**)&kn2,   g_kn2);
    cudaGetSymbolAddress((void**)&lg,    g_lg);
    cudaGetSymbolAddress((void**)&xt_hi, g_xt_hi);
    cudaGetSymbolAddress((void**)&xt_lo, g_xt_lo);
    cudaGetSymbolAddress((void**)&ct_hi, g_ct_hi);
    cudaGetSymbolAddress((void**)&ct_lo, g_ct_lo);
    cudaGetSymbolAddress((void**)&aq_hi, g_aq_hi);
    cudaGetSymbolAddress((void**)&aq_lo, g_aq_lo);
    cudaGetSymbolAddress((void**)&akv_hi, g_akv_hi);
    cudaGetSymbolAddress((void**)&akv_lo, g_akv_lo);

    cudaFuncSetAttribute(gemm_tc, cudaFuncAttributeMaxDynamicSharedMemorySize, GEMM_SMEM);
    cudaFuncSetAttribute(wtconv_k_down, cudaFuncAttributeMaxDynamicSharedMemorySize, KD_SMEM);

    static cudaStream_t s1 = nullptr, s2 = nullptr;
    static cudaEvent_t ev0 = nullptr, evW = nullptr, evE = nullptr, evF = nullptr, evH = nullptr;
    if (s1 == nullptr) {
        cudaStreamCreateWithFlags(&s1, cudaStreamNonBlocking);
        cudaStreamCreateWithFlags(&s2, cudaStreamNonBlocking);
        cudaEventCreateWithFlags(&ev0, cudaEventDisableTiming);
        cudaEventCreateWithFlags(&evW, cudaEventDisableTiming);
        cudaEventCreateWithFlags(&evE, cudaEventDisableTiming);
        cudaEventCreateWithFlags(&evF, cudaEventDisableTiming);
        cudaEventCreateWithFlags(&evH, cudaEventDisableTiming);
    }
    cudaStream_t s0 = 0;

    // fork
    cudaEventRecord(ev0, s0);
    cudaStreamWaitEvent(s1, ev0, 0);
    cudaStreamWaitEvent(s2, ev0, 0);

    // s2: weights convert + zero accumulators (off critical path)
    convert_w<<<768, 256, 0, s2>>>(Wq, Wk, Wv, aq_hi, aq_lo, akv_hi, akv_lo, lg, kn2, qn2);
    cudaEventRecord(evW, s2);

    // s1: q-path prologue
    convert_x<<<dim3(NQ / 32, 4, BATCH), 256, 0, s1>>>(x, xt_hi, xt_lo, NQ);
    cudaStreamWaitEvent(s1, evW, 0);
    gemm_tc<<<dim3(NQ / 128, 2, BATCH), 256, GEMM_SMEM, s1>>>(aq_hi, aq_lo, xt_hi, xt_lo, q, NQ);
    wtconv_q_norm<<<dim3(BATCH * CHN, 2), 256, 0, s1>>>(q, qwt, qbw, qbs, qww, qws, qn2);
    cudaEventRecord(evF, s1);

    // main: cf convert -> kv GEMM
    convert_x<<<dim3(NK / 32, 4, BATCH), 256, 0, s0>>>(cf, ct_hi, ct_lo, NK);
    cudaStreamWaitEvent(s0, evW, 0);
    gemm_tc<<<dim3(NK / 128, 4, BATCH), 256, GEMM_SMEM, s0>>>(akv_hi, akv_lo, ct_hi, ct_lo, kv, NK);
    cudaEventRecord(evE, s0);

    // s2: v wtconv (needs kv)
    cudaStreamWaitEvent(s2, evE, 0);
    wtconv_t<128><<<dim3(BATCH * CHN, 4), 256, 0, s2>>>(kv + (size_t)CHN * NK, vwt,
                                                        vbw, vbs, vww, vws, HK, 512);
    cudaEventRecord(evH, s2);

    // main: k wtconv + downsample + norm
    wtconv_k_down<<<dim3(BATCH * CHN, 4), 256, KD_SMEM, s0>>>(kv, kdn, kbw, kbs, kww, kws, kn2);

    // join q-path, attention logits
    cudaStreamWaitEvent(s0, evF, 0);
    attn_partial<<<dim3(NQ / 512, BATCH * HEADS), 256, 0, s0>>>(qwt, kdn, lg, NQ);

    // join v-path, fused softmax + av + proj
    cudaStreamWaitEvent(s0, evH, 0);
    av_proj_kernel<<<dim3(64, BATCH * HEADS), 256, 0, s0>>>(lg, qn2, kn2, temp, vwt,
                                                            pbw, pbs, pww, pws, out);
}

// round 12
// speedup vs baseline: 1.2358x; 1.0389x over previous
#include <cuda_runtime.h>
#include <cuda_bf16.h>
#include <math.h>
#include <stdint.h>

// ---------------- arch feature gate (tcgen05 is an "a"-feature) ----------------
#if defined(__CUDA_ARCH_FEAT_SM103_ALL) || defined(__CUDA_ARCH_FEAT_SM100_ALL) || \
    defined(__CUDA_ARCH_FEAT_SM101_ALL) || \
    (defined(__CUDA_ARCH_SPECIFIC__) && (__CUDA_ARCH_SPECIFIC__ >= 1000))
#define HAS_TCGEN05 1
#else
#define HAS_TCGEN05 0
#endif

// ---------------- problem constants ----------------
#define BATCH 2
#define CHN   256
#define HQ    64
#define WQ    64
#define HK    128
#define WK    128
#define NQ    (HQ*WQ)     // 4096
#define NK    (HK*WK)     // 16384
#define HEADS 8
#define CPH   32

// ---------------- scratch (device globals) ----------------
static __device__ float g_q  [BATCH*CHN*NQ];
static __device__ float g_kv [BATCH*2*CHN*NK];
static __device__ float g_qwt[BATCH*CHN*NQ];
static __device__ float g_vwt[BATCH*CHN*NK];
static __device__ float g_kdn[BATCH*CHN*NQ];
static __device__ float g_qn2[BATCH*CHN];
static __device__ float g_kn2[BATCH*CHN];
static __device__ float g_lg [BATCH*HEADS*CPH*CPH];
static __device__ __nv_bfloat16 g_xt_hi[BATCH*NQ*CHN];
static __device__ __nv_bfloat16 g_xt_lo[BATCH*NQ*CHN];
static __device__ __nv_bfloat16 g_ct_hi[BATCH*NK*CHN];
static __device__ __nv_bfloat16 g_ct_lo[BATCH*NK*CHN];
static __device__ __nv_bfloat16 g_aq_hi[CHN*CHN];
static __device__ __nv_bfloat16 g_aq_lo[CHN*CHN];
static __device__ __nv_bfloat16 g_akv_hi[2*CHN*CHN];
static __device__ __nv_bfloat16 g_akv_lo[2*CHN*CHN];

// ---------------- PTX helpers ----------------
__device__ __forceinline__ uint32_t smem_to_u32(const void* p) {
    uint32_t a;
    asm("{ .reg .u64 t; cvta.to.shared.u64 t, %1; cvt.u32.u64 %0, t; }" : "=r"(a) : "l"(p));
    return a;
}
#define SW128(o) ((o) ^ (((o) >> 3) & 0x70))

// warp-shuffle block reduction: 256 threads -> lane-0 of warp 0 holds sum
__device__ __forceinline__ float block_reduce_sum(float v, float* red8, int tid) {
#pragma unroll
    for (int o = 16; o; o >>= 1) v += __shfl_xor_sync(0xffffffffu, v, o);
    if ((tid & 31) == 0) red8[tid >> 5] = v;
    __syncthreads();
    if (tid < 8) {
        v = red8[tid];
#pragma unroll
        for (int o = 4; o; o >>= 1) v += __shfl_xor_sync(0xffu, v, o);
    }
    return v;   // valid on tid 0
}

#if HAS_TCGEN05
__device__ __forceinline__ uint32_t elect_one_pred() {
    uint32_t pred;
    asm volatile("{\n\t.reg .pred p;\n\telect.sync _|p, 0xFFFFFFFF;\n\tselp.b32 %0, 1, 0, p;\n\t}"
                 : "=r"(pred));
    return pred;
}

static constexpr uint64_t SMEM_DESC_BASE_SW128 =
    (uint64_t(2) << 61) | (uint64_t(1) << 46) | (uint64_t(64) << 32) | (uint64_t(1) << 16);
#define MAKE_SMEM_DESC(base_addr) \
    (SMEM_DESC_BASE_SW128 | ((uint64_t)((base_addr) >> 4) & 0x3FFF))

#define TCGEN05_ALLOC(smem_result_addr, nCols) \
    asm volatile("tcgen05.alloc.cta_group::1.sync.aligned.shared::cta.b32 [%0], %1;" \
        :: "r"((uint32_t)(smem_result_addr)), "r"((uint32_t)(nCols)) : "memory")
#define TCGEN05_DEALLOC(tmem_addr, nCols) \
    asm volatile("tcgen05.dealloc.cta_group::1.sync.aligned.b32 %0, %1;" \
        :: "r"(tmem_addr), "r"((uint32_t)(nCols)))
#define TCGEN05_RELINQUISH() \
    asm volatile("tcgen05.relinquish_alloc_permit.cta_group::1.sync.aligned;")
#define TCGEN05_COMMIT(mbar_smem_addr) \
    asm volatile("tcgen05.commit.cta_group::1.mbarrier::arrive::one.shared::cluster.b64 [%0];" \
        :: "r"((uint32_t)(mbar_smem_addr)) : "memory")
#define TCGEN05_FENCE_AFTER() \
    asm volatile("tcgen05.fence::after_thread_sync;" ::: "memory")
#define TCGEN05_WAIT_LD() \
    asm volatile("tcgen05.wait::ld.sync.aligned;" ::: "memory")
#define FENCE_PROXY_ASYNC_SHARED_CTA() \
    asm volatile("fence.proxy.async.shared::cta;" ::: "memory")
#define MBARRIER_INIT(mbar, count) \
    asm volatile("mbarrier.init.shared.b64 [%0], %1;" \
        :: "r"((uint32_t)(mbar)), "r"((uint32_t)(count)) : "memory")
#define MBARRIER_INVAL(mbar) \
    asm volatile("mbarrier.inval.shared.b64 [%0];" :: "r"((uint32_t)(mbar)) : "memory")
#define MBARRIER_WAIT_PARITY(mbar_smem_addr, phase_parity) do { \
    uint32_t _mbar = (uint32_t)(mbar_smem_addr); \
    uint32_t _parity = (uint32_t)(phase_parity); \
    uint32_t _done; \
    asm volatile("{\n\t.reg .pred p;\n\t" \
        "mbarrier.try_wait.parity.acquire.cta.shared::cta.b64 p, [%1], %2;\n\t" \
        "selp.b32 %0, 1, 0, p;\n\t}" \
        : "=r"(_done) : "r"(_mbar), "r"(_parity) : "memory"); \
    if (!_done) { \
        asm volatile("{\n\t.reg .pred P1;\n\t" \
            "WAIT_LOOP_%=:\n\t" \
            "mbarrier.try_wait.parity.acquire.cta.shared::cta.b64 P1, [%0], %1, 0x989680;\n\t" \
            "@P1 bra.uni WAIT_DONE_%=;\n\t" \
            "bra.uni WAIT_LOOP_%=;\n\t" \
            "WAIT_DONE_%=:\n\t}" \
            :: "r"(_mbar), "r"(_parity) : "memory"); \
    } \
} while(0)

#define TCGEN05_LD_32X32B_X32(r, tmem_addr) \
    asm volatile("tcgen05.ld.sync.aligned.32x32b.x32.b32 " \
        "{%0, %1, %2, %3, %4, %5, %6, %7, %8, %9, %10, %11, %12, %13, %14, %15, " \
        " %16, %17, %18, %19, %20, %21, %22, %23, %24, %25, %26, %27, %28, %29, %30, %31}, [%32];" \
        : "=r"((r)[0]),  "=r"((r)[1]),  "=r"((r)[2]),  "=r"((r)[3]), \
          "=r"((r)[4]),  "=r"((r)[5]),  "=r"((r)[6]),  "=r"((r)[7]), \
          "=r"((r)[8]),  "=r"((r)[9]),  "=r"((r)[10]), "=r"((r)[11]), \
          "=r"((r)[12]), "=r"((r)[13]), "=r"((r)[14]), "=r"((r)[15]), \
          "=r"((r)[16]), "=r"((r)[17]), "=r"((r)[18]), "=r"((r)[19]), \
          "=r"((r)[20]), "=r"((r)[21]), "=r"((r)[22]), "=r"((r)[23]), \
          "=r"((r)[24]), "=r"((r)[25]), "=r"((r)[26]), "=r"((r)[27]), \
          "=r"((r)[28]), "=r"((r)[29]), "=r"((r)[30]), "=r"((r)[31]) \
        : "r"(tmem_addr))

__device__ __forceinline__ void mma_f16_ss(uint32_t d_tmem, uint64_t a_desc, uint64_t b_desc,
                                           uint32_t idesc, uint32_t enable_d) {
    asm volatile(
        "{\n\t.reg .pred p;\n\t"
        "setp.ne.u32 p, %4, 0;\n\t"
        "tcgen05.mma.cta_group::1.kind::f16 [%0], %1, %2, %3, {%5, %5, %5, %5}, p;\n\t}"
        :: "r"(d_tmem), "l"(a_desc), "l"(b_desc), "r"(idesc), "r"(enable_d), "r"(0u)
        : "memory");
}

static constexpr uint32_t GEMM_IDESC =
    (1u << 4) | (1u << 7) | (1u << 10) | ((128u / 8u) << 17) | ((128u / 16u) << 24);
#endif  // HAS_TCGEN05

// ---------------- convert helpers ----------------
__device__ __forceinline__ void split_bf16(float x, __nv_bfloat16& h, __nv_bfloat16& l) {
    h = __float2bfloat16(x);
    l = __float2bfloat16(x - __bfloat162float(h));
}
__device__ __forceinline__ float bfu2f(uint32_t u16) {
    return __bfloat162float(__ushort_as_bfloat16((unsigned short)u16));
}

__global__ void convert_w(const float* __restrict__ Wq, const float* __restrict__ Wk,
                          const float* __restrict__ Wv,
                          __nv_bfloat16* __restrict__ aq_hi, __nv_bfloat16* __restrict__ aq_lo,
                          __nv_bfloat16* __restrict__ akv_hi, __nv_bfloat16* __restrict__ akv_lo,
                          float* __restrict__ lg, float* __restrict__ kn2,
                          float* __restrict__ qn2)
{
    if (blockIdx.x == 0) {
        for (int i = threadIdx.x; i < BATCH*HEADS*CPH*CPH; i += 256) lg[i] = 0.f;
        for (int i = threadIdx.x; i < BATCH*CHN; i += 256) { kn2[i] = 0.f; qn2[i] = 0.f; }
    }
    int i = blockIdx.x * 256 + threadIdx.x;
    __nv_bfloat16 h, l;
    if (i < 65536) {
        split_bf16(Wq[i], h, l); aq_hi[i] = h; aq_lo[i] = l;
    } else if (i < 131072) {
        int j = i - 65536;
        split_bf16(Wk[j], h, l); akv_hi[j] = h; akv_lo[j] = l;
    } else {
        int j = i - 131072;
        split_bf16(Wv[j], h, l); akv_hi[65536 + j] = h; akv_lo[65536 + j] = l;
    }
}

// ---------------- X convert: [B,C,N] f32 -> [B,N,C] bf16 hi/lo ----------------
__global__ __launch_bounds__(256) void convert_x(const float* __restrict__ X,
                                                 __nv_bfloat16* __restrict__ Th,
                                                 __nv_bfloat16* __restrict__ Tl, int N)
{
    __shared__ float s[64][33];
    int b = blockIdx.z, c0 = blockIdx.y * 64, n0 = blockIdx.x * 32;
    const float* Xb = X + (size_t)b * 256 * N;
    int lane = threadIdx.x & 31, w = threadIdx.x >> 5;
#pragma unroll
    for (int i = 0; i < 8; i++) {
        int c = w + i * 8;
        s[c][lane] = Xb[(size_t)(c0 + c) * N + n0 + lane];
    }
    __syncthreads();
    uint32_t* TH = (uint32_t*)(Th + (size_t)b * N * 256);
    uint32_t* TL = (uint32_t*)(Tl + (size_t)b * N * 256);
#pragma unroll
    for (int i = 0; i < 4; i++) {
        int n = w + i * 8;
        float x0 = s[2 * lane][n], x1 = s[2 * lane + 1][n];
        __nv_bfloat16 h0, l0, h1, l1;
        split_bf16(x0, h0, l0); split_bf16(x1, h1, l1);
        uint32_t hp = ((uint32_t)__bfloat16_as_ushort(h1) << 16) | __bfloat16_as_ushort(h0);
        uint32_t lp = ((uint32_t)__bfloat16_as_ushort(l1) << 16) | __bfloat16_as_ushort(l0);
        size_t idx = (size_t)(n0 + n) * 128 + (c0 >> 1) + lane;
        TH[idx] = hp; TL[idx] = lp;
    }
}

// ---------------- GEMM ----------------
#if HAS_TCGEN05
__device__ __forceinline__ void load_tile_sw(const __nv_bfloat16* __restrict__ src,
                                             char* __restrict__ dst, int tid)
{
#pragma unroll
    for (int it = 0; it < 4; it++) {
        int i = tid + it * 256;
        int row = i >> 3, seg = i & 7;
        uint4 v = *(const uint4*)(src + (size_t)row * 256 + seg * 8);
        uint32_t off = (uint32_t)(row * 128 + seg * 16);
        *(uint4*)(dst + SW128(off)) = v;
    }
}
#endif

__global__ __launch_bounds__(256, 1) void gemm_tc(
    const __nv_bfloat16* __restrict__ Ahi, const __nv_bfloat16* __restrict__ Alo,
    const __nv_bfloat16* __restrict__ Bhi, const __nv_bfloat16* __restrict__ Blo,
    float* __restrict__ Y, int Ntot)
{
    extern __shared__ char dsm[];
    int tid = threadIdx.x;
    int m0 = blockIdx.y * 128, n0 = blockIdx.x * 128, b = blockIdx.z;
    int Mtot = gridDim.y * 128;
    const __nv_bfloat16* Bh = Bhi + (size_t)b * Ntot * 256;
    const __nv_bfloat16* Bl = Blo + (size_t)b * Ntot * 256;
    float* Yb = Y + (size_t)b * Mtot * Ntot;

#if HAS_TCGEN05
    __shared__ uint32_t s_tmem[1];
    __shared__ unsigned long long s_mbar[2];
    uint32_t dsm_u = smem_to_u32(dsm);
    uint32_t sb = (dsm_u + 1023) & ~1023u;
    char* sbp = dsm + (sb - dsm_u);
    uint32_t mb[2] = { smem_to_u32(&s_mbar[0]), smem_to_u32(&s_mbar[1]) };
    int wid = tid >> 5;

    if (wid == 0) TCGEN05_ALLOC(smem_to_u32(s_tmem), 128);
    if (tid == 0) { MBARRIER_INIT(mb[0], 1); MBARRIER_INIT(mb[1], 1); }
    __syncthreads();
    uint32_t tbase = s_tmem[0];

    for (int ch = 0; ch < 4; ch++) {
        int buf = ch & 1;
        char* bp = sbp + buf * 65536;
        if (ch >= 2) MBARRIER_WAIT_PARITY(mb[buf], 0);
        int c0 = ch * 64;
        load_tile_sw(Ahi + (size_t)m0 * 256 + c0, bp,          tid);
        load_tile_sw(Alo + (size_t)m0 * 256 + c0, bp + 16384,  tid);
        load_tile_sw(Bh  + (size_t)n0 * 256 + c0, bp + 32768,  tid);
        load_tile_sw(Bl  + (size_t)n0 * 256 + c0, bp + 49152,  tid);
        FENCE_PROXY_ASYNC_SHARED_CTA();
        __syncthreads();
        if (wid == 0) {
            if (elect_one_pred()) {
                uint32_t base = sb + buf * 65536;
                uint64_t dah = MAKE_SMEM_DESC(base);
                uint64_t dal = MAKE_SMEM_DESC(base + 16384);
                uint64_t dbh = MAKE_SMEM_DESC(base + 32768);
                uint64_t dbl = MAKE_SMEM_DESC(base + 49152);
#pragma unroll
                for (int k = 0; k < 4; k++)
                    mma_f16_ss(tbase, dah + 2 * k, dbh + 2 * k, GEMM_IDESC,
                               (ch > 0 || k > 0) ? 1u : 0u);
#pragma unroll
                for (int k = 0; k < 4; k++)
                    mma_f16_ss(tbase, dah + 2 * k, dbl + 2 * k, GEMM_IDESC, 1u);
#pragma unroll
                for (int k = 0; k < 4; k++)
                    mma_f16_ss(tbase, dal + 2 * k, dbh + 2 * k, GEMM_IDESC, 1u);
                TCGEN05_COMMIT(mb[buf]);
            }
        }
    }

    MBARRIER_WAIT_PARITY(mb[0], 1);
    MBARRIER_WAIT_PARITY(mb[1], 1);
    TCGEN05_FENCE_AFTER();

    float* Ds = (float*)sbp;
    uint32_t woff = (uint32_t)(wid & 3) << 21;
    int cb0 = (wid >= 4) ? 2 : 0;
    int lane = tid & 31;
    int row = (wid & 3) * 32 + lane;
    uint32_t regs[32];
#pragma unroll
    for (int j = 0; j < 2; j++) {
        int cb = cb0 + j;
        TCGEN05_LD_32X32B_X32(regs, tbase + cb * 32 + woff);
        TCGEN05_WAIT_LD();
#pragma unroll
        for (int c = 0; c < 32; c++)
            Ds[row * 132 + cb * 32 + c] = __uint_as_float(regs[c]);
    }
    __syncthreads();
#pragma unroll
    for (int it = 0; it < 16; it++) {
        int i = tid + it * 256;
        int r = i >> 5, c4 = (i & 31) * 4;
        float4 v = *(float4*)&Ds[r * 132 + c4];
        *(float4*)&Yb[(size_t)(m0 + r) * Ntot + n0 + c4] = v;
    }
    __syncthreads();
    if (tid == 0) { MBARRIER_INVAL(mb[0]); MBARRIER_INVAL(mb[1]); }
    if (wid == 0) { TCGEN05_RELINQUISH(); TCGEN05_DEALLOC(tbase, 128); }

#else  // SIMT fallback
    float* As = (float*)dsm;
    float* Bs = As + 8 * 128;
    int ty = tid >> 4, tx = tid & 15;
    int r = tid >> 1, kq = (tid & 1) * 4;

    float acc[8][8];
#pragma unroll
    for (int i = 0; i < 8; i++)
#pragma unroll
        for (int j = 0; j < 8; j++) acc[i][j] = 0.f;

    for (int c0 = 0; c0 < 256; c0 += 8) {
        {
            size_t off = (size_t)(m0 + r) * 256 + c0 + kq;
            uint2 vh = *(const uint2*)(Ahi + off);
            uint2 vl = *(const uint2*)(Alo + off);
            As[(kq + 0) * 128 + r] = bfu2f(vh.x & 0xffff)  + bfu2f(vl.x & 0xffff);
            As[(kq + 1) * 128 + r] = bfu2f(vh.x >> 16)     + bfu2f(vl.x >> 16);
            As[(kq + 2) * 128 + r] = bfu2f(vh.y & 0xffff)  + bfu2f(vl.y & 0xffff);
            As[(kq + 3) * 128 + r] = bfu2f(vh.y >> 16)     + bfu2f(vl.y >> 16);
            size_t offb = (size_t)(n0 + r) * 256 + c0 + kq;
            uint2 wh = *(const uint2*)(Bh + offb);
            uint2 wl = *(const uint2*)(Bl + offb);
            Bs[(kq + 0) * 128 + r] = bfu2f(wh.x & 0xffff)  + bfu2f(wl.x & 0xffff);
            Bs[(kq + 1) * 128 + r] = bfu2f(wh.x >> 16)     + bfu2f(wl.x >> 16);
            Bs[(kq + 2) * 128 + r] = bfu2f(wh.y & 0xffff)  + bfu2f(wl.y & 0xffff);
            Bs[(kq + 3) * 128 + r] = bfu2f(wh.y >> 16)     + bfu2f(wl.y >> 16);
        }
        __syncthreads();
#pragma unroll
        for (int kk = 0; kk < 8; kk++) {
            float a[8], bb[8];
            *(float4*)&a[0]  = *(const float4*)&As[kk * 128 + ty * 8];
            *(float4*)&a[4]  = *(const float4*)&As[kk * 128 + ty * 8 + 4];
            *(float4*)&bb[0] = *(const float4*)&Bs[kk * 128 + tx * 8];
            *(float4*)&bb[4] = *(const float4*)&Bs[kk * 128 + tx * 8 + 4];
#pragma unroll
            for (int i = 0; i < 8; i++)
#pragma unroll
                for (int j = 0; j < 8; j++)
                    acc[i][j] = fmaf(a[i], bb[j], acc[i][j]);
        }
        __syncthreads();
    }
#pragma unroll
    for (int i = 0; i < 8; i++) {
        float* yp = Yb + (size_t)(m0 + ty * 8 + i) * Ntot + n0 + tx * 8;
        *(float4*)yp       = make_float4(acc[i][0], acc[i][1], acc[i][2], acc[i][3]);
        *(float4*)(yp + 4) = make_float4(acc[i][4], acc[i][5], acc[i][6], acc[i][7]);
    }
#endif
}

// ---------------- plain templated WTConv (Haar, ks=3), 32-row tiles — used for v ----------------
template<int W>
__global__ __launch_bounds__(256, 4) void wtconv_t(
    const float* __restrict__ X, float* __restrict__ Y,
    const float* __restrict__ base_w, const float* __restrict__ base_s,
    const float* __restrict__ wav_w,  const float* __restrict__ wav_s,
    int H, int cs_in)
{
    constexpr int LW = W + 4;
    constexpr int SWc = (W >> 1) + 2;
    constexpr int Wh = W >> 1;
    __shared__ float ins[36][LW];
    __shared__ float sub[4][18][SWc];
    __shared__ float swav[4][9];
    __shared__ float sbw[9];
    __shared__ float swsc[4];
    __shared__ float sbs;

    int bc = blockIdx.x;
    int b  = bc >> 8;
    int c  = bc & 255;
    int y0 = blockIdx.y * 32;
    const float* Xc = X + ((size_t)b * cs_in + c) * H * W;
    float*       Yc = Y + (size_t)bc * H * W;
    int tid = threadIdx.x;

    if (tid < 36) {
        int f = tid / 9, i = tid - f * 9;
        swav[f][i] = wav_w[(size_t)(c * 4 + f) * 9 + i];
    } else if (tid < 45) {
        sbw[tid - 36] = base_w[(size_t)c * 9 + tid - 36];
    } else if (tid < 49) {
        swsc[tid - 45] = wav_s[c * 4 + tid - 45];
    } else if (tid == 49) {
        sbs = base_s[c];
    }

    for (int idx = tid; idx < 36 * LW; idx += 256) {
        int ly = idx / LW, lx = idx - ly * LW;
        int gy = y0 + ly - 2, gx = lx - 2;
        float v = 0.f;
        if (gy >= 0 && gy < H && gx >= 0 && gx < W) v = Xc[gy * W + gx];
        ins[ly][lx] = v;
    }
    __syncthreads();

    for (int idx = tid; idx < 18 * SWc; idx += 256) {
        int sy = idx / SWc, sx = idx - sy * SWc;
        float a = ins[2 * sy][2 * sx],     bq = ins[2 * sy][2 * sx + 1];
        float d = ins[2 * sy + 1][2 * sx], e = ins[2 * sy + 1][2 * sx + 1];
        sub[0][sy][sx] = 0.5f * (a + bq + d + e);
        sub[1][sy][sx] = 0.5f * (a + bq - d - e);
        sub[2][sy][sx] = 0.5f * (a - bq + d - e);
        sub[3][sy][sx] = 0.5f * (a - bq - d + e);
    }
    __syncthreads();

    for (int idx = tid; idx < 16 * Wh; idx += 256) {
        int syi = idx / Wh, sxi = idx - syi * Wh;
        int sy = syi + 1, sx = sxi + 1;
        float r[4];
#pragma unroll
        for (int f = 0; f < 4; f++) {
            float s = 0.f;
#pragma unroll
            for (int dy = 0; dy < 3; dy++)
#pragma unroll
                for (int dx = 0; dx < 3; dx++)
                    s = fmaf(swav[f][dy * 3 + dx], sub[f][sy - 1 + dy][sx - 1 + dx], s);
            r[f] = s * swsc[f];
        }
        float y00 = 0.5f * (r[0] + r[1] + r[2] + r[3]);
        float y01 = 0.5f * (r[0] + r[1] - r[2] - r[3]);
        float y10 = 0.5f * (r[0] - r[1] + r[2] - r[3]);
        float y11 = 0.5f * (r[0] - r[1] - r[2] + r[3]);

        float base[2][2];
#pragma unroll
        for (int p = 0; p < 2; p++)
#pragma unroll
            for (int q = 0; q < 2; q++) {
                float s = 0.f;
#pragma unroll
                for (int dy = 0; dy < 3; dy++)
#pragma unroll
                    for (int dx = 0; dx < 3; dx++)
                        s = fmaf(sbw[dy * 3 + dx],
                                 ins[2 * sy + p - 1 + dy][2 * sx + q - 1 + dx], s);
                base[p][q] = s * sbs;
            }
        int gy = y0 + 2 * syi, gx = 2 * sxi;
        Yc[(gy + 0) * W + gx + 0] = base[0][0] + y00;
        Yc[(gy + 0) * W + gx + 1] = base[0][1] + y01;
        Yc[(gy + 1) * W + gx + 0] = base[1][0] + y10;
        Yc[(gy + 1) * W + gx + 1] = base[1][1] + y11;
    }
}

// ---------------- fused wtconv(k) + transposed-bilinear downsample + ||k||², 32-row tiles ----------------
#define KD_SMEM ((40*132 + 4*20*66 + 36*130) * 4)

__global__ __launch_bounds__(256, 3) void wtconv_k_down(
    const float* __restrict__ X, float* __restrict__ kdn,
    const float* __restrict__ base_w, const float* __restrict__ base_s,
    const float* __restrict__ wav_w,  const float* __restrict__ wav_s,
    float* __restrict__ kn2)
{
    extern __shared__ float sm[];
    float* ins  = sm;                    // [40][132]
    float* sub  = ins + 40 * 132;        // [4][20][66]
    float* outb = sub + 4 * 20 * 66;     // [36][130]
    __shared__ float swav[4][9];
    __shared__ float sbw[9];
    __shared__ float swsc[4];
    __shared__ float sbs;
    __shared__ float red8[8];

    int bc = blockIdx.x;
    int b  = bc >> 8;
    int c  = bc & 255;
    int by = blockIdx.y;
    int y0 = by * 32;
    const float* Xc = X + ((size_t)b * 512 + c) * (size_t)NK;
    int tid = threadIdx.x;

    if (tid < 36) {
        int f = tid / 9, i = tid - f * 9;
        swav[f][i] = wav_w[(size_t)(c * 4 + f) * 9 + i];
    } else if (tid < 45) {
        sbw[tid - 36] = base_w[(size_t)c * 9 + tid - 36];
    } else if (tid < 49) {
        swsc[tid - 45] = wav_s[c * 4 + tid - 45];
    } else if (tid == 49) {
        sbs = base_s[c];
    }

    for (int idx = tid; idx < 40 * 132; idx += 256) {
        int ly = idx / 132, lx = idx - ly * 132;
        int gy = y0 + ly - 4, gx = lx - 2;
        float v = 0.f;
        if (gy >= 0 && gy < 128 && gx >= 0 && gx < 128) v = Xc[gy * 128 + gx];
        ins[idx] = v;
    }
    __syncthreads();

    for (int idx = tid; idx < 20 * 66; idx += 256) {
        int sy = idx / 66, sx = idx - sy * 66;
        const float* r0 = ins + (2 * sy) * 132 + 2 * sx;
        float a = r0[0], bq = r0[1], d = r0[132], e = r0[133];
        sub[0 * 1320 + idx] = 0.5f * (a + bq + d + e);
        sub[1 * 1320 + idx] = 0.5f * (a + bq - d - e);
        sub[2 * 1320 + idx] = 0.5f * (a - bq + d - e);
        sub[3 * 1320 + idx] = 0.5f * (a - bq - d + e);
    }
    __syncthreads();

    for (int idx = tid; idx < 18 * 64; idx += 256) {
        int syo = idx >> 6, j = idx & 63;
        int sy = syo + 1, sx = j + 1;
        float r[4];
#pragma unroll
        for (int f = 0; f < 4; f++) {
            const float* sf = sub + f * 1320;
            float s = 0.f;
#pragma unroll
            for (int dy = 0; dy < 3; dy++)
#pragma unroll
                for (int dx = 0; dx < 3; dx++)
                    s = fmaf(swav[f][dy * 3 + dx], sf[(sy - 1 + dy) * 66 + sx - 1 + dx], s);
            r[f] = s * swsc[f];
        }
        float y00 = 0.5f * (r[0] + r[1] + r[2] + r[3]);
        float y01 = 0.5f * (r[0] + r[1] - r[2] - r[3]);
        float y10 = 0.5f * (r[0] - r[1] + r[2] - r[3]);
        float y11 = 0.5f * (r[0] - r[1] - r[2] + r[3]);

        float base[2][2];
#pragma unroll
        for (int p = 0; p < 2; p++)
#pragma unroll
            for (int q = 0; q < 2; q++) {
                float s = 0.f;
#pragma unroll
                for (int dy = 0; dy < 3; dy++)
#pragma unroll
                    for (int dx = 0; dx < 3; dx++)
                        s = fmaf(sbw[dy * 3 + dx],
                                 ins[(2 * syo + 1 + p + dy) * 132 + 2 * j + 1 + q + dx], s);
                base[p][q] = s * sbs;
            }
        outb[(2 * syo) * 130 + 2 * j]         = base[0][0] + y00;
        outb[(2 * syo) * 130 + 2 * j + 1]     = base[0][1] + y01;
        outb[(2 * syo + 1) * 130 + 2 * j]     = base[1][0] + y10;
        outb[(2 * syo + 1) * 130 + 2 * j + 1] = base[1][1] + y11;
    }
    __syncthreads();

    float sumsq = 0.f;
    for (int idx = tid; idx < 32 * 128; idx += 256) {
        int lr = (idx >> 7) + 2, lc = idx & 127;
        float v = outb[lr * 130 + lc];
        sumsq += v * v;
    }

    for (int idx = tid; idx < 16 * 64; idx += 256) {
        int jj = idx >> 6, jx = idx & 63;
        int jy = 16 * by + jj;
        int lyt[4]; float wyt[4]; int cy = 0;
        if (jy > 0)  { lyt[cy] = 2*jj+1; wyt[cy++] = 0.25f; }
        lyt[cy] = 2*jj+2; wyt[cy++] = (jy == 0)  ? 1.0f : 0.75f;
        lyt[cy] = 2*jj+3; wyt[cy++] = (jy == 63) ? 1.0f : 0.75f;
        if (jy < 63) { lyt[cy] = 2*jj+4; wyt[cy++] = 0.25f; }
        int lxt[4]; float wxt[4]; int cx = 0;
        if (jx > 0)  { lxt[cx] = 2*jx-1; wxt[cx++] = 0.25f; }
        lxt[cx] = 2*jx;   wxt[cx++] = (jx == 0)  ? 1.0f : 0.75f;
        lxt[cx] = 2*jx+1; wxt[cx++] = (jx == 63) ? 1.0f : 0.75f;
        if (jx < 63) { lxt[cx] = 2*jx+2; wxt[cx++] = 0.25f; }
        float s = 0.f;
        for (int a = 0; a < cy; a++) {
            const float* row = outb + lyt[a] * 130;
            float rs = 0.f;
            for (int e = 0; e < cx; e++) rs = fmaf(wxt[e], row[lxt[e]], rs);
            s = fmaf(wyt[a], rs, s);
        }
        kdn[(size_t)bc * NQ + jy * 64 + jx] = s;
    }

    __syncthreads();
    float tot = block_reduce_sum(sumsq, red8, tid);
    if (tid == 0) atomicAdd(&kn2[bc], tot);
}

// ---------------- fused wtconv(q) + ||upsample(q)||² via Gram quadratic form ----------------
__global__ __launch_bounds__(256, 4) void wtconv_q_norm(
    const float* __restrict__ X, float* __restrict__ Y,
    const float* __restrict__ base_w, const float* __restrict__ base_s,
    const float* __restrict__ wav_w,  const float* __restrict__ wav_s,
    float* __restrict__ qn2)
{
    __shared__ float ins[40][68];
    __shared__ float sub[4][20][36];
    __shared__ float outb[36][66];
    __shared__ float swav[4][9];
    __shared__ float sbw[9];
    __shared__ float swsc[4];
    __shared__ float sbs;
    __shared__ float red8[8];

    int bc = blockIdx.x;
    int c  = bc & 255;
    int by = blockIdx.y;
    int y0 = by * 32;
    const float* Xc = X + (size_t)bc * NQ;
    float*       Yc = Y + (size_t)bc * NQ;
    int tid = threadIdx.x;

    if (tid < 36) {
        int f = tid / 9, i = tid - f * 9;
        swav[f][i] = wav_w[(size_t)(c * 4 + f) * 9 + i];
    } else if (tid < 45) {
        sbw[tid - 36] = base_w[(size_t)c * 9 + tid - 36];
    } else if (tid < 49) {
        swsc[tid - 45] = wav_s[c * 4 + tid - 45];
    } else if (tid == 49) {
        sbs = base_s[c];
    }

    for (int idx = tid; idx < 40 * 68; idx += 256) {
        int ly = idx / 68, lx = idx - ly * 68;
        int gy = y0 + ly - 4, gx = lx - 2;
        float v = 0.f;
        if (gy >= 0 && gy < 64 && gx >= 0 && gx < 64) v = Xc[gy * 64 + gx];
        ins[ly][lx] = v;
    }
    __syncthreads();

    for (int idx = tid; idx < 20 * 34; idx += 256) {
        int sy = idx / 34, sx = idx - sy * 34;
        float a = ins[2 * sy][2 * sx],     bq = ins[2 * sy][2 * sx + 1];
        float d = ins[2 * sy + 1][2 * sx], e = ins[2 * sy + 1][2 * sx + 1];
        sub[0][sy][sx] = 0.5f * (a + bq + d + e);
        sub[1][sy][sx] = 0.5f * (a + bq - d - e);
        sub[2][sy][sx] = 0.5f * (a - bq + d - e);
        sub[3][sy][sx] = 0.5f * (a - bq - d + e);
    }
    __syncthreads();

    for (int idx = tid; idx < 18 * 32; idx += 256) {
        int syo = idx >> 5, j = idx & 31;
        int sy = syo + 1, sx = j + 1;
        float r[4];
#pragma unroll
        for (int f = 0; f < 4; f++) {
            float s = 0.f;
#pragma unroll
            for (int dy = 0; dy < 3; dy++)
#pragma unroll
                for (int dx = 0; dx < 3; dx++)
                    s = fmaf(swav[f][dy * 3 + dx], sub[f][sy - 1 + dy][sx - 1 + dx], s);
            r[f] = s * swsc[f];
        }
        float y00 = 0.5f * (r[0] + r[1] + r[2] + r[3]);
        float y01 = 0.5f * (r[0] + r[1] - r[2] - r[3]);
        float y10 = 0.5f * (r[0] - r[1] + r[2] - r[3]);
        float y11 = 0.5f * (r[0] - r[1] - r[2] + r[3]);

        float base[2][2];
#pragma unroll
        for (int p = 0; p < 2; p++)
#pragma unroll
            for (int q = 0; q < 2; q++) {
                float s = 0.f;
#pragma unroll
                for (int dy = 0; dy < 3; dy++)
#pragma unroll
                    for (int dx = 0; dx < 3; dx++)
                        s = fmaf(sbw[dy * 3 + dx],
                                 ins[2 * syo + 1 + p + dy][2 * j + 1 + q + dx], s);
                base[p][q] = s * sbs;
            }
        float o00 = base[0][0] + y00, o01 = base[0][1] + y01;
        float o10 = base[1][0] + y10, o11 = base[1][1] + y11;
        outb[2 * syo][2 * j]         = o00;
        outb[2 * syo][2 * j + 1]     = o01;
        outb[2 * syo + 1][2 * j]     = o10;
        outb[2 * syo + 1][2 * j + 1] = o11;
        if (syo >= 1 && syo <= 16) {
            int gy = y0 - 2 + 2 * syo;
            Yc[(gy + 0) * 64 + 2 * j]     = o00;
            Yc[(gy + 0) * 64 + 2 * j + 1] = o01;
            Yc[(gy + 1) * 64 + 2 * j]     = o10;
            Yc[(gy + 1) * 64 + 2 * j + 1] = o11;
        }
    }
    __syncthreads();

    // Gram quadratic form over owned rows (global y0..y0+31, local 2..33)
    float sum = 0.f;
    for (int idx = tid; idx < 32 * 64; idx += 256) {
        int yl = idx >> 6, x = idx & 63;
        int yg = y0 + yl;
        int ly = yl + 2;
        float dyc = (yg == 0 || yg == 63) ? 1.625f : 1.25f;
        float dxc = (x == 0 || x == 63) ? 1.625f : 1.25f;
        float ql = (x > 0)  ? 0.375f : 0.f;
        float qr = (x < 63) ? 0.375f : 0.f;

        const float* rm = &outb[ly - 1][x];
        const float* rc = &outb[ly][x];
        const float* rp = &outb[ly + 1][x];
        float um = ql * rm[-1] + dxc * rm[0] + qr * rm[1];
        float uc = ql * rc[-1] + dxc * rc[0] + qr * rc[1];
        float up = ql * rp[-1] + dxc * rp[0] + qr * rp[1];

        float gm = (yg > 0)  ? 0.375f : 0.f;
        float gp = (yg < 63) ? 0.375f : 0.f;
        sum += rc[0] * (gm * um + dyc * uc + gp * up);
    }
    float tot = block_reduce_sum(sum, red8, tid);
    if (tid == 0) atomicAdd(&qn2[bc], tot);
}

// ---------------- attention logits ----------------
__global__ __launch_bounds__(256) void attn_partial(
    const float* __restrict__ qp, const float* __restrict__ kp,
    float* __restrict__ logits, int N)
{
    __shared__ float qsT[64][33];
    __shared__ float ksT[64][33];
    int bh = blockIdx.y;
    int n0 = blockIdx.x * 512;
    const float* q = qp + (size_t)bh * 32 * N + n0;
    const float* k = kp + (size_t)bh * 32 * N + n0;
    int tid = threadIdx.x;
    int i0 = (tid & 7) * 4, j0 = ((tid >> 3) & 7) * 4, ns = tid >> 6;

    float acc[4][4];
#pragma unroll
    for (int i = 0; i < 4; i++)
#pragma unroll
        for (int j = 0; j < 4; j++) acc[i][j] = 0.f;

    for (int nc = 0; nc < 512; nc += 64) {
        for (int l = tid; l < 512; l += 256) {
            int row = l >> 4, col4 = (l & 15) * 4;
            float4 a = *(const float4*)(q + (size_t)row * N + nc + col4);
            float4 b = *(const float4*)(k + (size_t)row * N + nc + col4);
            qsT[col4 + 0][row] = a.x; qsT[col4 + 1][row] = a.y;
            qsT[col4 + 2][row] = a.z; qsT[col4 + 3][row] = a.w;
            ksT[col4 + 0][row] = b.x; ksT[col4 + 1][row] = b.y;
            ksT[col4 + 2][row] = b.z; ksT[col4 + 3][row] = b.w;
        }
        __syncthreads();
        for (int nn = ns; nn < 64; nn += 4) {
            float qv[4], kv[4];
#pragma unroll
            for (int m = 0; m < 4; m++) { qv[m] = qsT[nn][i0 + m]; kv[m] = ksT[nn][j0 + m]; }
#pragma unroll
            for (int i = 0; i < 4; i++)
#pragma unroll
                for (int j = 0; j < 4; j++)
                    acc[i][j] = fmaf(qv[i], kv[j], acc[i][j]);
        }
        __syncthreads();
    }
    float* L = logits + (size_t)bh * 1024;
#pragma unroll
    for (int i = 0; i < 4; i++)
#pragma unroll
        for (int j = 0; j < 4; j++)
            atomicAdd(&L[(i0 + i) * 32 + j0 + j], acc[i][j]);
}

// ---------------- fused softmax + (attn @ v) + proj WTConv(ks=1) -> d_out ----------------
__global__ __launch_bounds__(256) void av_proj_kernel(
    const float* __restrict__ logits, const float* __restrict__ qn2,
    const float* __restrict__ kn2, const float* __restrict__ temp,
    const float* __restrict__ v,
    const float* __restrict__ pbw, const float* __restrict__ pbs,
    const float* __restrict__ pww, const float* __restrict__ pws,
    float* __restrict__ out)
{
    __shared__ float As[32][33];
    __shared__ float2 vt[32][2][8];

    int by = blockIdx.x;
    int bh = blockIdx.y;
    int b  = bh >> 3, h = bh & 7;
    int tid = threadIdx.x;
    int i  = tid >> 3;
    int pb = tid & 7;

    for (int l = tid; l < 1024; l += 256) As[l >> 5][l & 31] = logits[(size_t)bh * 1024 + l];
    __syncthreads();

    {
        int w = tid >> 5, lane = tid & 31;
        float tmp = temp[h];
        float kvn = fmaxf(sqrtf(kn2[b * 256 + h * 32 + lane]), 1e-12f);
#pragma unroll
        for (int rr = 0; rr < 4; rr++) {
            int r = w * 4 + rr;
            float qvn = fmaxf(sqrtf(qn2[b * 256 + h * 32 + r]), 1e-12f);
            float val = As[r][lane] * tmp / (qvn * kvn);
            float m = val;
#pragma unroll
            for (int o = 16; o; o >>= 1) m = fmaxf(m, __shfl_xor_sync(0xffffffffu, m, o));
            float e = expf(val - m);
            float s = e;
#pragma unroll
            for (int o = 16; o; o >>= 1) s += __shfl_xor_sync(0xffffffffu, s, o);
            As[r][lane] = e / s;
        }
    }
    __syncthreads();

    float arow[32];
#pragma unroll
    for (int j = 0; j < 32; j++) arow[j] = As[i][j];

    int cw = h * 32 + i;
    float bw  = pbw[cw] * pbs[cw];
    float wv0 = pww[cw * 4 + 0] * pws[cw * 4 + 0];
    float wv1 = pww[cw * 4 + 1] * pws[cw * 4 + 1];
    float wv2 = pww[cw * 4 + 2] * pws[cw * 4 + 2];
    float wv3 = pww[cw * 4 + 3] * pws[cw * 4 + 3];

    const float* vb = v + (size_t)(b * 256 + h * 32) * NK;
    float* ob = out + (size_t)(b * 256 + h * 32 + i) * NK;

    int sj = tid >> 3, sr = (tid >> 2) & 1, sxq = tid & 3;

    for (int bx0 = 0; bx0 < 64; bx0 += 8) {
        __syncthreads();
        {
            float4 v4 = *(const float4*)(vb + (size_t)sj * NK + (2 * by + sr) * 128
                                         + 2 * bx0 + sxq * 4);
            vt[sj][sr][2 * sxq + 0] = make_float2(v4.x, v4.y);
            vt[sj][sr][2 * sxq + 1] = make_float2(v4.z, v4.w);
        }
        __syncthreads();

        float a00 = 0.f, a01 = 0.f, a10 = 0.f, a11 = 0.f;
#pragma unroll
        for (int j = 0; j < 32; j++) {
            float aA = arow[j];
            float2 t0 = vt[j][0][pb];
            float2 t1 = vt[j][1][pb];
            a00 = fmaf(aA, t0.x, a00); a01 = fmaf(aA, t0.y, a01);
            a10 = fmaf(aA, t1.x, a10); a11 = fmaf(aA, t1.y, a11);
        }

        float r0 = 0.5f * (a00 + a01 + a10 + a11) * wv0;
        float r1 = 0.5f * (a00 + a01 - a10 - a11) * wv1;
        float r2 = 0.5f * (a00 - a01 + a10 - a11) * wv2;
        float r3 = 0.5f * (a00 - a01 - a10 + a11) * wv3;
        float y00 = 0.5f * (r0 + r1 + r2 + r3) + a00 * bw;
        float y01 = 0.5f * (r0 + r1 - r2 - r3) + a01 * bw;
        float y10 = 0.5f * (r0 - r1 + r2 - r3) + a10 * bw;
        float y11 = 0.5f * (r0 - r1 - r2 + r3) + a11 * bw;

        int gx = 2 * (bx0 + pb);
        *(float2*)&ob[(2 * by + 0) * 128 + gx] = make_float2(y00, y01);
        *(float2*)&ob[(2 * by + 1) * 128 + gx] = make_float2(y10, y11);
    }
}

// ---------------- launch (multi-stream fork/join DAG) ----------------
#define GEMM_SMEM (1024 + 2 * 65536)

extern "C" void kernel_launch(void* const* d_in, const int* in_sizes, int n_in,
                              void* d_out, int out_size)
{
    const float* x    = (const float*)d_in[0];
    const float* cf   = (const float*)d_in[1];
    const float* Wq   = (const float*)d_in[2];
    const float* Wk   = (const float*)d_in[3];
    const float* Wv   = (const float*)d_in[4];
    const float* temp = (const float*)d_in[5];
    const float* qbw = (const float*)d_in[6];  const float* qbs = (const float*)d_in[7];
    const float* qww = (const float*)d_in[8];  const float* qws = (const float*)d_in[9];
    const float* kbw = (const float*)d_in[10]; const float* kbs = (const float*)d_in[11];
    const float* kww = (const float*)d_in[12]; const float* kws = (const float*)d_in[13];
    const float* vbw = (const float*)d_in[14]; const float* vbs = (const float*)d_in[15];
    const float* vww = (const float*)d_in[16]; const float* vws = (const float*)d_in[17];
    const float* pbw = (const float*)d_in[18]; const float* pbs = (const float*)d_in[19];
    const float* pww = (const float*)d_in[20]; const float* pws = (const float*)d_in[21];
    float* out = (float*)d_out;

    float *q, *kv, *qwt, *vwt, *kdn, *qn2, *kn2, *lg;
    __nv_bfloat16 *xt_hi, *xt_lo, *ct_hi, *ct_lo, *aq_hi, *aq_lo, *akv_hi, *akv_lo;
    cudaGetSymbolAddress((void**)&q,     g_q);
    cudaGetSymbolAddress((void**)&kv,    g_kv);
    cudaGetSymbolAddress((void**)&qwt,   g_qwt);
    cudaGetSymbolAddress((void**)&vwt,   g_vwt);
    cudaGetSymbolAddress((void**)&kdn,   g_kdn);
    cudaGetSymbolAddress((void**)&qn2,   g_qn2);
    cudaGetSymbolAddress((void**)&kn2,   g_kn2);
    cudaGetSymbolAddress((void**)&lg,    g_lg);
    cudaGetSymbolAddress((void**)&xt_hi, g_xt_hi);
    cudaGetSymbolAddress((void**)&xt_lo, g_xt_lo);
    cudaGetSymbolAddress((void**)&ct_hi, g_ct_hi);
    cudaGetSymbolAddress((void**)&ct_lo, g_ct_lo);
    cudaGetSymbolAddress((void**)&aq_hi, g_aq_hi);
    cudaGetSymbolAddress((void**)&aq_lo, g_aq_lo);
    cudaGetSymbolAddress((void**)&akv_hi, g_akv_hi);
    cudaGetSymbolAddress((void**)&akv_lo, g_akv_lo);

    cudaFuncSetAttribute(gemm_tc, cudaFuncAttributeMaxDynamicSharedMemorySize, GEMM_SMEM);
    cudaFuncSetAttribute(wtconv_k_down, cudaFuncAttributeMaxDynamicSharedMemorySize, KD_SMEM);

    static cudaStream_t s1 = nullptr, s2 = nullptr;
    static cudaEvent_t ev0 = nullptr, evW = nullptr, evE = nullptr, evF = nullptr, evH = nullptr;
    if (s1 == nullptr) {
        cudaStreamCreateWithFlags(&s1, cudaStreamNonBlocking);
        cudaStreamCreateWithFlags(&s2, cudaStreamNonBlocking);
        cudaEventCreateWithFlags(&ev0, cudaEventDisableTiming);
        cudaEventCreateWithFlags(&evW, cudaEventDisableTiming);
        cudaEventCreateWithFlags(&evE, cudaEventDisableTiming);
        cudaEventCreateWithFlags(&evF, cudaEventDisableTiming);
        cudaEventCreateWithFlags(&evH, cudaEventDisableTiming);
    }
    cudaStream_t s0 = 0;

    // fork
    cudaEventRecord(ev0, s0);
    cudaStreamWaitEvent(s1, ev0, 0);
    cudaStreamWaitEvent(s2, ev0, 0);

    // s2: weights convert + zero accumulators (off critical path)
    convert_w<<<768, 256, 0, s2>>>(Wq, Wk, Wv, aq_hi, aq_lo, akv_hi, akv_lo, lg, kn2, qn2);
    cudaEventRecord(evW, s2);

    // s1: q-path prologue
    convert_x<<<dim3(NQ / 32, 4, BATCH), 256, 0, s1>>>(x, xt_hi, xt_lo, NQ);
    cudaStreamWaitEvent(s1, evW, 0);
    gemm_tc<<<dim3(NQ / 128, 2, BATCH), 256, GEMM_SMEM, s1>>>(aq_hi, aq_lo, xt_hi, xt_lo, q, NQ);
    wtconv_q_norm<<<dim3(BATCH * CHN, 2), 256, 0, s1>>>(q, qwt, qbw, qbs, qww, qws, qn2);
    cudaEventRecord(evF, s1);

    // main: cf convert -> kv GEMM
    convert_x<<<dim3(NK / 32, 4, BATCH), 256, 0, s0>>>(cf, ct_hi, ct_lo, NK);
    cudaStreamWaitEvent(s0, evW, 0);
    gemm_tc<<<dim3(NK / 128, 4, BATCH), 256, GEMM_SMEM, s0>>>(akv_hi, akv_lo, ct_hi, ct_lo, kv, NK);
    cudaEventRecord(evE, s0);

    // s2: v wtconv (needs kv)
    cudaStreamWaitEvent(s2, evE, 0);
    wtconv_t<128><<<dim3(BATCH * CHN, 4), 256, 0, s2>>>(kv + (size_t)CHN * NK, vwt,
                                                        vbw, vbs, vww, vws, HK, 512);
    cudaEventRecord(evH, s2);

    // main: k wtconv + downsample + norm
    wtconv_k_down<<<dim3(BATCH * CHN, 4), 256, KD_SMEM, s0>>>(kv, kdn, kbw, kbs, kww, kws, kn2);

    // join q-path, attention logits
    cudaStreamWaitEvent(s0, evF, 0);
    attn_partial<<<dim3(NQ / 512, BATCH * HEADS), 256, 0, s0>>>(qwt, kdn, lg, NQ);

    // join v-path, fused softmax + av + proj
    cudaStreamWaitEvent(s0, evH, 0);
    av_proj_kernel<<<dim3(64, BATCH * HEADS), 256, 0, s0>>>(lg, qn2, kn2, temp, vwt,
                                                            pbw, pbs, pww, pws, out);
}

// round 13
// speedup vs baseline: 1.2359x; 1.0001x over previous
#include <cuda_runtime.h>
#include <cuda_bf16.h>
#include <math.h>
#include <stdint.h>

// ---------------- arch feature gate (tcgen05 is an "a"-feature) ----------------
#if defined(__CUDA_ARCH_FEAT_SM103_ALL) || defined(__CUDA_ARCH_FEAT_SM100_ALL) || \
    defined(__CUDA_ARCH_FEAT_SM101_ALL) || \
    (defined(__CUDA_ARCH_SPECIFIC__) && (__CUDA_ARCH_SPECIFIC__ >= 1000))
#define HAS_TCGEN05 1
#else
#define HAS_TCGEN05 0
#endif

// ---------------- problem constants ----------------
#define BATCH 2
#define CHN   256
#define HQ    64
#define WQ    64
#define HK    128
#define WK    128
#define NQ    (HQ*WQ)     // 4096
#define NK    (HK*WK)     // 16384
#define HEADS 8
#define CPH   32

// ---------------- scratch (device globals) ----------------
static __device__ float g_q  [BATCH*CHN*NQ];
static __device__ float g_kv [BATCH*2*CHN*NK];
static __device__ float g_qwt[BATCH*CHN*NQ];
static __device__ float g_vwt[BATCH*CHN*NK];
static __device__ float g_kdn[BATCH*CHN*NQ];
static __device__ float g_qn2[BATCH*CHN];
static __device__ float g_kn2[BATCH*CHN];
static __device__ float g_lg [BATCH*HEADS*CPH*CPH];
static __device__ __nv_bfloat16 g_xt_hi[BATCH*NQ*CHN];
static __device__ __nv_bfloat16 g_xt_lo[BATCH*NQ*CHN];
static __device__ __nv_bfloat16 g_ct_hi[BATCH*NK*CHN];
static __device__ __nv_bfloat16 g_ct_lo[BATCH*NK*CHN];
static __device__ __nv_bfloat16 g_aq_hi[CHN*CHN];
static __device__ __nv_bfloat16 g_aq_lo[CHN*CHN];
static __device__ __nv_bfloat16 g_akv_hi[2*CHN*CHN];
static __device__ __nv_bfloat16 g_akv_lo[2*CHN*CHN];

// ---------------- PTX helpers ----------------
__device__ __forceinline__ uint32_t smem_to_u32(const void* p) {
    uint32_t a;
    asm("{ .reg .u64 t; cvta.to.shared.u64 t, %1; cvt.u32.u64 %0, t; }" : "=r"(a) : "l"(p));
    return a;
}
#define SW128(o) ((o) ^ (((o) >> 3) & 0x70))

// warp-shuffle block reduction: 256 threads -> lane-0 of warp 0 holds sum
__device__ __forceinline__ float block_reduce_sum(float v, float* red8, int tid) {
#pragma unroll
    for (int o = 16; o; o >>= 1) v += __shfl_xor_sync(0xffffffffu, v, o);
    if ((tid & 31) == 0) red8[tid >> 5] = v;
    __syncthreads();
    if (tid < 8) {
        v = red8[tid];
#pragma unroll
        for (int o = 4; o; o >>= 1) v += __shfl_xor_sync(0xffu, v, o);
    }
    return v;   // valid on tid 0
}

#if HAS_TCGEN05
__device__ __forceinline__ uint32_t elect_one_pred() {
    uint32_t pred;
    asm volatile("{\n\t.reg .pred p;\n\telect.sync _|p, 0xFFFFFFFF;\n\tselp.b32 %0, 1, 0, p;\n\t}"
                 : "=r"(pred));
    return pred;
}

static constexpr uint64_t SMEM_DESC_BASE_SW128 =
    (uint64_t(2) << 61) | (uint64_t(1) << 46) | (uint64_t(64) << 32) | (uint64_t(1) << 16);
#define MAKE_SMEM_DESC(base_addr) \
    (SMEM_DESC_BASE_SW128 | ((uint64_t)((base_addr) >> 4) & 0x3FFF))

#define TCGEN05_ALLOC(smem_result_addr, nCols) \
    asm volatile("tcgen05.alloc.cta_group::1.sync.aligned.shared::cta.b32 [%0], %1;" \
        :: "r"((uint32_t)(smem_result_addr)), "r"((uint32_t)(nCols)) : "memory")
#define TCGEN05_DEALLOC(tmem_addr, nCols) \
    asm volatile("tcgen05.dealloc.cta_group::1.sync.aligned.b32 %0, %1;" \
        :: "r"(tmem_addr), "r"((uint32_t)(nCols)))
#define TCGEN05_RELINQUISH() \
    asm volatile("tcgen05.relinquish_alloc_permit.cta_group::1.sync.aligned;")
#define TCGEN05_COMMIT(mbar_smem_addr) \
    asm volatile("tcgen05.commit.cta_group::1.mbarrier::arrive::one.shared::cluster.b64 [%0];" \
        :: "r"((uint32_t)(mbar_smem_addr)) : "memory")
#define TCGEN05_FENCE_AFTER() \
    asm volatile("tcgen05.fence::after_thread_sync;" ::: "memory")
#define TCGEN05_WAIT_LD() \
    asm volatile("tcgen05.wait::ld.sync.aligned;" ::: "memory")
#define FENCE_PROXY_ASYNC_SHARED_CTA() \
    asm volatile("fence.proxy.async.shared::cta;" ::: "memory")
#define MBARRIER_INIT(mbar, count) \
    asm volatile("mbarrier.init.shared.b64 [%0], %1;" \
        :: "r"((uint32_t)(mbar)), "r"((uint32_t)(count)) : "memory")
#define MBARRIER_INVAL(mbar) \
    asm volatile("mbarrier.inval.shared.b64 [%0];" :: "r"((uint32_t)(mbar)) : "memory")
#define MBARRIER_WAIT_PARITY(mbar_smem_addr, phase_parity) do { \
    uint32_t _mbar = (uint32_t)(mbar_smem_addr); \
    uint32_t _parity = (uint32_t)(phase_parity); \
    uint32_t _done; \
    asm volatile("{\n\t.reg .pred p;\n\t" \
        "mbarrier.try_wait.parity.acquire.cta.shared::cta.b64 p, [%1], %2;\n\t" \
        "selp.b32 %0, 1, 0, p;\n\t}" \
        : "=r"(_done) : "r"(_mbar), "r"(_parity) : "memory"); \
    if (!_done) { \
        asm volatile("{\n\t.reg .pred P1;\n\t" \
            "WAIT_LOOP_%=:\n\t" \
            "mbarrier.try_wait.parity.acquire.cta.shared::cta.b64 P1, [%0], %1, 0x989680;\n\t" \
            "@P1 bra.uni WAIT_DONE_%=;\n\t" \
            "bra.uni WAIT_LOOP_%=;\n\t" \
            "WAIT_DONE_%=:\n\t}" \
            :: "r"(_mbar), "r"(_parity) : "memory"); \
    } \
} while(0)

#define TCGEN05_LD_32X32B_X32(r, tmem_addr) \
    asm volatile("tcgen05.ld.sync.aligned.32x32b.x32.b32 " \
        "{%0, %1, %2, %3, %4, %5, %6, %7, %8, %9, %10, %11, %12, %13, %14, %15, " \
        " %16, %17, %18, %19, %20, %21, %22, %23, %24, %25, %26, %27, %28, %29, %30, %31}, [%32];" \
        : "=r"((r)[0]),  "=r"((r)[1]),  "=r"((r)[2]),  "=r"((r)[3]), \
          "=r"((r)[4]),  "=r"((r)[5]),  "=r"((r)[6]),  "=r"((r)[7]), \
          "=r"((r)[8]),  "=r"((r)[9]),  "=r"((r)[10]), "=r"((r)[11]), \
          "=r"((r)[12]), "=r"((r)[13]), "=r"((r)[14]), "=r"((r)[15]), \
          "=r"((r)[16]), "=r"((r)[17]), "=r"((r)[18]), "=r"((r)[19]), \
          "=r"((r)[20]), "=r"((r)[21]), "=r"((r)[22]), "=r"((r)[23]), \
          "=r"((r)[24]), "=r"((r)[25]), "=r"((r)[26]), "=r"((r)[27]), \
          "=r"((r)[28]), "=r"((r)[29]), "=r"((r)[30]), "=r"((r)[31]) \
        : "r"(tmem_addr))

__device__ __forceinline__ void mma_f16_ss(uint32_t d_tmem, uint64_t a_desc, uint64_t b_desc,
                                           uint32_t idesc, uint32_t enable_d) {
    asm volatile(
        "{\n\t.reg .pred p;\n\t"
        "setp.ne.u32 p, %4, 0;\n\t"
        "tcgen05.mma.cta_group::1.kind::f16 [%0], %1, %2, %3, {%5, %5, %5, %5}, p;\n\t}"
        :: "r"(d_tmem), "l"(a_desc), "l"(b_desc), "r"(idesc), "r"(enable_d), "r"(0u)
        : "memory");
}

static constexpr uint32_t GEMM_IDESC =
    (1u << 4) | (1u << 7) | (1u << 10) | ((128u / 8u) << 17) | ((128u / 16u) << 24);
#endif  // HAS_TCGEN05

// ---------------- convert helpers ----------------
__device__ __forceinline__ void split_bf16(float x, __nv_bfloat16& h, __nv_bfloat16& l) {
    h = __float2bfloat16(x);
    l = __float2bfloat16(x - __bfloat162float(h));
}
__device__ __forceinline__ float bfu2f(uint32_t u16) {
    return __bfloat162float(__ushort_as_bfloat16((unsigned short)u16));
}

__global__ void convert_w(const float* __restrict__ Wq, const float* __restrict__ Wk,
                          const float* __restrict__ Wv,
                          __nv_bfloat16* __restrict__ aq_hi, __nv_bfloat16* __restrict__ aq_lo,
                          __nv_bfloat16* __restrict__ akv_hi, __nv_bfloat16* __restrict__ akv_lo,
                          float* __restrict__ lg, float* __restrict__ kn2,
                          float* __restrict__ qn2)
{
    if (blockIdx.x == 0) {
        for (int i = threadIdx.x; i < BATCH*HEADS*CPH*CPH; i += 256) lg[i] = 0.f;
        for (int i = threadIdx.x; i < BATCH*CHN; i += 256) { kn2[i] = 0.f; qn2[i] = 0.f; }
    }
    int i = blockIdx.x * 256 + threadIdx.x;
    __nv_bfloat16 h, l;
    if (i < 65536) {
        split_bf16(Wq[i], h, l); aq_hi[i] = h; aq_lo[i] = l;
    } else if (i < 131072) {
        int j = i - 65536;
        split_bf16(Wk[j], h, l); akv_hi[j] = h; akv_lo[j] = l;
    } else {
        int j = i - 131072;
        split_bf16(Wv[j], h, l); akv_hi[65536 + j] = h; akv_lo[65536 + j] = l;
    }
}

// ---------------- X convert: [B,C,N] f32 -> [B,N,C] bf16 hi/lo ----------------
__global__ __launch_bounds__(256) void convert_x(const float* __restrict__ X,
                                                 __nv_bfloat16* __restrict__ Th,
                                                 __nv_bfloat16* __restrict__ Tl, int N)
{
    __shared__ float s[64][33];
    int b = blockIdx.z, c0 = blockIdx.y * 64, n0 = blockIdx.x * 32;
    const float* Xb = X + (size_t)b * 256 * N;
    int lane = threadIdx.x & 31, w = threadIdx.x >> 5;
#pragma unroll
    for (int i = 0; i < 8; i++) {
        int c = w + i * 8;
        s[c][lane] = Xb[(size_t)(c0 + c) * N + n0 + lane];
    }
    __syncthreads();
    uint32_t* TH = (uint32_t*)(Th + (size_t)b * N * 256);
    uint32_t* TL = (uint32_t*)(Tl + (size_t)b * N * 256);
#pragma unroll
    for (int i = 0; i < 4; i++) {
        int n = w + i * 8;
        float x0 = s[2 * lane][n], x1 = s[2 * lane + 1][n];
        __nv_bfloat16 h0, l0, h1, l1;
        split_bf16(x0, h0, l0); split_bf16(x1, h1, l1);
        uint32_t hp = ((uint32_t)__bfloat16_as_ushort(h1) << 16) | __bfloat16_as_ushort(h0);
        uint32_t lp = ((uint32_t)__bfloat16_as_ushort(l1) << 16) | __bfloat16_as_ushort(l0);
        size_t idx = (size_t)(n0 + n) * 128 + (c0 >> 1) + lane;
        TH[idx] = hp; TL[idx] = lp;
    }
}

// ---------------- GEMM ----------------
#if HAS_TCGEN05
__device__ __forceinline__ void load_tile_sw(const __nv_bfloat16* __restrict__ src,
                                             char* __restrict__ dst, int tid)
{
#pragma unroll
    for (int it = 0; it < 4; it++) {
        int i = tid + it * 256;
        int row = i >> 3, seg = i & 7;
        uint4 v = *(const uint4*)(src + (size_t)row * 256 + seg * 8);
        uint32_t off = (uint32_t)(row * 128 + seg * 16);
        *(uint4*)(dst + SW128(off)) = v;
    }
}
#endif

__global__ __launch_bounds__(256, 1) void gemm_tc(
    const __nv_bfloat16* __restrict__ Ahi, const __nv_bfloat16* __restrict__ Alo,
    const __nv_bfloat16* __restrict__ Bhi, const __nv_bfloat16* __restrict__ Blo,
    float* __restrict__ Y, int Ntot)
{
    extern __shared__ char dsm[];
    int tid = threadIdx.x;
    int m0 = blockIdx.y * 128, n0 = blockIdx.x * 128, b = blockIdx.z;
    int Mtot = gridDim.y * 128;
    const __nv_bfloat16* Bh = Bhi + (size_t)b * Ntot * 256;
    const __nv_bfloat16* Bl = Blo + (size_t)b * Ntot * 256;
    float* Yb = Y + (size_t)b * Mtot * Ntot;

#if HAS_TCGEN05
    __shared__ uint32_t s_tmem[1];
    __shared__ unsigned long long s_mbar[2];
    uint32_t dsm_u = smem_to_u32(dsm);
    uint32_t sb = (dsm_u + 1023) & ~1023u;
    char* sbp = dsm + (sb - dsm_u);
    uint32_t mb[2] = { smem_to_u32(&s_mbar[0]), smem_to_u32(&s_mbar[1]) };
    int wid = tid >> 5;

    if (wid == 0) TCGEN05_ALLOC(smem_to_u32(s_tmem), 128);
    if (tid == 0) { MBARRIER_INIT(mb[0], 1); MBARRIER_INIT(mb[1], 1); }
    __syncthreads();
    uint32_t tbase = s_tmem[0];

    for (int ch = 0; ch < 4; ch++) {
        int buf = ch & 1;
        char* bp = sbp + buf * 65536;
        if (ch >= 2) MBARRIER_WAIT_PARITY(mb[buf], 0);
        int c0 = ch * 64;
        load_tile_sw(Ahi + (size_t)m0 * 256 + c0, bp,          tid);
        load_tile_sw(Alo + (size_t)m0 * 256 + c0, bp + 16384,  tid);
        load_tile_sw(Bh  + (size_t)n0 * 256 + c0, bp + 32768,  tid);
        load_tile_sw(Bl  + (size_t)n0 * 256 + c0, bp + 49152,  tid);
        FENCE_PROXY_ASYNC_SHARED_CTA();
        __syncthreads();
        if (wid == 0) {
            if (elect_one_pred()) {
                uint32_t base = sb + buf * 65536;
                uint64_t dah = MAKE_SMEM_DESC(base);
                uint64_t dal = MAKE_SMEM_DESC(base + 16384);
                uint64_t dbh = MAKE_SMEM_DESC(base + 32768);
                uint64_t dbl = MAKE_SMEM_DESC(base + 49152);
#pragma unroll
                for (int k = 0; k < 4; k++)
                    mma_f16_ss(tbase, dah + 2 * k, dbh + 2 * k, GEMM_IDESC,
                               (ch > 0 || k > 0) ? 1u : 0u);
#pragma unroll
                for (int k = 0; k < 4; k++)
                    mma_f16_ss(tbase, dah + 2 * k, dbl + 2 * k, GEMM_IDESC, 1u);
#pragma unroll
                for (int k = 0; k < 4; k++)
                    mma_f16_ss(tbase, dal + 2 * k, dbh + 2 * k, GEMM_IDESC, 1u);
                TCGEN05_COMMIT(mb[buf]);
            }
        }
    }

    MBARRIER_WAIT_PARITY(mb[0], 1);
    MBARRIER_WAIT_PARITY(mb[1], 1);
    TCGEN05_FENCE_AFTER();

    float* Ds = (float*)sbp;
    uint32_t woff = (uint32_t)(wid & 3) << 21;
    int cb0 = (wid >= 4) ? 2 : 0;
    int lane = tid & 31;
    int row = (wid & 3) * 32 + lane;
    uint32_t regs[32];
#pragma unroll
    for (int j = 0; j < 2; j++) {
        int cb = cb0 + j;
        TCGEN05_LD_32X32B_X32(regs, tbase + cb * 32 + woff);
        TCGEN05_WAIT_LD();
#pragma unroll
        for (int c = 0; c < 32; c++)
            Ds[row * 132 + cb * 32 + c] = __uint_as_float(regs[c]);
    }
    __syncthreads();
#pragma unroll
    for (int it = 0; it < 16; it++) {
        int i = tid + it * 256;
        int r = i >> 5, c4 = (i & 31) * 4;
        float4 v = *(float4*)&Ds[r * 132 + c4];
        *(float4*)&Yb[(size_t)(m0 + r) * Ntot + n0 + c4] = v;
    }
    __syncthreads();
    if (tid == 0) { MBARRIER_INVAL(mb[0]); MBARRIER_INVAL(mb[1]); }
    if (wid == 0) { TCGEN05_RELINQUISH(); TCGEN05_DEALLOC(tbase, 128); }

#else  // SIMT fallback
    float* As = (float*)dsm;
    float* Bs = As + 8 * 128;
    int ty = tid >> 4, tx = tid & 15;
    int r = tid >> 1, kq = (tid & 1) * 4;

    float acc[8][8];
#pragma unroll
    for (int i = 0; i < 8; i++)
#pragma unroll
        for (int j = 0; j < 8; j++) acc[i][j] = 0.f;

    for (int c0 = 0; c0 < 256; c0 += 8) {
        {
            size_t off = (size_t)(m0 + r) * 256 + c0 + kq;
            uint2 vh = *(const uint2*)(Ahi + off);
            uint2 vl = *(const uint2*)(Alo + off);
            As[(kq + 0) * 128 + r] = bfu2f(vh.x & 0xffff)  + bfu2f(vl.x & 0xffff);
            As[(kq + 1) * 128 + r] = bfu2f(vh.x >> 16)     + bfu2f(vl.x >> 16);
            As[(kq + 2) * 128 + r] = bfu2f(vh.y & 0xffff)  + bfu2f(vl.y & 0xffff);
            As[(kq + 3) * 128 + r] = bfu2f(vh.y >> 16)     + bfu2f(vl.y >> 16);
            size_t offb = (size_t)(n0 + r) * 256 + c0 + kq;
            uint2 wh = *(const uint2*)(Bh + offb);
            uint2 wl = *(const uint2*)(Bl + offb);
            Bs[(kq + 0) * 128 + r] = bfu2f(wh.x & 0xffff)  + bfu2f(wl.x & 0xffff);
            Bs[(kq + 1) * 128 + r] = bfu2f(wh.x >> 16)     + bfu2f(wl.x >> 16);
            Bs[(kq + 2) * 128 + r] = bfu2f(wh.y & 0xffff)  + bfu2f(wl.y & 0xffff);
            Bs[(kq + 3) * 128 + r] = bfu2f(wh.y >> 16)     + bfu2f(wl.y >> 16);
        }
        __syncthreads();
#pragma unroll
        for (int kk = 0; kk < 8; kk++) {
            float a[8], bb[8];
            *(float4*)&a[0]  = *(const float4*)&As[kk * 128 + ty * 8];
            *(float4*)&a[4]  = *(const float4*)&As[kk * 128 + ty * 8 + 4];
            *(float4*)&bb[0] = *(const float4*)&Bs[kk * 128 + tx * 8];
            *(float4*)&bb[4] = *(const float4*)&Bs[kk * 128 + tx * 8 + 4];
#pragma unroll
            for (int i = 0; i < 8; i++)
#pragma unroll
                for (int j = 0; j < 8; j++)
                    acc[i][j] = fmaf(a[i], bb[j], acc[i][j]);
        }
        __syncthreads();
    }
#pragma unroll
    for (int i = 0; i < 8; i++) {
        float* yp = Yb + (size_t)(m0 + ty * 8 + i) * Ntot + n0 + tx * 8;
        *(float4*)yp       = make_float4(acc[i][0], acc[i][1], acc[i][2], acc[i][3]);
        *(float4*)(yp + 4) = make_float4(acc[i][4], acc[i][5], acc[i][6], acc[i][7]);
    }
#endif
}

// ---------------- plain templated WTConv (Haar, ks=3), 32-row tiles, float4 subbands ----------------
template<int W>
__global__ __launch_bounds__(256, 4) void wtconv_t(
    const float* __restrict__ X, float* __restrict__ Y,
    const float* __restrict__ base_w, const float* __restrict__ base_s,
    const float* __restrict__ wav_w,  const float* __restrict__ wav_s,
    int H, int cs_in)
{
    constexpr int LW = W + 4;
    constexpr int SWc = (W >> 1) + 2;
    constexpr int Wh = W >> 1;
    __shared__ float ins[36][LW];
    __shared__ float4 sub4[18][SWc];
    __shared__ float swav[4][9];
    __shared__ float sbw[9];
    __shared__ float swsc[4];
    __shared__ float sbs;

    int bc = blockIdx.x;
    int b  = bc >> 8;
    int c  = bc & 255;
    int y0 = blockIdx.y * 32;
    const float* Xc = X + ((size_t)b * cs_in + c) * H * W;
    float*       Yc = Y + (size_t)bc * H * W;
    int tid = threadIdx.x;

    if (tid < 36) {
        int f = tid / 9, i = tid - f * 9;
        swav[f][i] = wav_w[(size_t)(c * 4 + f) * 9 + i];
    } else if (tid < 45) {
        sbw[tid - 36] = base_w[(size_t)c * 9 + tid - 36];
    } else if (tid < 49) {
        swsc[tid - 45] = wav_s[c * 4 + tid - 45];
    } else if (tid == 49) {
        sbs = base_s[c];
    }

    for (int idx = tid; idx < 36 * LW; idx += 256) {
        int ly = idx / LW, lx = idx - ly * LW;
        int gy = y0 + ly - 2, gx = lx - 2;
        float v = 0.f;
        if (gy >= 0 && gy < H && gx >= 0 && gx < W) v = Xc[gy * W + gx];
        ins[ly][lx] = v;
    }
    __syncthreads();

    for (int idx = tid; idx < 18 * SWc; idx += 256) {
        int sy = idx / SWc, sx = idx - sy * SWc;
        float a = ins[2 * sy][2 * sx],     bq = ins[2 * sy][2 * sx + 1];
        float d = ins[2 * sy + 1][2 * sx], e = ins[2 * sy + 1][2 * sx + 1];
        sub4[sy][sx] = make_float4(0.5f * (a + bq + d + e), 0.5f * (a + bq - d - e),
                                   0.5f * (a - bq + d - e), 0.5f * (a - bq - d + e));
    }
    __syncthreads();

    for (int idx = tid; idx < 16 * Wh; idx += 256) {
        int syi = idx / Wh, sxi = idx - syi * Wh;
        int sy = syi + 1, sx = sxi + 1;
        float r0 = 0.f, r1 = 0.f, r2 = 0.f, r3 = 0.f;
#pragma unroll
        for (int dy = 0; dy < 3; dy++)
#pragma unroll
            for (int dx = 0; dx < 3; dx++) {
                float4 s = sub4[sy - 1 + dy][sx - 1 + dx];
                int kk = dy * 3 + dx;
                r0 = fmaf(swav[0][kk], s.x, r0);
                r1 = fmaf(swav[1][kk], s.y, r1);
                r2 = fmaf(swav[2][kk], s.z, r2);
                r3 = fmaf(swav[3][kk], s.w, r3);
            }
        r0 *= swsc[0]; r1 *= swsc[1]; r2 *= swsc[2]; r3 *= swsc[3];
        float y00 = 0.5f * (r0 + r1 + r2 + r3);
        float y01 = 0.5f * (r0 + r1 - r2 - r3);
        float y10 = 0.5f * (r0 - r1 + r2 - r3);
        float y11 = 0.5f * (r0 - r1 - r2 + r3);

        float base[2][2];
#pragma unroll
        for (int p = 0; p < 2; p++)
#pragma unroll
            for (int q = 0; q < 2; q++) {
                float s = 0.f;
#pragma unroll
                for (int dy = 0; dy < 3; dy++)
#pragma unroll
                    for (int dx = 0; dx < 3; dx++)
                        s = fmaf(sbw[dy * 3 + dx],
                                 ins[2 * sy + p - 1 + dy][2 * sx + q - 1 + dx], s);
                base[p][q] = s * sbs;
            }
        int gy = y0 + 2 * syi, gx = 2 * sxi;
        Yc[(gy + 0) * W + gx + 0] = base[0][0] + y00;
        Yc[(gy + 0) * W + gx + 1] = base[0][1] + y01;
        Yc[(gy + 1) * W + gx + 0] = base[1][0] + y10;
        Yc[(gy + 1) * W + gx + 1] = base[1][1] + y11;
    }
}

// ---------------- fused wtconv(k) + transposed-bilinear downsample + ||k||², float4 subbands ----------------
#define KD_SMEM ((40*132 + 4*20*66 + 36*130) * 4)

__global__ __launch_bounds__(256, 3) void wtconv_k_down(
    const float* __restrict__ X, float* __restrict__ kdn,
    const float* __restrict__ base_w, const float* __restrict__ base_s,
    const float* __restrict__ wav_w,  const float* __restrict__ wav_s,
    float* __restrict__ kn2)
{
    extern __shared__ float sm[];
    float*  ins  = sm;                          // [40][132]
    float4* sub4 = (float4*)(ins + 40 * 132);   // [20*66] interleaved subbands
    float*  outb = ins + 40 * 132 + 4 * 20 * 66; // [36][130]
    __shared__ float swav[4][9];
    __shared__ float sbw[9];
    __shared__ float swsc[4];
    __shared__ float sbs;
    __shared__ float red8[8];

    int bc = blockIdx.x;
    int b  = bc >> 8;
    int c  = bc & 255;
    int by = blockIdx.y;
    int y0 = by * 32;
    const float* Xc = X + ((size_t)b * 512 + c) * (size_t)NK;
    int tid = threadIdx.x;

    if (tid < 36) {
        int f = tid / 9, i = tid - f * 9;
        swav[f][i] = wav_w[(size_t)(c * 4 + f) * 9 + i];
    } else if (tid < 45) {
        sbw[tid - 36] = base_w[(size_t)c * 9 + tid - 36];
    } else if (tid < 49) {
        swsc[tid - 45] = wav_s[c * 4 + tid - 45];
    } else if (tid == 49) {
        sbs = base_s[c];
    }

    for (int idx = tid; idx < 40 * 132; idx += 256) {
        int ly = idx / 132, lx = idx - ly * 132;
        int gy = y0 + ly - 4, gx = lx - 2;
        float v = 0.f;
        if (gy >= 0 && gy < 128 && gx >= 0 && gx < 128) v = Xc[gy * 128 + gx];
        ins[idx] = v;
    }
    __syncthreads();

    for (int idx = tid; idx < 20 * 66; idx += 256) {
        int sy = idx / 66, sx = idx - sy * 66;
        const float* r0p = ins + (2 * sy) * 132 + 2 * sx;
        float a = r0p[0], bq = r0p[1], d = r0p[132], e = r0p[133];
        sub4[idx] = make_float4(0.5f * (a + bq + d + e), 0.5f * (a + bq - d - e),
                                0.5f * (a - bq + d - e), 0.5f * (a - bq - d + e));
    }
    __syncthreads();

    for (int idx = tid; idx < 18 * 64; idx += 256) {
        int syo = idx >> 6, j = idx & 63;
        int sy = syo + 1, sx = j + 1;
        float r0 = 0.f, r1 = 0.f, r2 = 0.f, r3 = 0.f;
#pragma unroll
        for (int dy = 0; dy < 3; dy++)
#pragma unroll
            for (int dx = 0; dx < 3; dx++) {
                float4 s = sub4[(sy - 1 + dy) * 66 + sx - 1 + dx];
                int kk = dy * 3 + dx;
                r0 = fmaf(swav[0][kk], s.x, r0);
                r1 = fmaf(swav[1][kk], s.y, r1);
                r2 = fmaf(swav[2][kk], s.z, r2);
                r3 = fmaf(swav[3][kk], s.w, r3);
            }
        r0 *= swsc[0]; r1 *= swsc[1]; r2 *= swsc[2]; r3 *= swsc[3];
        float y00 = 0.5f * (r0 + r1 + r2 + r3);
        float y01 = 0.5f * (r0 + r1 - r2 - r3);
        float y10 = 0.5f * (r0 - r1 + r2 - r3);
        float y11 = 0.5f * (r0 - r1 - r2 + r3);

        float base[2][2];
#pragma unroll
        for (int p = 0; p < 2; p++)
#pragma unroll
            for (int q = 0; q < 2; q++) {
                float s = 0.f;
#pragma unroll
                for (int dy = 0; dy < 3; dy++)
#pragma unroll
                    for (int dx = 0; dx < 3; dx++)
                        s = fmaf(sbw[dy * 3 + dx],
                                 ins[(2 * syo + 1 + p + dy) * 132 + 2 * j + 1 + q + dx], s);
                base[p][q] = s * sbs;
            }
        outb[(2 * syo) * 130 + 2 * j]         = base[0][0] + y00;
        outb[(2 * syo) * 130 + 2 * j + 1]     = base[0][1] + y01;
        outb[(2 * syo + 1) * 130 + 2 * j]     = base[1][0] + y10;
        outb[(2 * syo + 1) * 130 + 2 * j + 1] = base[1][1] + y11;
    }
    __syncthreads();

    float sumsq = 0.f;
    for (int idx = tid; idx < 32 * 128; idx += 256) {
        int lr = (idx >> 7) + 2, lc = idx & 127;
        float v = outb[lr * 130 + lc];
        sumsq += v * v;
    }

    for (int idx = tid; idx < 16 * 64; idx += 256) {
        int jj = idx >> 6, jx = idx & 63;
        int jy = 16 * by + jj;
        int lyt[4]; float wyt[4]; int cy = 0;
        if (jy > 0)  { lyt[cy] = 2*jj+1; wyt[cy++] = 0.25f; }
        lyt[cy] = 2*jj+2; wyt[cy++] = (jy == 0)  ? 1.0f : 0.75f;
        lyt[cy] = 2*jj+3; wyt[cy++] = (jy == 63) ? 1.0f : 0.75f;
        if (jy < 63) { lyt[cy] = 2*jj+4; wyt[cy++] = 0.25f; }
        int lxt[4]; float wxt[4]; int cx = 0;
        if (jx > 0)  { lxt[cx] = 2*jx-1; wxt[cx++] = 0.25f; }
        lxt[cx] = 2*jx;   wxt[cx++] = (jx == 0)  ? 1.0f : 0.75f;
        lxt[cx] = 2*jx+1; wxt[cx++] = (jx == 63) ? 1.0f : 0.75f;
        if (jx < 63) { lxt[cx] = 2*jx+2; wxt[cx++] = 0.25f; }
        float s = 0.f;
        for (int a = 0; a < cy; a++) {
            const float* row = outb + lyt[a] * 130;
            float rs = 0.f;
            for (int e = 0; e < cx; e++) rs = fmaf(wxt[e], row[lxt[e]], rs);
            s = fmaf(wyt[a], rs, s);
        }
        kdn[(size_t)bc * NQ + jy * 64 + jx] = s;
    }

    __syncthreads();
    float tot = block_reduce_sum(sumsq, red8, tid);
    if (tid == 0) atomicAdd(&kn2[bc], tot);
}

// ---------------- fused wtconv(q) + ||upsample(q)||² via Gram form, float4 subbands ----------------
__global__ __launch_bounds__(256, 4) void wtconv_q_norm(
    const float* __restrict__ X, float* __restrict__ Y,
    const float* __restrict__ base_w, const float* __restrict__ base_s,
    const float* __restrict__ wav_w,  const float* __restrict__ wav_s,
    float* __restrict__ qn2)
{
    __shared__ float ins[40][68];
    __shared__ float4 sub4[20][36];
    __shared__ float outb[36][66];
    __shared__ float swav[4][9];
    __shared__ float sbw[9];
    __shared__ float swsc[4];
    __shared__ float sbs;
    __shared__ float red8[8];

    int bc = blockIdx.x;
    int c  = bc & 255;
    int by = blockIdx.y;
    int y0 = by * 32;
    const float* Xc = X + (size_t)bc * NQ;
    float*       Yc = Y + (size_t)bc * NQ;
    int tid = threadIdx.x;

    if (tid < 36) {
        int f = tid / 9, i = tid - f * 9;
        swav[f][i] = wav_w[(size_t)(c * 4 + f) * 9 + i];
    } else if (tid < 45) {
        sbw[tid - 36] = base_w[(size_t)c * 9 + tid - 36];
    } else if (tid < 49) {
        swsc[tid - 45] = wav_s[c * 4 + tid - 45];
    } else if (tid == 49) {
        sbs = base_s[c];
    }

    for (int idx = tid; idx < 40 * 68; idx += 256) {
        int ly = idx / 68, lx = idx - ly * 68;
        int gy = y0 + ly - 4, gx = lx - 2;
        float v = 0.f;
        if (gy >= 0 && gy < 64 && gx >= 0 && gx < 64) v = Xc[gy * 64 + gx];
        ins[ly][lx] = v;
    }
    __syncthreads();

    for (int idx = tid; idx < 20 * 34; idx += 256) {
        int sy = idx / 34, sx = idx - sy * 34;
        float a = ins[2 * sy][2 * sx],     bq = ins[2 * sy][2 * sx + 1];
        float d = ins[2 * sy + 1][2 * sx], e = ins[2 * sy + 1][2 * sx + 1];
        sub4[sy][sx] = make_float4(0.5f * (a + bq + d + e), 0.5f * (a + bq - d - e),
                                   0.5f * (a - bq + d - e), 0.5f * (a - bq - d + e));
    }
    __syncthreads();

    for (int idx = tid; idx < 18 * 32; idx += 256) {
        int syo = idx >> 5, j = idx & 31;
        int sy = syo + 1, sx = j + 1;
        float r0 = 0.f, r1 = 0.f, r2 = 0.f, r3 = 0.f;
#pragma unroll
        for (int dy = 0; dy < 3; dy++)
#pragma unroll
            for (int dx = 0; dx < 3; dx++) {
                float4 s = sub4[sy - 1 + dy][sx - 1 + dx];
                int kk = dy * 3 + dx;
                r0 = fmaf(swav[0][kk], s.x, r0);
                r1 = fmaf(swav[1][kk], s.y, r1);
                r2 = fmaf(swav[2][kk], s.z, r2);
                r3 = fmaf(swav[3][kk], s.w, r3);
            }
        r0 *= swsc[0]; r1 *= swsc[1]; r2 *= swsc[2]; r3 *= swsc[3];
        float y00 = 0.5f * (r0 + r1 + r2 + r3);
        float y01 = 0.5f * (r0 + r1 - r2 - r3);
        float y10 = 0.5f * (r0 - r1 + r2 - r3);
        float y11 = 0.5f * (r0 - r1 - r2 + r3);

        float base[2][2];
#pragma unroll
        for (int p = 0; p < 2; p++)
#pragma unroll
            for (int q = 0; q < 2; q++) {
                float s = 0.f;
#pragma unroll
                for (int dy = 0; dy < 3; dy++)
#pragma unroll
                    for (int dx = 0; dx < 3; dx++)
                        s = fmaf(sbw[dy * 3 + dx],
                                 ins[2 * syo + 1 + p + dy][2 * j + 1 + q + dx], s);
                base[p][q] = s * sbs;
            }
        float o00 = base[0][0] + y00, o01 = base[0][1] + y01;
        float o10 = base[1][0] + y10, o11 = base[1][1] + y11;
        outb[2 * syo][2 * j]         = o00;
        outb[2 * syo][2 * j + 1]     = o01;
        outb[2 * syo + 1][2 * j]     = o10;
        outb[2 * syo + 1][2 * j + 1] = o11;
        if (syo >= 1 && syo <= 16) {
            int gy = y0 - 2 + 2 * syo;
            Yc[(gy + 0) * 64 + 2 * j]     = o00;
            Yc[(gy + 0) * 64 + 2 * j + 1] = o01;
            Yc[(gy + 1) * 64 + 2 * j]     = o10;
            Yc[(gy + 1) * 64 + 2 * j + 1] = o11;
        }
    }
    __syncthreads();

    // Gram quadratic form over owned rows (global y0..y0+31, local 2..33)
    float sum = 0.f;
    for (int idx = tid; idx < 32 * 64; idx += 256) {
        int yl = idx >> 6, x = idx & 63;
        int yg = y0 + yl;
        int ly = yl + 2;
        float dyc = (yg == 0 || yg == 63) ? 1.625f : 1.25f;
        float dxc = (x == 0 || x == 63) ? 1.625f : 1.25f;
        float ql = (x > 0)  ? 0.375f : 0.f;
        float qr = (x < 63) ? 0.375f : 0.f;

        const float* rm = &outb[ly - 1][x];
        const float* rc = &outb[ly][x];
        const float* rp = &outb[ly + 1][x];
        float um = ql * rm[-1] + dxc * rm[0] + qr * rm[1];
        float uc = ql * rc[-1] + dxc * rc[0] + qr * rc[1];
        float up = ql * rp[-1] + dxc * rp[0] + qr * rp[1];

        float gm = (yg > 0)  ? 0.375f : 0.f;
        float gp = (yg < 63) ? 0.375f : 0.f;
        sum += rc[0] * (gm * um + dyc * uc + gp * up);
    }
    float tot = block_reduce_sum(sum, red8, tid);
    if (tid == 0) atomicAdd(&qn2[bc], tot);
}

// ---------------- attention logits ----------------
__global__ __launch_bounds__(256) void attn_partial(
    const float* __restrict__ qp, const float* __restrict__ kp,
    float* __restrict__ logits, int N)
{
    __shared__ float qsT[64][33];
    __shared__ float ksT[64][33];
    int bh = blockIdx.y;
    int n0 = blockIdx.x * 512;
    const float* q = qp + (size_t)bh * 32 * N + n0;
    const float* k = kp + (size_t)bh * 32 * N + n0;
    int tid = threadIdx.x;
    int i0 = (tid & 7) * 4, j0 = ((tid >> 3) & 7) * 4, ns = tid >> 6;

    float acc[4][4];
#pragma unroll
    for (int i = 0; i < 4; i++)
#pragma unroll
        for (int j = 0; j < 4; j++) acc[i][j] = 0.f;

    for (int nc = 0; nc < 512; nc += 64) {
        for (int l = tid; l < 512; l += 256) {
            int row = l >> 4, col4 = (l & 15) * 4;
            float4 a = *(const float4*)(q + (size_t)row * N + nc + col4);
            float4 b = *(const float4*)(k + (size_t)row * N + nc + col4);
            qsT[col4 + 0][row] = a.x; qsT[col4 + 1][row] = a.y;
            qsT[col4 + 2][row] = a.z; qsT[col4 + 3][row] = a.w;
            ksT[col4 + 0][row] = b.x; ksT[col4 + 1][row] = b.y;
            ksT[col4 + 2][row] = b.z; ksT[col4 + 3][row] = b.w;
        }
        __syncthreads();
        for (int nn = ns; nn < 64; nn += 4) {
            float qv[4], kv[4];
#pragma unroll
            for (int m = 0; m < 4; m++) { qv[m] = qsT[nn][i0 + m]; kv[m] = ksT[nn][j0 + m]; }
#pragma unroll
            for (int i = 0; i < 4; i++)
#pragma unroll
                for (int j = 0; j < 4; j++)
                    acc[i][j] = fmaf(qv[i], kv[j], acc[i][j]);
        }
        __syncthreads();
    }
    float* L = logits + (size_t)bh * 1024;
#pragma unroll
    for (int i = 0; i < 4; i++)
#pragma unroll
        for (int j = 0; j < 4; j++)
            atomicAdd(&L[(i0 + i) * 32 + j0 + j], acc[i][j]);
}

// ---------------- fused softmax + (attn @ v) + proj WTConv(ks=1) -> d_out ----------------
__global__ __launch_bounds__(256) void av_proj_kernel(
    const float* __restrict__ logits, const float* __restrict__ qn2,
    const float* __restrict__ kn2, const float* __restrict__ temp,
    const float* __restrict__ v,
    const float* __restrict__ pbw, const float* __restrict__ pbs,
    const float* __restrict__ pww, const float* __restrict__ pws,
    float* __restrict__ out)
{
    __shared__ float As[32][33];
    __shared__ float2 vt[32][2][8];

    int by = blockIdx.x;
    int bh = blockIdx.y;
    int b  = bh >> 3, h = bh & 7;
    int tid = threadIdx.x;
    int i  = tid >> 3;
    int pb = tid & 7;

    for (int l = tid; l < 1024; l += 256) As[l >> 5][l & 31] = logits[(size_t)bh * 1024 + l];
    __syncthreads();

    {
        int w = tid >> 5, lane = tid & 31;
        float tmp = temp[h];
        float kvn = fmaxf(sqrtf(kn2[b * 256 + h * 32 + lane]), 1e-12f);
#pragma unroll
        for (int rr = 0; rr < 4; rr++) {
            int r = w * 4 + rr;
            float qvn = fmaxf(sqrtf(qn2[b * 256 + h * 32 + r]), 1e-12f);
            float val = As[r][lane] * tmp / (qvn * kvn);
            float m = val;
#pragma unroll
            for (int o = 16; o; o >>= 1) m = fmaxf(m, __shfl_xor_sync(0xffffffffu, m, o));
            float e = expf(val - m);
            float s = e;
#pragma unroll
            for (int o = 16; o; o >>= 1) s += __shfl_xor_sync(0xffffffffu, s, o);
            As[r][lane] = e / s;
        }
    }
    __syncthreads();

    float arow[32];
#pragma unroll
    for (int j = 0; j < 32; j++) arow[j] = As[i][j];

    int cw = h * 32 + i;
    float bw  = pbw[cw] * pbs[cw];
    float wv0 = pww[cw * 4 + 0] * pws[cw * 4 + 0];
    float wv1 = pww[cw * 4 + 1] * pws[cw * 4 + 1];
    float wv2 = pww[cw * 4 + 2] * pws[cw * 4 + 2];
    float wv3 = pww[cw * 4 + 3] * pws[cw * 4 + 3];

    const float* vb = v + (size_t)(b * 256 + h * 32) * NK;
    float* ob = out + (size_t)(b * 256 + h * 32 + i) * NK;

    int sj = tid >> 3, sr = (tid >> 2) & 1, sxq = tid & 3;

    for (int bx0 = 0; bx0 < 64; bx0 += 8) {
        __syncthreads();
        {
            float4 v4 = *(const float4*)(vb + (size_t)sj * NK + (2 * by + sr) * 128
                                         + 2 * bx0 + sxq * 4);
            vt[sj][sr][2 * sxq + 0] = make_float2(v4.x, v4.y);
            vt[sj][sr][2 * sxq + 1] = make_float2(v4.z, v4.w);
        }
        __syncthreads();

        float a00 = 0.f, a01 = 0.f, a10 = 0.f, a11 = 0.f;
#pragma unroll
        for (int j = 0; j < 32; j++) {
            float aA = arow[j];
            float2 t0 = vt[j][0][pb];
            float2 t1 = vt[j][1][pb];
            a00 = fmaf(aA, t0.x, a00); a01 = fmaf(aA, t0.y, a01);
            a10 = fmaf(aA, t1.x, a10); a11 = fmaf(aA, t1.y, a11);
        }

        float r0 = 0.5f * (a00 + a01 + a10 + a11) * wv0;
        float r1 = 0.5f * (a00 + a01 - a10 - a11) * wv1;
        float r2 = 0.5f * (a00 - a01 + a10 - a11) * wv2;
        float r3 = 0.5f * (a00 - a01 - a10 + a11) * wv3;
        float y00 = 0.5f * (r0 + r1 + r2 + r3) + a00 * bw;
        float y01 = 0.5f * (r0 + r1 - r2 - r3) + a01 * bw;
        float y10 = 0.5f * (r0 - r1 + r2 - r3) + a10 * bw;
        float y11 = 0.5f * (r0 - r1 - r2 + r3) + a11 * bw;

        int gx = 2 * (bx0 + pb);
        *(float2*)&ob[(2 * by + 0) * 128 + gx] = make_float2(y00, y01);
        *(float2*)&ob[(2 * by + 1) * 128 + gx] = make_float2(y10, y11);
    }
}

// ---------------- launch (multi-stream fork/join DAG) ----------------
#define GEMM_SMEM (1024 + 2 * 65536)

extern "C" void kernel_launch(void* const* d_in, const int* in_sizes, int n_in,
                              void* d_out, int out_size)
{
    const float* x    = (const float*)d_in[0];
    const float* cf   = (const float*)d_in[1];
    const float* Wq   = (const float*)d_in[2];
    const float* Wk   = (const float*)d_in[3];
    const float* Wv   = (const float*)d_in[4];
    const float* temp = (const float*)d_in[5];
    const float* qbw = (const float*)d_in[6];  const float* qbs = (const float*)d_in[7];
    const float* qww = (const float*)d_in[8];  const float* qws = (const float*)d_in[9];
    const float* kbw = (const float*)d_in[10]; const float* kbs = (const float*)d_in[11];
    const float* kww = (const float*)d_in[12]; const float* kws = (const float*)d_in[13];
    const float* vbw = (const float*)d_in[14]; const float* vbs = (const float*)d_in[15];
    const float* vww = (const float*)d_in[16]; const float* vws = (const float*)d_in[17];
    const float* pbw = (const float*)d_in[18]; const float* pbs = (const float*)d_in[19];
    const float* pww = (const float*)d_in[20]; const float* pws = (const float*)d_in[21];
    float* out = (float*)d_out;

    float *q, *kv, *qwt, *vwt, *kdn, *qn2, *kn2, *lg;
    __nv_bfloat16 *xt_hi, *xt_lo, *ct_hi, *ct_lo, *aq_hi, *aq_lo, *akv_hi, *akv_lo;
    cudaGetSymbolAddress((void**)&q,     g_q);
    cudaGetSymbolAddress((void**)&kv,    g_kv);
    cudaGetSymbolAddress((void**)&qwt,   g_qwt);
    cudaGetSymbolAddress((void**)&vwt,   g_vwt);
    cudaGetSymbolAddress((void**)&kdn,   g_kdn);
    cudaGetSymbolAddress((void**)&qn2,   g_qn2);
    cudaGetSymbolAddress((void**)&kn2,   g_kn2);
    cudaGetSymbolAddress((void**)&lg,    g_lg);
    cudaGetSymbolAddress((void**)&xt_hi, g_xt_hi);
    cudaGetSymbolAddress((void**)&xt_lo, g_xt_lo);
    cudaGetSymbolAddress((void**)&ct_hi, g_ct_hi);
    cudaGetSymbolAddress((void**)&ct_lo, g_ct_lo);
    cudaGetSymbolAddress((void**)&aq_hi, g_aq_hi);
    cudaGetSymbolAddress((void**)&aq_lo, g_aq_lo);
    cudaGetSymbolAddress((void**)&akv_hi, g_akv_hi);
    cudaGetSymbolAddress((void**)&akv_lo, g_akv_lo);

    cudaFuncSetAttribute(gemm_tc, cudaFuncAttributeMaxDynamicSharedMemorySize, GEMM_SMEM);
    cudaFuncSetAttribute(wtconv_k_down, cudaFuncAttributeMaxDynamicSharedMemorySize, KD_SMEM);

    static cudaStream_t s1 = nullptr, s2 = nullptr;
    static cudaEvent_t ev0 = nullptr, evW = nullptr, evE = nullptr, evF = nullptr, evH = nullptr;
    if (s1 == nullptr) {
        cudaStreamCreateWithFlags(&s1, cudaStreamNonBlocking);
        cudaStreamCreateWithFlags(&s2, cudaStreamNonBlocking);
        cudaEventCreateWithFlags(&ev0, cudaEventDisableTiming);
        cudaEventCreateWithFlags(&evW, cudaEventDisableTiming);
        cudaEventCreateWithFlags(&evE, cudaEventDisableTiming);
        cudaEventCreateWithFlags(&evF, cudaEventDisableTiming);
        cudaEventCreateWithFlags(&evH, cudaEventDisableTiming);
    }
    cudaStream_t s0 = 0;

    // fork
    cudaEventRecord(ev0, s0);
    cudaStreamWaitEvent(s1, ev0, 0);
    cudaStreamWaitEvent(s2, ev0, 0);

    // s2: weights convert + zero accumulators (off critical path)
    convert_w<<<768, 256, 0, s2>>>(Wq, Wk, Wv, aq_hi, aq_lo, akv_hi, akv_lo, lg, kn2, qn2);
    cudaEventRecord(evW, s2);

    // s1: q-path prologue
    convert_x<<<dim3(NQ / 32, 4, BATCH), 256, 0, s1>>>(x, xt_hi, xt_lo, NQ);
    cudaStreamWaitEvent(s1, evW, 0);
    gemm_tc<<<dim3(NQ / 128, 2, BATCH), 256, GEMM_SMEM, s1>>>(aq_hi, aq_lo, xt_hi, xt_lo, q, NQ);
    wtconv_q_norm<<<dim3(BATCH * CHN, 2), 256, 0, s1>>>(q, qwt, qbw, qbs, qww, qws, qn2);
    cudaEventRecord(evF, s1);

    // main: cf convert -> kv GEMM
    convert_x<<<dim3(NK / 32, 4, BATCH), 256, 0, s0>>>(cf, ct_hi, ct_lo, NK);
    cudaStreamWaitEvent(s0, evW, 0);
    gemm_tc<<<dim3(NK / 128, 4, BATCH), 256, GEMM_SMEM, s0>>>(akv_hi, akv_lo, ct_hi, ct_lo, kv, NK);
    cudaEventRecord(evE, s0);

    // s2: v wtconv (needs kv)
    cudaStreamWaitEvent(s2, evE, 0);
    wtconv_t<128><<<dim3(BATCH * CHN, 4), 256, 0, s2>>>(kv + (size_t)CHN * NK, vwt,
                                                        vbw, vbs, vww, vws, HK, 512);
    cudaEventRecord(evH, s2);

    // main: k wtconv + downsample + norm
    wtconv_k_down<<<dim3(BATCH * CHN, 4), 256, KD_SMEM, s0>>>(kv, kdn, kbw, kbs, kww, kws, kn2);

    // join q-path, attention logits
    cudaStreamWaitEvent(s0, evF, 0);
    attn_partial<<<dim3(NQ / 512, BATCH * HEADS), 256, 0, s0>>>(qwt, kdn, lg, NQ);

    // join v-path, fused softmax + av + proj
    cudaStreamWaitEvent(s0, evH, 0);
    av_proj_kernel<<<dim3(64, BATCH * HEADS), 256, 0, s0>>>(lg, qn2, kn2, temp, vwt,
                                                            pbw, pbs, pww, pws, out);
}

// round 14
// speedup vs baseline: 1.2690x; 1.0268x over previous
#include <cuda_runtime.h>
#include <cuda_bf16.h>
#include <math.h>
#include <stdint.h>

// ---------------- arch feature gate (tcgen05 is an "a"-feature) ----------------
#if defined(__CUDA_ARCH_FEAT_SM103_ALL) || defined(__CUDA_ARCH_FEAT_SM100_ALL) || \
    defined(__CUDA_ARCH_FEAT_SM101_ALL) || \
    (defined(__CUDA_ARCH_SPECIFIC__) && (__CUDA_ARCH_SPECIFIC__ >= 1000))
#define HAS_TCGEN05 1
#else
#define HAS_TCGEN05 0
#endif

// ---------------- problem constants ----------------
#define BATCH 2
#define CHN   256
#define HQ    64
#define WQ    64
#define HK    128
#define WK    128
#define NQ    (HQ*WQ)     // 4096
#define NK    (HK*WK)     // 16384
#define HEADS 8
#define CPH   32

// ---------------- scratch (device globals) ----------------
static __device__ float g_q  [BATCH*CHN*NQ];
static __device__ float g_kv [BATCH*2*CHN*NK];
static __device__ float g_qwt[BATCH*CHN*NQ];
static __device__ float g_vwt[BATCH*CHN*NK];
static __device__ float g_kdn[BATCH*CHN*NQ];
static __device__ float g_qn2[BATCH*CHN];
static __device__ float g_kn2[BATCH*CHN];
static __device__ float g_lg [BATCH*HEADS*CPH*CPH];
static __device__ __nv_bfloat16 g_xt_hi[BATCH*NQ*CHN];
static __device__ __nv_bfloat16 g_xt_lo[BATCH*NQ*CHN];
static __device__ __nv_bfloat16 g_ct_hi[BATCH*NK*CHN];
static __device__ __nv_bfloat16 g_ct_lo[BATCH*NK*CHN];
static __device__ __nv_bfloat16 g_aq_hi[CHN*CHN];
static __device__ __nv_bfloat16 g_aq_lo[CHN*CHN];
static __device__ __nv_bfloat16 g_akv_hi[2*CHN*CHN];
static __device__ __nv_bfloat16 g_akv_lo[2*CHN*CHN];

// ---------------- PTX helpers ----------------
__device__ __forceinline__ uint32_t smem_to_u32(const void* p) {
    uint32_t a;
    asm("{ .reg .u64 t; cvta.to.shared.u64 t, %1; cvt.u32.u64 %0, t; }" : "=r"(a) : "l"(p));
    return a;
}
#define SW128(o) ((o) ^ (((o) >> 3) & 0x70))

// warp-shuffle block reduction: 256 threads -> lane-0 of warp 0 holds sum
__device__ __forceinline__ float block_reduce_sum(float v, float* red8, int tid) {
#pragma unroll
    for (int o = 16; o; o >>= 1) v += __shfl_xor_sync(0xffffffffu, v, o);
    if ((tid & 31) == 0) red8[tid >> 5] = v;
    __syncthreads();
    if (tid < 8) {
        v = red8[tid];
#pragma unroll
        for (int o = 4; o; o >>= 1) v += __shfl_xor_sync(0xffu, v, o);
    }
    return v;   // valid on tid 0
}

#if HAS_TCGEN05
__device__ __forceinline__ uint32_t elect_one_pred() {
    uint32_t pred;
    asm volatile("{\n\t.reg .pred p;\n\telect.sync _|p, 0xFFFFFFFF;\n\tselp.b32 %0, 1, 0, p;\n\t}"
                 : "=r"(pred));
    return pred;
}

static constexpr uint64_t SMEM_DESC_BASE_SW128 =
    (uint64_t(2) << 61) | (uint64_t(1) << 46) | (uint64_t(64) << 32) | (uint64_t(1) << 16);
#define MAKE_SMEM_DESC(base_addr) \
    (SMEM_DESC_BASE_SW128 | ((uint64_t)((base_addr) >> 4) & 0x3FFF))

#define TCGEN05_ALLOC(smem_result_addr, nCols) \
    asm volatile("tcgen05.alloc.cta_group::1.sync.aligned.shared::cta.b32 [%0], %1;" \
        :: "r"((uint32_t)(smem_result_addr)), "r"((uint32_t)(nCols)) : "memory")
#define TCGEN05_DEALLOC(tmem_addr, nCols) \
    asm volatile("tcgen05.dealloc.cta_group::1.sync.aligned.b32 %0, %1;" \
        :: "r"(tmem_addr), "r"((uint32_t)(nCols)))
#define TCGEN05_RELINQUISH() \
    asm volatile("tcgen05.relinquish_alloc_permit.cta_group::1.sync.aligned;")
#define TCGEN05_COMMIT(mbar_smem_addr) \
    asm volatile("tcgen05.commit.cta_group::1.mbarrier::arrive::one.shared::cluster.b64 [%0];" \
        :: "r"((uint32_t)(mbar_smem_addr)) : "memory")
#define TCGEN05_FENCE_AFTER() \
    asm volatile("tcgen05.fence::after_thread_sync;" ::: "memory")
#define TCGEN05_WAIT_LD() \
    asm volatile("tcgen05.wait::ld.sync.aligned;" ::: "memory")
#define FENCE_PROXY_ASYNC_SHARED_CTA() \
    asm volatile("fence.proxy.async.shared::cta;" ::: "memory")
#define MBARRIER_INIT(mbar, count) \
    asm volatile("mbarrier.init.shared.b64 [%0], %1;" \
        :: "r"((uint32_t)(mbar)), "r"((uint32_t)(count)) : "memory")
#define MBARRIER_INVAL(mbar) \
    asm volatile("mbarrier.inval.shared.b64 [%0];" :: "r"((uint32_t)(mbar)) : "memory")
#define MBARRIER_WAIT_PARITY(mbar_smem_addr, phase_parity) do { \
    uint32_t _mbar = (uint32_t)(mbar_smem_addr); \
    uint32_t _parity = (uint32_t)(phase_parity); \
    uint32_t _done; \
    asm volatile("{\n\t.reg .pred p;\n\t" \
        "mbarrier.try_wait.parity.acquire.cta.shared::cta.b64 p, [%1], %2;\n\t" \
        "selp.b32 %0, 1, 0, p;\n\t}" \
        : "=r"(_done) : "r"(_mbar), "r"(_parity) : "memory"); \
    if (!_done) { \
        asm volatile("{\n\t.reg .pred P1;\n\t" \
            "WAIT_LOOP_%=:\n\t" \
            "mbarrier.try_wait.parity.acquire.cta.shared::cta.b64 P1, [%0], %1, 0x989680;\n\t" \
            "@P1 bra.uni WAIT_DONE_%=;\n\t" \
            "bra.uni WAIT_LOOP_%=;\n\t" \
            "WAIT_DONE_%=:\n\t}" \
            :: "r"(_mbar), "r"(_parity) : "memory"); \
    } \
} while(0)

#define TCGEN05_LD_32X32B_X32(r, tmem_addr) \
    asm volatile("tcgen05.ld.sync.aligned.32x32b.x32.b32 " \
        "{%0, %1, %2, %3, %4, %5, %6, %7, %8, %9, %10, %11, %12, %13, %14, %15, " \
        " %16, %17, %18, %19, %20, %21, %22, %23, %24, %25, %26, %27, %28, %29, %30, %31}, [%32];" \
        : "=r"((r)[0]),  "=r"((r)[1]),  "=r"((r)[2]),  "=r"((r)[3]), \
          "=r"((r)[4]),  "=r"((r)[5]),  "=r"((r)[6]),  "=r"((r)[7]), \
          "=r"((r)[8]),  "=r"((r)[9]),  "=r"((r)[10]), "=r"((r)[11]), \
          "=r"((r)[12]), "=r"((r)[13]), "=r"((r)[14]), "=r"((r)[15]), \
          "=r"((r)[16]), "=r"((r)[17]), "=r"((r)[18]), "=r"((r)[19]), \
          "=r"((r)[20]), "=r"((r)[21]), "=r"((r)[22]), "=r"((r)[23]), \
          "=r"((r)[24]), "=r"((r)[25]), "=r"((r)[26]), "=r"((r)[27]), \
          "=r"((r)[28]), "=r"((r)[29]), "=r"((r)[30]), "=r"((r)[31]) \
        : "r"(tmem_addr))

__device__ __forceinline__ void mma_f16_ss(uint32_t d_tmem, uint64_t a_desc, uint64_t b_desc,
                                           uint32_t idesc, uint32_t enable_d) {
    asm volatile(
        "{\n\t.reg .pred p;\n\t"
        "setp.ne.u32 p, %4, 0;\n\t"
        "tcgen05.mma.cta_group::1.kind::f16 [%0], %1, %2, %3, {%5, %5, %5, %5}, p;\n\t}"
        :: "r"(d_tmem), "l"(a_desc), "l"(b_desc), "r"(idesc), "r"(enable_d), "r"(0u)
        : "memory");
}

static constexpr uint32_t GEMM_IDESC =
    (1u << 4) | (1u << 7) | (1u << 10) | ((128u / 8u) << 17) | ((128u / 16u) << 24);
#endif  // HAS_TCGEN05

// ---------------- convert helpers ----------------
__device__ __forceinline__ void split_bf16(float x, __nv_bfloat16& h, __nv_bfloat16& l) {
    h = __float2bfloat16(x);
    l = __float2bfloat16(x - __bfloat162float(h));
}
__device__ __forceinline__ float bfu2f(uint32_t u16) {
    return __bfloat162float(__ushort_as_bfloat16((unsigned short)u16));
}

__global__ void convert_w(const float* __restrict__ Wq, const float* __restrict__ Wk,
                          const float* __restrict__ Wv,
                          __nv_bfloat16* __restrict__ aq_hi, __nv_bfloat16* __restrict__ aq_lo,
                          __nv_bfloat16* __restrict__ akv_hi, __nv_bfloat16* __restrict__ akv_lo,
                          float* __restrict__ lg, float* __restrict__ kn2,
                          float* __restrict__ qn2)
{
    if (blockIdx.x == 0) {
        for (int i = threadIdx.x; i < BATCH*HEADS*CPH*CPH; i += 256) lg[i] = 0.f;
        for (int i = threadIdx.x; i < BATCH*CHN; i += 256) { kn2[i] = 0.f; qn2[i] = 0.f; }
    }
    int i = blockIdx.x * 256 + threadIdx.x;
    __nv_bfloat16 h, l;
    if (i < 65536) {
        split_bf16(Wq[i], h, l); aq_hi[i] = h; aq_lo[i] = l;
    } else if (i < 131072) {
        int j = i - 65536;
        split_bf16(Wk[j], h, l); akv_hi[j] = h; akv_lo[j] = l;
    } else {
        int j = i - 131072;
        split_bf16(Wv[j], h, l); akv_hi[65536 + j] = h; akv_lo[65536 + j] = l;
    }
}

// ---------------- X convert: [B,C,N] f32 -> [B,N,C] bf16 hi/lo ----------------
__global__ __launch_bounds__(256) void convert_x(const float* __restrict__ X,
                                                 __nv_bfloat16* __restrict__ Th,
                                                 __nv_bfloat16* __restrict__ Tl, int N)
{
    __shared__ float s[64][33];
    int b = blockIdx.z, c0 = blockIdx.y * 64, n0 = blockIdx.x * 32;
    const float* Xb = X + (size_t)b * 256 * N;
    int lane = threadIdx.x & 31, w = threadIdx.x >> 5;
#pragma unroll
    for (int i = 0; i < 8; i++) {
        int c = w + i * 8;
        s[c][lane] = Xb[(size_t)(c0 + c) * N + n0 + lane];
    }
    __syncthreads();
    uint32_t* TH = (uint32_t*)(Th + (size_t)b * N * 256);
    uint32_t* TL = (uint32_t*)(Tl + (size_t)b * N * 256);
#pragma unroll
    for (int i = 0; i < 4; i++) {
        int n = w + i * 8;
        float x0 = s[2 * lane][n], x1 = s[2 * lane + 1][n];
        __nv_bfloat16 h0, l0, h1, l1;
        split_bf16(x0, h0, l0); split_bf16(x1, h1, l1);
        uint32_t hp = ((uint32_t)__bfloat16_as_ushort(h1) << 16) | __bfloat16_as_ushort(h0);
        uint32_t lp = ((uint32_t)__bfloat16_as_ushort(l1) << 16) | __bfloat16_as_ushort(l0);
        size_t idx = (size_t)(n0 + n) * 128 + (c0 >> 1) + lane;
        TH[idx] = hp; TL[idx] = lp;
    }
}

// ---------------- GEMM ----------------
#if HAS_TCGEN05
// async swizzled tile load: 128 rows x 64 bf16 (128B/row), src row stride 256
__device__ __forceinline__ void load_tile_cp(const __nv_bfloat16* __restrict__ src,
                                             uint32_t dst_u32, int tid)
{
#pragma unroll
    for (int it = 0; it < 4; it++) {
        int i = tid + it * 256;
        int row = i >> 3, seg = i & 7;
        uint32_t off = SW128((uint32_t)(row * 128 + seg * 16));
        asm volatile("cp.async.cg.shared.global [%0], [%1], 16;"
                     :: "r"(dst_u32 + off), "l"(src + (size_t)row * 256 + seg * 8)
                     : "memory");
    }
}
#endif

__global__ __launch_bounds__(256, 1) void gemm_tc(
    const __nv_bfloat16* __restrict__ Ahi, const __nv_bfloat16* __restrict__ Alo,
    const __nv_bfloat16* __restrict__ Bhi, const __nv_bfloat16* __restrict__ Blo,
    float* __restrict__ Y, int Ntot)
{
    extern __shared__ char dsm[];
    int tid = threadIdx.x;
    int m0 = blockIdx.y * 128, n0 = blockIdx.x * 128, b = blockIdx.z;
    int Mtot = gridDim.y * 128;
    const __nv_bfloat16* Bh = Bhi + (size_t)b * Ntot * 256;
    const __nv_bfloat16* Bl = Blo + (size_t)b * Ntot * 256;
    float* Yb = Y + (size_t)b * Mtot * Ntot;

#if HAS_TCGEN05
    __shared__ uint32_t s_tmem[1];
    __shared__ unsigned long long s_mbar[2];
    uint32_t dsm_u = smem_to_u32(dsm);
    uint32_t sb = (dsm_u + 1023) & ~1023u;
    char* sbp = dsm + (sb - dsm_u);
    uint32_t mb[2] = { smem_to_u32(&s_mbar[0]), smem_to_u32(&s_mbar[1]) };
    int wid = tid >> 5;

    if (wid == 0) TCGEN05_ALLOC(smem_to_u32(s_tmem), 128);
    if (tid == 0) { MBARRIER_INIT(mb[0], 1); MBARRIER_INIT(mb[1], 1); }
    __syncthreads();
    uint32_t tbase = s_tmem[0];

    for (int ch = 0; ch < 4; ch++) {
        int buf = ch & 1;
        uint32_t base = sb + buf * 65536;
        if (ch >= 2) MBARRIER_WAIT_PARITY(mb[buf], 0);
        int c0 = ch * 64;
        load_tile_cp(Ahi + (size_t)m0 * 256 + c0, base,          tid);
        load_tile_cp(Alo + (size_t)m0 * 256 + c0, base + 16384,  tid);
        load_tile_cp(Bh  + (size_t)n0 * 256 + c0, base + 32768,  tid);
        load_tile_cp(Bl  + (size_t)n0 * 256 + c0, base + 49152,  tid);
        asm volatile("cp.async.commit_group;" ::: "memory");
        asm volatile("cp.async.wait_group 0;" ::: "memory");
        FENCE_PROXY_ASYNC_SHARED_CTA();
        __syncthreads();
        if (wid == 0) {
            if (elect_one_pred()) {
                uint64_t dah = MAKE_SMEM_DESC(base);
                uint64_t dal = MAKE_SMEM_DESC(base + 16384);
                uint64_t dbh = MAKE_SMEM_DESC(base + 32768);
                uint64_t dbl = MAKE_SMEM_DESC(base + 49152);
#pragma unroll
                for (int k = 0; k < 4; k++)
                    mma_f16_ss(tbase, dah + 2 * k, dbh + 2 * k, GEMM_IDESC,
                               (ch > 0 || k > 0) ? 1u : 0u);
#pragma unroll
                for (int k = 0; k < 4; k++)
                    mma_f16_ss(tbase, dah + 2 * k, dbl + 2 * k, GEMM_IDESC, 1u);
#pragma unroll
                for (int k = 0; k < 4; k++)
                    mma_f16_ss(tbase, dal + 2 * k, dbh + 2 * k, GEMM_IDESC, 1u);
                TCGEN05_COMMIT(mb[buf]);
            }
        }
    }

    MBARRIER_WAIT_PARITY(mb[0], 1);
    MBARRIER_WAIT_PARITY(mb[1], 1);
    TCGEN05_FENCE_AFTER();

    float* Ds = (float*)sbp;
    uint32_t woff = (uint32_t)(wid & 3) << 21;
    int cb0 = (wid >= 4) ? 2 : 0;
    int lane = tid & 31;
    int row = (wid & 3) * 32 + lane;
    uint32_t regs[32];
#pragma unroll
    for (int j = 0; j < 2; j++) {
        int cb = cb0 + j;
        TCGEN05_LD_32X32B_X32(regs, tbase + cb * 32 + woff);
        TCGEN05_WAIT_LD();
#pragma unroll
        for (int c = 0; c < 32; c++)
            Ds[row * 132 + cb * 32 + c] = __uint_as_float(regs[c]);
    }
    __syncthreads();
#pragma unroll
    for (int it = 0; it < 16; it++) {
        int i = tid + it * 256;
        int r = i >> 5, c4 = (i & 31) * 4;
        float4 v = *(float4*)&Ds[r * 132 + c4];
        *(float4*)&Yb[(size_t)(m0 + r) * Ntot + n0 + c4] = v;
    }
    __syncthreads();
    if (tid == 0) { MBARRIER_INVAL(mb[0]); MBARRIER_INVAL(mb[1]); }
    if (wid == 0) { TCGEN05_RELINQUISH(); TCGEN05_DEALLOC(tbase, 128); }

#else  // SIMT fallback
    float* As = (float*)dsm;
    float* Bs = As + 8 * 128;
    int ty = tid >> 4, tx = tid & 15;
    int r = tid >> 1, kq = (tid & 1) * 4;

    float acc[8][8];
#pragma unroll
    for (int i = 0; i < 8; i++)
#pragma unroll
        for (int j = 0; j < 8; j++) acc[i][j] = 0.f;

    for (int c0 = 0; c0 < 256; c0 += 8) {
        {
            size_t off = (size_t)(m0 + r) * 256 + c0 + kq;
            uint2 vh = *(const uint2*)(Ahi + off);
            uint2 vl = *(const uint2*)(Alo + off);
            As[(kq + 0) * 128 + r] = bfu2f(vh.x & 0xffff)  + bfu2f(vl.x & 0xffff);
            As[(kq + 1) * 128 + r] = bfu2f(vh.x >> 16)     + bfu2f(vl.x >> 16);
            As[(kq + 2) * 128 + r] = bfu2f(vh.y & 0xffff)  + bfu2f(vl.y & 0xffff);
            As[(kq + 3) * 128 + r] = bfu2f(vh.y >> 16)     + bfu2f(vl.y >> 16);
            size_t offb = (size_t)(n0 + r) * 256 + c0 + kq;
            uint2 wh = *(const uint2*)(Bh + offb);
            uint2 wl = *(const uint2*)(Bl + offb);
            Bs[(kq + 0) * 128 + r] = bfu2f(wh.x & 0xffff)  + bfu2f(wl.x & 0xffff);
            Bs[(kq + 1) * 128 + r] = bfu2f(wh.x >> 16)     + bfu2f(wl.x >> 16);
            Bs[(kq + 2) * 128 + r] = bfu2f(wh.y & 0xffff)  + bfu2f(wl.y & 0xffff);
            Bs[(kq + 3) * 128 + r] = bfu2f(wh.y >> 16)     + bfu2f(wl.y >> 16);
        }
        __syncthreads();
#pragma unroll
        for (int kk = 0; kk < 8; kk++) {
            float a[8], bb[8];
            *(float4*)&a[0]  = *(const float4*)&As[kk * 128 + ty * 8];
            *(float4*)&a[4]  = *(const float4*)&As[kk * 128 + ty * 8 + 4];
            *(float4*)&bb[0] = *(const float4*)&Bs[kk * 128 + tx * 8];
            *(float4*)&bb[4] = *(const float4*)&Bs[kk * 128 + tx * 8 + 4];
#pragma unroll
            for (int i = 0; i < 8; i++)
#pragma unroll
                for (int j = 0; j < 8; j++)
                    acc[i][j] = fmaf(a[i], bb[j], acc[i][j]);
        }
        __syncthreads();
    }
#pragma unroll
    for (int i = 0; i < 8; i++) {
        float* yp = Yb + (size_t)(m0 + ty * 8 + i) * Ntot + n0 + tx * 8;
        *(float4*)yp       = make_float4(acc[i][0], acc[i][1], acc[i][2], acc[i][3]);
        *(float4*)(yp + 4) = make_float4(acc[i][4], acc[i][5], acc[i][6], acc[i][7]);
    }
#endif
}

// ---------------- plain templated WTConv (Haar, ks=3), 32-row tiles, float4 subbands ----------------
template<int W>
__global__ __launch_bounds__(256, 4) void wtconv_t(
    const float* __restrict__ X, float* __restrict__ Y,
    const float* __restrict__ base_w, const float* __restrict__ base_s,
    const float* __restrict__ wav_w,  const float* __restrict__ wav_s,
    int H, int cs_in)
{
    constexpr int LW = W + 4;
    constexpr int SWc = (W >> 1) + 2;
    constexpr int Wh = W >> 1;
    __shared__ float ins[36][LW];
    __shared__ float4 sub4[18][SWc];
    __shared__ float swav[4][9];
    __shared__ float sbw[9];
    __shared__ float swsc[4];
    __shared__ float sbs;

    int bc = blockIdx.x;
    int b  = bc >> 8;
    int c  = bc & 255;
    int y0 = blockIdx.y * 32;
    const float* Xc = X + ((size_t)b * cs_in + c) * H * W;
    float*       Yc = Y + (size_t)bc * H * W;
    int tid = threadIdx.x;

    if (tid < 36) {
        int f = tid / 9, i = tid - f * 9;
        swav[f][i] = wav_w[(size_t)(c * 4 + f) * 9 + i];
    } else if (tid < 45) {
        sbw[tid - 36] = base_w[(size_t)c * 9 + tid - 36];
    } else if (tid < 49) {
        swsc[tid - 45] = wav_s[c * 4 + tid - 45];
    } else if (tid == 49) {
        sbs = base_s[c];
    }

    for (int idx = tid; idx < 36 * LW; idx += 256) {
        int ly = idx / LW, lx = idx - ly * LW;
        int gy = y0 + ly - 2, gx = lx - 2;
        float v = 0.f;
        if (gy >= 0 && gy < H && gx >= 0 && gx < W) v = Xc[gy * W + gx];
        ins[ly][lx] = v;
    }
    __syncthreads();

    for (int idx = tid; idx < 18 * SWc; idx += 256) {
        int sy = idx / SWc, sx = idx - sy * SWc;
        float a = ins[2 * sy][2 * sx],     bq = ins[2 * sy][2 * sx + 1];
        float d = ins[2 * sy + 1][2 * sx], e = ins[2 * sy + 1][2 * sx + 1];
        sub4[sy][sx] = make_float4(0.5f * (a + bq + d + e), 0.5f * (a + bq - d - e),
                                   0.5f * (a - bq + d - e), 0.5f * (a - bq - d + e));
    }
    __syncthreads();

    for (int idx = tid; idx < 16 * Wh; idx += 256) {
        int syi = idx / Wh, sxi = idx - syi * Wh;
        int sy = syi + 1, sx = sxi + 1;
        float r0 = 0.f, r1 = 0.f, r2 = 0.f, r3 = 0.f;
#pragma unroll
        for (int dy = 0; dy < 3; dy++)
#pragma unroll
            for (int dx = 0; dx < 3; dx++) {
                float4 s = sub4[sy - 1 + dy][sx - 1 + dx];
                int kk = dy * 3 + dx;
                r0 = fmaf(swav[0][kk], s.x, r0);
                r1 = fmaf(swav[1][kk], s.y, r1);
                r2 = fmaf(swav[2][kk], s.z, r2);
                r3 = fmaf(swav[3][kk], s.w, r3);
            }
        r0 *= swsc[0]; r1 *= swsc[1]; r2 *= swsc[2]; r3 *= swsc[3];
        float y00 = 0.5f * (r0 + r1 + r2 + r3);
        float y01 = 0.5f * (r0 + r1 - r2 - r3);
        float y10 = 0.5f * (r0 - r1 + r2 - r3);
        float y11 = 0.5f * (r0 - r1 - r2 + r3);

        float base[2][2];
#pragma unroll
        for (int p = 0; p < 2; p++)
#pragma unroll
            for (int q = 0; q < 2; q++) {
                float s = 0.f;
#pragma unroll
                for (int dy = 0; dy < 3; dy++)
#pragma unroll
                    for (int dx = 0; dx < 3; dx++)
                        s = fmaf(sbw[dy * 3 + dx],
                                 ins[2 * sy + p - 1 + dy][2 * sx + q - 1 + dx], s);
                base[p][q] = s * sbs;
            }
        int gy = y0 + 2 * syi, gx = 2 * sxi;
        Yc[(gy + 0) * W + gx + 0] = base[0][0] + y00;
        Yc[(gy + 0) * W + gx + 1] = base[0][1] + y01;
        Yc[(gy + 1) * W + gx + 0] = base[1][0] + y10;
        Yc[(gy + 1) * W + gx + 1] = base[1][1] + y11;
    }
}

// ---------------- fused wtconv(k) + transposed-bilinear downsample + ||k||², float4 subbands ----------------
#define KD_SMEM ((40*132 + 4*20*66 + 36*130) * 4)

__global__ __launch_bounds__(256, 3) void wtconv_k_down(
    const float* __restrict__ X, float* __restrict__ kdn,
    const float* __restrict__ base_w, const float* __restrict__ base_s,
    const float* __restrict__ wav_w,  const float* __restrict__ wav_s,
    float* __restrict__ kn2)
{
    extern __shared__ float sm[];
    float*  ins  = sm;                          // [40][132]
    float4* sub4 = (float4*)(ins + 40 * 132);   // [20*66] interleaved subbands
    float*  outb = ins + 40 * 132 + 4 * 20 * 66; // [36][130]
    __shared__ float swav[4][9];
    __shared__ float sbw[9];
    __shared__ float swsc[4];
    __shared__ float sbs;
    __shared__ float red8[8];

    int bc = blockIdx.x;
    int b  = bc >> 8;
    int c  = bc & 255;
    int by = blockIdx.y;
    int y0 = by * 32;
    const float* Xc = X + ((size_t)b * 512 + c) * (size_t)NK;
    int tid = threadIdx.x;

    if (tid < 36) {
        int f = tid / 9, i = tid - f * 9;
        swav[f][i] = wav_w[(size_t)(c * 4 + f) * 9 + i];
    } else if (tid < 45) {
        sbw[tid - 36] = base_w[(size_t)c * 9 + tid - 36];
    } else if (tid < 49) {
        swsc[tid - 45] = wav_s[c * 4 + tid - 45];
    } else if (tid == 49) {
        sbs = base_s[c];
    }

    for (int idx = tid; idx < 40 * 132; idx += 256) {
        int ly = idx / 132, lx = idx - ly * 132;
        int gy = y0 + ly - 4, gx = lx - 2;
        float v = 0.f;
        if (gy >= 0 && gy < 128 && gx >= 0 && gx < 128) v = Xc[gy * 128 + gx];
        ins[idx] = v;
    }
    __syncthreads();

    for (int idx = tid; idx < 20 * 66; idx += 256) {
        int sy = idx / 66, sx = idx - sy * 66;
        const float* r0p = ins + (2 * sy) * 132 + 2 * sx;
        float a = r0p[0], bq = r0p[1], d = r0p[132], e = r0p[133];
        sub4[idx] = make_float4(0.5f * (a + bq + d + e), 0.5f * (a + bq - d - e),
                                0.5f * (a - bq + d - e), 0.5f * (a - bq - d + e));
    }
    __syncthreads();

    for (int idx = tid; idx < 18 * 64; idx += 256) {
        int syo = idx >> 6, j = idx & 63;
        int sy = syo + 1, sx = j + 1;
        float r0 = 0.f, r1 = 0.f, r2 = 0.f, r3 = 0.f;
#pragma unroll
        for (int dy = 0; dy < 3; dy++)
#pragma unroll
            for (int dx = 0; dx < 3; dx++) {
                float4 s = sub4[(sy - 1 + dy) * 66 + sx - 1 + dx];
                int kk = dy * 3 + dx;
                r0 = fmaf(swav[0][kk], s.x, r0);
                r1 = fmaf(swav[1][kk], s.y, r1);
                r2 = fmaf(swav[2][kk], s.z, r2);
                r3 = fmaf(swav[3][kk], s.w, r3);
            }
        r0 *= swsc[0]; r1 *= swsc[1]; r2 *= swsc[2]; r3 *= swsc[3];
        float y00 = 0.5f * (r0 + r1 + r2 + r3);
        float y01 = 0.5f * (r0 + r1 - r2 - r3);
        float y10 = 0.5f * (r0 - r1 + r2 - r3);
        float y11 = 0.5f * (r0 - r1 - r2 + r3);

        float base[2][2];
#pragma unroll
        for (int p = 0; p < 2; p++)
#pragma unroll
            for (int q = 0; q < 2; q++) {
                float s = 0.f;
#pragma unroll
                for (int dy = 0; dy < 3; dy++)
#pragma unroll
                    for (int dx = 0; dx < 3; dx++)
                        s = fmaf(sbw[dy * 3 + dx],
                                 ins[(2 * syo + 1 + p + dy) * 132 + 2 * j + 1 + q + dx], s);
                base[p][q] = s * sbs;
            }
        outb[(2 * syo) * 130 + 2 * j]         = base[0][0] + y00;
        outb[(2 * syo) * 130 + 2 * j + 1]     = base[0][1] + y01;
        outb[(2 * syo + 1) * 130 + 2 * j]     = base[1][0] + y10;
        outb[(2 * syo + 1) * 130 + 2 * j + 1] = base[1][1] + y11;
    }
    __syncthreads();

    float sumsq = 0.f;
    for (int idx = tid; idx < 32 * 128; idx += 256) {
        int lr = (idx >> 7) + 2, lc = idx & 127;
        float v = outb[lr * 130 + lc];
        sumsq += v * v;
    }

    for (int idx = tid; idx < 16 * 64; idx += 256) {
        int jj = idx >> 6, jx = idx & 63;
        int jy = 16 * by + jj;
        int lyt[4]; float wyt[4]; int cy = 0;
        if (jy > 0)  { lyt[cy] = 2*jj+1; wyt[cy++] = 0.25f; }
        lyt[cy] = 2*jj+2; wyt[cy++] = (jy == 0)  ? 1.0f : 0.75f;
        lyt[cy] = 2*jj+3; wyt[cy++] = (jy == 63) ? 1.0f : 0.75f;
        if (jy < 63) { lyt[cy] = 2*jj+4; wyt[cy++] = 0.25f; }
        int lxt[4]; float wxt[4]; int cx = 0;
        if (jx > 0)  { lxt[cx] = 2*jx-1; wxt[cx++] = 0.25f; }
        lxt[cx] = 2*jx;   wxt[cx++] = (jx == 0)  ? 1.0f : 0.75f;
        lxt[cx] = 2*jx+1; wxt[cx++] = (jx == 63) ? 1.0f : 0.75f;
        if (jx < 63) { lxt[cx] = 2*jx+2; wxt[cx++] = 0.25f; }
        float s = 0.f;
        for (int a = 0; a < cy; a++) {
            const float* row = outb + lyt[a] * 130;
            float rs = 0.f;
            for (int e = 0; e < cx; e++) rs = fmaf(wxt[e], row[lxt[e]], rs);
            s = fmaf(wyt[a], rs, s);
        }
        kdn[(size_t)bc * NQ + jy * 64 + jx] = s;
    }

    __syncthreads();
    float tot = block_reduce_sum(sumsq, red8, tid);
    if (tid == 0) atomicAdd(&kn2[bc], tot);
}

// ---------------- fused wtconv(q) + ||upsample(q)||² via Gram form, float4 subbands ----------------
__global__ __launch_bounds__(256, 4) void wtconv_q_norm(
    const float* __restrict__ X, float* __restrict__ Y,
    const float* __restrict__ base_w, const float* __restrict__ base_s,
    const float* __restrict__ wav_w,  const float* __restrict__ wav_s,
    float* __restrict__ qn2)
{
    __shared__ float ins[40][68];
    __shared__ float4 sub4[20][36];
    __shared__ float outb[36][66];
    __shared__ float swav[4][9];
    __shared__ float sbw[9];
    __shared__ float swsc[4];
    __shared__ float sbs;
    __shared__ float red8[8];

    int bc = blockIdx.x;
    int c  = bc & 255;
    int by = blockIdx.y;
    int y0 = by * 32;
    const float* Xc = X + (size_t)bc * NQ;
    float*       Yc = Y + (size_t)bc * NQ;
    int tid = threadIdx.x;

    if (tid < 36) {
        int f = tid / 9, i = tid - f * 9;
        swav[f][i] = wav_w[(size_t)(c * 4 + f) * 9 + i];
    } else if (tid < 45) {
        sbw[tid - 36] = base_w[(size_t)c * 9 + tid - 36];
    } else if (tid < 49) {
        swsc[tid - 45] = wav_s[c * 4 + tid - 45];
    } else if (tid == 49) {
        sbs = base_s[c];
    }

    for (int idx = tid; idx < 40 * 68; idx += 256) {
        int ly = idx / 68, lx = idx - ly * 68;
        int gy = y0 + ly - 4, gx = lx - 2;
        float v = 0.f;
        if (gy >= 0 && gy < 64 && gx >= 0 && gx < 64) v = Xc[gy * 64 + gx];
        ins[ly][lx] = v;
    }
    __syncthreads();

    for (int idx = tid; idx < 20 * 34; idx += 256) {
        int sy = idx / 34, sx = idx - sy * 34;
        float a = ins[2 * sy][2 * sx],     bq = ins[2 * sy][2 * sx + 1];
        float d = ins[2 * sy + 1][2 * sx], e = ins[2 * sy + 1][2 * sx + 1];
        sub4[sy][sx] = make_float4(0.5f * (a + bq + d + e), 0.5f * (a + bq - d - e),
                                   0.5f * (a - bq + d - e), 0.5f * (a - bq - d + e));
    }
    __syncthreads();

    for (int idx = tid; idx < 18 * 32; idx += 256) {
        int syo = idx >> 5, j = idx & 31;
        int sy = syo + 1, sx = j + 1;
        float r0 = 0.f, r1 = 0.f, r2 = 0.f, r3 = 0.f;
#pragma unroll
        for (int dy = 0; dy < 3; dy++)
#pragma unroll
            for (int dx = 0; dx < 3; dx++) {
                float4 s = sub4[sy - 1 + dy][sx - 1 + dx];
                int kk = dy * 3 + dx;
                r0 = fmaf(swav[0][kk], s.x, r0);
                r1 = fmaf(swav[1][kk], s.y, r1);
                r2 = fmaf(swav[2][kk], s.z, r2);
                r3 = fmaf(swav[3][kk], s.w, r3);
            }
        r0 *= swsc[0]; r1 *= swsc[1]; r2 *= swsc[2]; r3 *= swsc[3];
        float y00 = 0.5f * (r0 + r1 + r2 + r3);
        float y01 = 0.5f * (r0 + r1 - r2 - r3);
        float y10 = 0.5f * (r0 - r1 + r2 - r3);
        float y11 = 0.5f * (r0 - r1 - r2 + r3);

        float base[2][2];
#pragma unroll
        for (int p = 0; p < 2; p++)
#pragma unroll
            for (int q = 0; q < 2; q++) {
                float s = 0.f;
#pragma unroll
                for (int dy = 0; dy < 3; dy++)
#pragma unroll
                    for (int dx = 0; dx < 3; dx++)
                        s = fmaf(sbw[dy * 3 + dx],
                                 ins[2 * syo + 1 + p + dy][2 * j + 1 + q + dx], s);
                base[p][q] = s * sbs;
            }
        float o00 = base[0][0] + y00, o01 = base[0][1] + y01;
        float o10 = base[1][0] + y10, o11 = base[1][1] + y11;
        outb[2 * syo][2 * j]         = o00;
        outb[2 * syo][2 * j + 1]     = o01;
        outb[2 * syo + 1][2 * j]     = o10;
        outb[2 * syo + 1][2 * j + 1] = o11;
        if (syo >= 1 && syo <= 16) {
            int gy = y0 - 2 + 2 * syo;
            Yc[(gy + 0) * 64 + 2 * j]     = o00;
            Yc[(gy + 0) * 64 + 2 * j + 1] = o01;
            Yc[(gy + 1) * 64 + 2 * j]     = o10;
            Yc[(gy + 1) * 64 + 2 * j + 1] = o11;
        }
    }
    __syncthreads();

    // Gram quadratic form over owned rows (global y0..y0+31, local 2..33)
    float sum = 0.f;
    for (int idx = tid; idx < 32 * 64; idx += 256) {
        int yl = idx >> 6, x = idx & 63;
        int yg = y0 + yl;
        int ly = yl + 2;
        float dyc = (yg == 0 || yg == 63) ? 1.625f : 1.25f;
        float dxc = (x == 0 || x == 63) ? 1.625f : 1.25f;
        float ql = (x > 0)  ? 0.375f : 0.f;
        float qr = (x < 63) ? 0.375f : 0.f;

        const float* rm = &outb[ly - 1][x];
        const float* rc = &outb[ly][x];
        const float* rp = &outb[ly + 1][x];
        float um = ql * rm[-1] + dxc * rm[0] + qr * rm[1];
        float uc = ql * rc[-1] + dxc * rc[0] + qr * rc[1];
        float up = ql * rp[-1] + dxc * rp[0] + qr * rp[1];

        float gm = (yg > 0)  ? 0.375f : 0.f;
        float gp = (yg < 63) ? 0.375f : 0.f;
        sum += rc[0] * (gm * um + dyc * uc + gp * up);
    }
    float tot = block_reduce_sum(sum, red8, tid);
    if (tid == 0) atomicAdd(&qn2[bc], tot);
}

// ---------------- attention logits ----------------
__global__ __launch_bounds__(256) void attn_partial(
    const float* __restrict__ qp, const float* __restrict__ kp,
    float* __restrict__ logits, int N)
{
    __shared__ float qsT[64][33];
    __shared__ float ksT[64][33];
    int bh = blockIdx.y;
    int n0 = blockIdx.x * 512;
    const float* q = qp + (size_t)bh * 32 * N + n0;
    const float* k = kp + (size_t)bh * 32 * N + n0;
    int tid = threadIdx.x;
    int i0 = (tid & 7) * 4, j0 = ((tid >> 3) & 7) * 4, ns = tid >> 6;

    float acc[4][4];
#pragma unroll
    for (int i = 0; i < 4; i++)
#pragma unroll
        for (int j = 0; j < 4; j++) acc[i][j] = 0.f;

    for (int nc = 0; nc < 512; nc += 64) {
        for (int l = tid; l < 512; l += 256) {
            int row = l >> 4, col4 = (l & 15) * 4;
            float4 a = *(const float4*)(q + (size_t)row * N + nc + col4);
            float4 b = *(const float4*)(k + (size_t)row * N + nc + col4);
            qsT[col4 + 0][row] = a.x; qsT[col4 + 1][row] = a.y;
            qsT[col4 + 2][row] = a.z; qsT[col4 + 3][row] = a.w;
            ksT[col4 + 0][row] = b.x; ksT[col4 + 1][row] = b.y;
            ksT[col4 + 2][row] = b.z; ksT[col4 + 3][row] = b.w;
        }
        __syncthreads();
        for (int nn = ns; nn < 64; nn += 4) {
            float qv[4], kv[4];
#pragma unroll
            for (int m = 0; m < 4; m++) { qv[m] = qsT[nn][i0 + m]; kv[m] = ksT[nn][j0 + m]; }
#pragma unroll
            for (int i = 0; i < 4; i++)
#pragma unroll
                for (int j = 0; j < 4; j++)
                    acc[i][j] = fmaf(qv[i], kv[j], acc[i][j]);
        }
        __syncthreads();
    }
    float* L = logits + (size_t)bh * 1024;
#pragma unroll
    for (int i = 0; i < 4; i++)
#pragma unroll
        for (int j = 0; j < 4; j++)
            atomicAdd(&L[(i0 + i) * 32 + j0 + j], acc[i][j]);
}

// ---------------- fused softmax + (attn @ v) + proj WTConv(ks=1) -> d_out ----------------
__global__ __launch_bounds__(256) void av_proj_kernel(
    const float* __restrict__ logits, const float* __restrict__ qn2,
    const float* __restrict__ kn2, const float* __restrict__ temp,
    const float* __restrict__ v,
    const float* __restrict__ pbw, const float* __restrict__ pbs,
    const float* __restrict__ pww, const float* __restrict__ pws,
    float* __restrict__ out)
{
    __shared__ float As[32][33];
    __shared__ float2 vt[32][2][8];

    int by = blockIdx.x;
    int bh = blockIdx.y;
    int b  = bh >> 3, h = bh & 7;
    int tid = threadIdx.x;
    int i  = tid >> 3;
    int pb = tid & 7;

    for (int l = tid; l < 1024; l += 256) As[l >> 5][l & 31] = logits[(size_t)bh * 1024 + l];
    __syncthreads();

    {
        int w = tid >> 5, lane = tid & 31;
        float tmp = temp[h];
        float kvn = fmaxf(sqrtf(kn2[b * 256 + h * 32 + lane]), 1e-12f);
#pragma unroll
        for (int rr = 0; rr < 4; rr++) {
            int r = w * 4 + rr;
            float qvn = fmaxf(sqrtf(qn2[b * 256 + h * 32 + r]), 1e-12f);
            float val = As[r][lane] * tmp / (qvn * kvn);
            float m = val;
#pragma unroll
            for (int o = 16; o; o >>= 1) m = fmaxf(m, __shfl_xor_sync(0xffffffffu, m, o));
            float e = expf(val - m);
            float s = e;
#pragma unroll
            for (int o = 16; o; o >>= 1) s += __shfl_xor_sync(0xffffffffu, s, o);
            As[r][lane] = e / s;
        }
    }
    __syncthreads();

    float arow[32];
#pragma unroll
    for (int j = 0; j < 32; j++) arow[j] = As[i][j];

    int cw = h * 32 + i;
    float bw  = pbw[cw] * pbs[cw];
    float wv0 = pww[cw * 4 + 0] * pws[cw * 4 + 0];
    float wv1 = pww[cw * 4 + 1] * pws[cw * 4 + 1];
    float wv2 = pww[cw * 4 + 2] * pws[cw * 4 + 2];
    float wv3 = pww[cw * 4 + 3] * pws[cw * 4 + 3];

    const float* vb = v + (size_t)(b * 256 + h * 32) * NK;
    float* ob = out + (size_t)(b * 256 + h * 32 + i) * NK;

    int sj = tid >> 3, sr = (tid >> 2) & 1, sxq = tid & 3;

    for (int bx0 = 0; bx0 < 64; bx0 += 8) {
        __syncthreads();
        {
            float4 v4 = *(const float4*)(vb + (size_t)sj * NK + (2 * by + sr) * 128
                                         + 2 * bx0 + sxq * 4);
            vt[sj][sr][2 * sxq + 0] = make_float2(v4.x, v4.y);
            vt[sj][sr][2 * sxq + 1] = make_float2(v4.z, v4.w);
        }
        __syncthreads();

        float a00 = 0.f, a01 = 0.f, a10 = 0.f, a11 = 0.f;
#pragma unroll
        for (int j = 0; j < 32; j++) {
            float aA = arow[j];
            float2 t0 = vt[j][0][pb];
            float2 t1 = vt[j][1][pb];
            a00 = fmaf(aA, t0.x, a00); a01 = fmaf(aA, t0.y, a01);
            a10 = fmaf(aA, t1.x, a10); a11 = fmaf(aA, t1.y, a11);
        }

        float r0 = 0.5f * (a00 + a01 + a10 + a11) * wv0;
        float r1 = 0.5f * (a00 + a01 - a10 - a11) * wv1;
        float r2 = 0.5f * (a00 - a01 + a10 - a11) * wv2;
        float r3 = 0.5f * (a00 - a01 - a10 + a11) * wv3;
        float y00 = 0.5f * (r0 + r1 + r2 + r3) + a00 * bw;
        float y01 = 0.5f * (r0 + r1 - r2 - r3) + a01 * bw;
        float y10 = 0.5f * (r0 - r1 + r2 - r3) + a10 * bw;
        float y11 = 0.5f * (r0 - r1 - r2 + r3) + a11 * bw;

        int gx = 2 * (bx0 + pb);
        *(float2*)&ob[(2 * by + 0) * 128 + gx] = make_float2(y00, y01);
        *(float2*)&ob[(2 * by + 1) * 128 + gx] = make_float2(y10, y11);
    }
}

// ---------------- launch (multi-stream fork/join DAG) ----------------
#define GEMM_SMEM (1024 + 2 * 65536)

extern "C" void kernel_launch(void* const* d_in, const int* in_sizes, int n_in,
                              void* d_out, int out_size)
{
    const float* x    = (const float*)d_in[0];
    const float* cf   = (const float*)d_in[1];
    const float* Wq   = (const float*)d_in[2];
    const float* Wk   = (const float*)d_in[3];
    const float* Wv   = (const float*)d_in[4];
    const float* temp = (const float*)d_in[5];
    const float* qbw = (const float*)d_in[6];  const float* qbs = (const float*)d_in[7];
    const float* qww = (const float*)d_in[8];  const float* qws = (const float*)d_in[9];
    const float* kbw = (const float*)d_in[10]; const float* kbs = (const float*)d_in[11];
    const float* kww = (const float*)d_in[12]; const float* kws = (const float*)d_in[13];
    const float* vbw = (const float*)d_in[14]; const float* vbs = (const float*)d_in[15];
    const float* vww = (const float*)d_in[16]; const float* vws = (const float*)d_in[17];
    const float* pbw = (const float*)d_in[18]; const float* pbs = (const float*)d_in[19];
    const float* pww = (const float*)d_in[20]; const float* pws = (const float*)d_in[21];
    float* out = (float*)d_out;

    float *q, *kv, *qwt, *vwt, *kdn, *qn2, *kn2, *lg;
    __nv_bfloat16 *xt_hi, *xt_lo, *ct_hi, *ct_lo, *aq_hi, *aq_lo, *akv_hi, *akv_lo;
    cudaGetSymbolAddress((void**)&q,     g_q);
    cudaGetSymbolAddress((void**)&kv,    g_kv);
    cudaGetSymbolAddress((void**)&qwt,   g_qwt);
    cudaGetSymbolAddress((void**)&vwt,   g_vwt);
    cudaGetSymbolAddress((void**)&kdn,   g_kdn);
    cudaGetSymbolAddress((void**)&qn2,   g_qn2);
    cudaGetSymbolAddress((void**)&kn2,   g_kn2);
    cudaGetSymbolAddress((void**)&lg,    g_lg);
    cudaGetSymbolAddress((void**)&xt_hi, g_xt_hi);
    cudaGetSymbolAddress((void**)&xt_lo, g_xt_lo);
    cudaGetSymbolAddress((void**)&ct_hi, g_ct_hi);
    cudaGetSymbolAddress((void**)&ct_lo, g_ct_lo);
    cudaGetSymbolAddress((void**)&aq_hi, g_aq_hi);
    cudaGetSymbolAddress((void**)&aq_lo, g_aq_lo);
    cudaGetSymbolAddress((void**)&akv_hi, g_akv_hi);
    cudaGetSymbolAddress((void**)&akv_lo, g_akv_lo);

    cudaFuncSetAttribute(gemm_tc, cudaFuncAttributeMaxDynamicSharedMemorySize, GEMM_SMEM);
    cudaFuncSetAttribute(wtconv_k_down, cudaFuncAttributeMaxDynamicSharedMemorySize, KD_SMEM);

    static cudaStream_t s1 = nullptr, s2 = nullptr;
    static cudaEvent_t ev0 = nullptr, evW = nullptr, evE = nullptr, evF = nullptr, evH = nullptr;
    if (s1 == nullptr) {
        cudaStreamCreateWithFlags(&s1, cudaStreamNonBlocking);
        cudaStreamCreateWithFlags(&s2, cudaStreamNonBlocking);
        cudaEventCreateWithFlags(&ev0, cudaEventDisableTiming);
        cudaEventCreateWithFlags(&evW, cudaEventDisableTiming);
        cudaEventCreateWithFlags(&evE, cudaEventDisableTiming);
        cudaEventCreateWithFlags(&evF, cudaEventDisableTiming);
        cudaEventCreateWithFlags(&evH, cudaEventDisableTiming);
    }
    cudaStream_t s0 = 0;

    // fork
    cudaEventRecord(ev0, s0);
    cudaStreamWaitEvent(s1, ev0, 0);
    cudaStreamWaitEvent(s2, ev0, 0);

    // s2: weights convert + zero accumulators (off critical path)
    convert_w<<<768, 256, 0, s2>>>(Wq, Wk, Wv, aq_hi, aq_lo, akv_hi, akv_lo, lg, kn2, qn2);
    cudaEventRecord(evW, s2);

    // s1: q-path prologue
    convert_x<<<dim3(NQ / 32, 4, BATCH), 256, 0, s1>>>(x, xt_hi, xt_lo, NQ);
    cudaStreamWaitEvent(s1, evW, 0);
    gemm_tc<<<dim3(NQ / 128, 2, BATCH), 256, GEMM_SMEM, s1>>>(aq_hi, aq_lo, xt_hi, xt_lo, q, NQ);
    wtconv_q_norm<<<dim3(BATCH * CHN, 2), 256, 0, s1>>>(q, qwt, qbw, qbs, qww, qws, qn2);
    cudaEventRecord(evF, s1);

    // main: cf convert -> kv GEMM
    convert_x<<<dim3(NK / 32, 4, BATCH), 256, 0, s0>>>(cf, ct_hi, ct_lo, NK);
    cudaStreamWaitEvent(s0, evW, 0);
    gemm_tc<<<dim3(NK / 128, 4, BATCH), 256, GEMM_SMEM, s0>>>(akv_hi, akv_lo, ct_hi, ct_lo, kv, NK);
    cudaEventRecord(evE, s0);

    // s2: v wtconv (needs kv)
    cudaStreamWaitEvent(s2, evE, 0);
    wtconv_t<128><<<dim3(BATCH * CHN, 4), 256, 0, s2>>>(kv + (size_t)CHN * NK, vwt,
                                                        vbw, vbs, vww, vws, HK, 512);
    cudaEventRecord(evH, s2);

    // main: k wtconv + downsample + norm
    wtconv_k_down<<<dim3(BATCH * CHN, 4), 256, KD_SMEM, s0>>>(kv, kdn, kbw, kbs, kww, kws, kn2);

    // join q-path, attention logits
    cudaStreamWaitEvent(s0, evF, 0);
    attn_partial<<<dim3(NQ / 512, BATCH * HEADS), 256, 0, s0>>>(qwt, kdn, lg, NQ);

    // join v-path, fused softmax + av + proj
    cudaStreamWaitEvent(s0, evH, 0);
    av_proj_kernel<<<dim3(64, BATCH * HEADS), 256, 0, s0>>>(lg, qn2, kn2, temp, vwt,
                                                            pbw, pbs, pww, pws, out);
}